// round 1
// baseline (speedup 1.0000x reference)
#include <cuda_runtime.h>
#include <math.h>

// ---------------- constants ----------------
#define B_ 8
#define C1_ 64
#define C2_ 128
#define H_ 192
#define W_ 192
#define h_ 96
#define w_ 96

#define R_ELEMS (B_*C1_*H_*W_)        // 18,874,368
#define OMAP_ELEMS (B_*1*H_*W_)       // 294,912

// transposed-weight offsets inside g_wt
#define WT_UP 0            // 128*49*64 = 401408
#define WT_C2 401408       // 64*9*64   = 36864
#define WT_D1 438272       // 128*9*64  = 73728
#define WT_D2 512000       // 64*9*64
#define WT_D3 548864       // 64*9*64
#define WT_TOTAL 585728

// ---------------- scratch (no runtime allocation allowed) ----------------
__device__ float g_u[B_*C1_*h_*w_];
__device__ float g_small[R_ELEMS];
__device__ float g_diffs[B_*h_*w_];
__device__ float g_inpb[B_*H_*W_];
__device__ float g_diffb[B_*H_*W_];
__device__ float g_bf[R_ELEMS];
__device__ float g_fn[R_ELEMS];
__device__ float g_r1[R_ELEMS];
__device__ float g_r2[R_ELEMS];
__device__ float g_wt[WT_TOTAL];

// ---------------- packed f32x2 helpers ----------------
typedef unsigned long long ull;

__device__ __forceinline__ ull ffma2(ull a, ull b, ull c) {
    ull d;
    asm("fma.rn.f32x2 %0, %1, %2, %3;" : "=l"(d) : "l"(a), "l"(b), "l"(c));
    return d;
}
__device__ __forceinline__ ull splat2(float x) {
    ull d; asm("mov.b64 %0, {%1, %1};" : "=l"(d) : "f"(x)); return d;
}
__device__ __forceinline__ float2 unpack2(ull a) {
    float2 r; asm("mov.b64 {%0, %1}, %2;" : "=f"(r.x), "=f"(r.y) : "l"(a)); return r;
}

__device__ __forceinline__ float gelu_exact(float y) {
    return 0.5f * y * (1.0f + erff(y * 0.70710678118654752f));
}

// ---------------- weight transpose: [O][I][k2] -> [I][k2][O] (O=64) ----------------
__global__ void transpose_w_kernel(const float* __restrict__ src, float* __restrict__ dst,
                                   int CIN, int KK)
{
    int total = CIN * KK * 64;
    for (int idx = blockIdx.x * blockDim.x + threadIdx.x; idx < total;
         idx += gridDim.x * blockDim.x) {
        int o  = idx & 63;
        int ct = idx >> 6;
        int t  = ct % KK;
        int c  = ct / KK;
        dst[idx] = src[(o * CIN + c) * KK + t];
    }
}

// ---------------- generic direct conv, Cout=64, 32x16 tile, f32x2 inner ----------------
// MODE 0: out = beta*(acc+bias)     MODE 1: out = gelu(bn(acc+bias))
template<int K, int CK, int CIN, int MODE, bool CONCAT>
__global__ __launch_bounds__(256)
void conv_main(const float* __restrict__ inA, const float* __restrict__ inB,
               const float* __restrict__ Wt,     // [CIN][K*K][64] transposed
               const float* __restrict__ bias,
               const float* __restrict__ gg, const float* __restrict__ bb,
               const float* __restrict__ mm, const float* __restrict__ vv,
               const float* __restrict__ betap,
               float* __restrict__ out, int H, int W)
{
    constexpr int KK  = K * K;
    constexpr int PAD = K / 2;
    constexpr int IH  = 16 + K - 1;
    constexpr int IW  = 32 + K - 1;

    __shared__ __align__(16) float s_in[CK * IH * IW];
    __shared__ __align__(16) float s_w[CK * KK * 16];

    int tid = threadIdx.x;
    int tx = tid & 31, ty = tid >> 5;
    int x0  = blockIdx.x * 32;
    int y0r = blockIdx.y * 16;
    int b   = blockIdx.z >> 2;
    int oc0 = (blockIdx.z & 3) << 4;
    size_t HW = (size_t)H * W;

    ull acc[8][2];
#pragma unroll
    for (int i = 0; i < 8; i++) { acc[i][0] = 0ULL; acc[i][1] = 0ULL; }

    for (int c0 = 0; c0 < CIN; c0 += CK) {
        // ---- stage input tile ----
        for (int idx = tid; idx < CK * IH * IW; idx += 256) {
            int c  = idx / (IH * IW);
            int r  = idx - c * IH * IW;
            int ly = r / IW, lx = r - ly * IW;
            int gy = y0r + ly - PAD, gx = x0 + lx - PAD;
            float v = 0.f;
            if ((unsigned)gy < (unsigned)H && (unsigned)gx < (unsigned)W) {
                int cc = c0 + c;
                const float* src;
                if (CONCAT) {
                    src = (cc < 64) ? (inA + (size_t)(b * 64 + cc) * HW)
                                    : (inB + (size_t)(b * 64 + cc - 64) * HW);
                } else {
                    src = inA + ((size_t)b * CIN + cc) * HW;
                }
                v = src[(size_t)gy * W + gx];
            }
            s_in[idx] = v;
        }
        // ---- stage weights ----
        for (int idx = tid; idx < CK * KK * 16; idx += 256) {
            int o  = idx & 15;
            int ct = idx >> 4;
            int t  = ct % KK, c = ct / KK;
            s_w[idx] = Wt[((size_t)(c0 + c) * KK + t) * 64 + oc0 + o];
        }
        __syncthreads();

        // ---- compute ----
#pragma unroll
        for (int c = 0; c < CK; c++) {
            for (int ky = 0; ky < K; ky++) {
#pragma unroll
                for (int kx = 0; kx < K; kx++) {
                    float v0 = s_in[(c * IH + ty + ky) * IW + tx + kx];
                    float v1 = s_in[(c * IH + ty + 8 + ky) * IW + tx + kx];
                    ull a2 = splat2(v0), b2 = splat2(v1);
                    const ull* wp = (const ull*)&s_w[(c * KK + ky * K + kx) * 16];
#pragma unroll
                    for (int op = 0; op < 8; op++) {
                        ull w2 = wp[op];
                        acc[op][0] = ffma2(w2, a2, acc[op][0]);
                        acc[op][1] = ffma2(w2, b2, acc[op][1]);
                    }
                }
            }
        }
        __syncthreads();
    }

    // ---- epilogue ----
    int ox = x0 + tx;
    float beta = 0.f;
    if (MODE == 0) beta = __ldg(betap);
#pragma unroll
    for (int op = 0; op < 8; op++) {
        int oc_a = oc0 + 2 * op, oc_b = oc_a + 1;
        float sA, tA, sB, tB;
        if (MODE == 1) {
            sA = gg[oc_a] * rsqrtf(vv[oc_a] + 1e-5f);
            tA = (bias[oc_a] - mm[oc_a]) * sA + bb[oc_a];
            sB = gg[oc_b] * rsqrtf(vv[oc_b] + 1e-5f);
            tB = (bias[oc_b] - mm[oc_b]) * sB + bb[oc_b];
        } else {
            sA = beta; tA = beta * bias[oc_a];
            sB = beta; tB = beta * bias[oc_b];
        }
#pragma unroll
        for (int px = 0; px < 2; px++) {
            int oy = y0r + ty + px * 8;
            float2 v = unpack2(acc[op][px]);
            float ya = v.x * sA + tA;
            float yb = v.y * sB + tB;
            if (MODE == 1) { ya = gelu_exact(ya); yb = gelu_exact(yb); }
            out[(size_t)(b * 64 + oc_a) * HW + (size_t)oy * W + ox] = ya;
            out[(size_t)(b * 64 + oc_b) * HW + (size_t)oy * W + ox] = yb;
        }
    }
}

// ---------------- bilinear up x2, align_corners=True, optional sigmoid ----------------
__global__ void up2_kernel(const float* __restrict__ in, float* __restrict__ out,
                           int BC, int n, int do_sigmoid)
{
    int N = 2 * n;
    size_t total = (size_t)BC * N * N;
    size_t idx = (size_t)blockIdx.x * blockDim.x + threadIdx.x;
    if (idx >= total) return;
    int xo = (int)(idx % N);
    size_t r = idx / N;
    int yo = (int)(r % N);
    int bc = (int)(r / N);
    float rr = (float)(n - 1) / (float)(N - 1);
    float sy = yo * rr; int iy0 = (int)sy; float wy = sy - (float)iy0; int iy1 = min(iy0 + 1, n - 1);
    float sx = xo * rr; int ix0 = (int)sx; float wx = sx - (float)ix0; int ix1 = min(ix0 + 1, n - 1);
    const float* p = in + (size_t)bc * n * n;
    float a = p[iy0 * n + ix0], bv = p[iy1 * n + ix0];
    float c = p[iy0 * n + ix1], d = p[iy1 * n + ix1];
    float ra = a * (1.f - wy) + bv * wy;
    float rb = c * (1.f - wy) + d * wy;
    float v  = ra * (1.f - wx) + rb * wx;
    if (do_sigmoid) v = 1.f / (1.f + expf(-v));
    out[idx] = v;
}

// ---------------- AP_MP(small,x) + AP_MP(x,small) at half resolution ----------------
__global__ void diff_kernel(const float* __restrict__ sm, const float* __restrict__ x,
                            float* __restrict__ out)
{
    int idx = blockIdx.x * blockDim.x + threadIdx.x;
    if (idx >= B_ * h_ * w_) return;
    int j = idx % w_;
    int t = idx / w_;
    int i = t % h_;
    int b = t / h_;
    float acc1 = 0.f, acc2 = 0.f;
    size_t base0 = ((size_t)b * 64 * H_ + 2 * i) * W_ + 2 * j;
    for (int c = 0; c < 64; c++) {
        size_t base = base0 + (size_t)c * H_ * W_;
        float2 s0 = *(const float2*)(sm + base);
        float2 s1 = *(const float2*)(sm + base + W_);
        float2 xa = *(const float2*)(x + base);
        float2 xb = *(const float2*)(x + base + W_);
        float as = 0.25f * (s0.x + s0.y + s1.x + s1.y);
        float ms = fmaxf(fmaxf(s0.x, s0.y), fmaxf(s1.x, s1.y));
        float ax = 0.25f * (xa.x + xa.y + xb.x + xb.y);
        float mx = fmaxf(fmaxf(xa.x, xa.y), fmaxf(xb.x, xb.y));
        float d1 = as - mx; acc1 += d1 * d1;
        float d2 = ax - ms; acc2 += d2 * d2;
    }
    out[idx] = sqrtf(acc1) + sqrtf(acc2);
}

// ---------------- dilate3 - map (two maps) + 1, times x -> b_feature ----------------
__global__ __launch_bounds__(256)
void scale_bf_kernel(const float* __restrict__ x, const float* __restrict__ inp,
                     const float* __restrict__ dif, float* __restrict__ bf)
{
    int tx = threadIdx.x & 31, ty = threadIdx.x >> 5;
    int gx = blockIdx.x * 32 + tx;
    int gy = blockIdx.y * 8 + ty;
    int b  = blockIdx.z;
    const float* ip = inp + (size_t)b * H_ * W_;
    const float* dp = dif + (size_t)b * H_ * W_;
    float mi = -INFINITY, md = -INFINITY;
    for (int dy = -1; dy <= 1; dy++) {
        int yy = gy + dy; if ((unsigned)yy >= (unsigned)H_) continue;
        for (int dx = -1; dx <= 1; dx++) {
            int xx = gx + dx; if ((unsigned)xx >= (unsigned)W_) continue;
            mi = fmaxf(mi, ip[yy * W_ + xx]);
            md = fmaxf(md, dp[yy * W_ + xx]);
        }
    }
    float s = (mi - ip[gy * W_ + gx]) + (md - dp[gy * W_ + gx]) + 1.0f;
    size_t base = ((size_t)b * 64 * H_ + gy) * W_ + gx;
    for (int c = 0; c < 64; c++) {
        size_t o = base + (size_t)c * H_ * W_;
        bf[o] = x[o] * s;
    }
}

// ---------------- final conv 7x7, 64 -> 1 ----------------
__global__ __launch_bounds__(256)
void conv_out_kernel(const float* __restrict__ rin, const float* __restrict__ Wo,
                     const float* __restrict__ bo, float* __restrict__ out)
{
    __shared__ float s_in[8 * 14 * 38];
    __shared__ float s_w[8 * 49];
    int tid = threadIdx.x, tx = tid & 31, ty = tid >> 5;
    int x0 = blockIdx.x * 32, ys = blockIdx.y * 8, b = blockIdx.z;
    float acc = 0.f;
    for (int c0 = 0; c0 < 64; c0 += 8) {
        for (int idx = tid; idx < 8 * 14 * 38; idx += 256) {
            int c = idx / (14 * 38);
            int r = idx - c * (14 * 38);
            int ly = r / 38, lx = r - ly * 38;
            int gy = ys + ly - 3, gx = x0 + lx - 3;
            float v = 0.f;
            if ((unsigned)gy < (unsigned)H_ && (unsigned)gx < (unsigned)W_)
                v = rin[((size_t)(b * 64 + c0 + c) * H_ + gy) * W_ + gx];
            s_in[idx] = v;
        }
        for (int idx = tid; idx < 8 * 49; idx += 256)
            s_w[idx] = Wo[(c0 + idx / 49) * 49 + idx % 49];
        __syncthreads();
#pragma unroll
        for (int c = 0; c < 8; c++)
            for (int ky = 0; ky < 7; ky++)
#pragma unroll
                for (int kx = 0; kx < 7; kx++)
                    acc += s_w[c * 49 + ky * 7 + kx] * s_in[(c * 14 + ty + ky) * 38 + tx + kx];
        __syncthreads();
    }
    out[((size_t)b * H_ + (ys + ty)) * W_ + x0 + tx] = acc + bo[0];
}

// ---------------- launch ----------------
extern "C" void kernel_launch(void* const* d_in, const int* in_sizes, int n_in,
                              void* d_out, int out_size)
{
    const float* x       = (const float*)d_in[0];
    const float* small_x = (const float*)d_in[1];
    const float* in_map  = (const float*)d_in[2];
    const float* W_up  = (const float*)d_in[3];
    const float* b_up  = (const float*)d_in[4];
    const float* gup   = (const float*)d_in[5];
    const float* beup  = (const float*)d_in[6];
    const float* mup   = (const float*)d_in[7];
    const float* vup   = (const float*)d_in[8];
    const float* W_c2  = (const float*)d_in[9];
    const float* b_c2  = (const float*)d_in[10];
    const float* W_d1  = (const float*)d_in[11];
    const float* b_d1  = (const float*)d_in[12];
    const float* gd1   = (const float*)d_in[13];
    const float* bed1  = (const float*)d_in[14];
    const float* md1   = (const float*)d_in[15];
    const float* vd1   = (const float*)d_in[16];
    const float* W_d2  = (const float*)d_in[17];
    const float* b_d2  = (const float*)d_in[18];
    const float* gd2   = (const float*)d_in[19];
    const float* bed2  = (const float*)d_in[20];
    const float* md2   = (const float*)d_in[21];
    const float* vd2   = (const float*)d_in[22];
    const float* W_d3  = (const float*)d_in[23];
    const float* b_d3  = (const float*)d_in[24];
    const float* gd3   = (const float*)d_in[25];
    const float* bed3  = (const float*)d_in[26];
    const float* md3   = (const float*)d_in[27];
    const float* vd3   = (const float*)d_in[28];
    const float* W_out = (const float*)d_in[29];
    const float* b_out = (const float*)d_in[30];
    const float* beta  = (const float*)d_in[31];

    float *u, *sm, *ds, *ib, *db, *bf, *fn, *r1, *r2, *wt;
    cudaGetSymbolAddress((void**)&u,  g_u);
    cudaGetSymbolAddress((void**)&sm, g_small);
    cudaGetSymbolAddress((void**)&ds, g_diffs);
    cudaGetSymbolAddress((void**)&ib, g_inpb);
    cudaGetSymbolAddress((void**)&db, g_diffb);
    cudaGetSymbolAddress((void**)&bf, g_bf);
    cudaGetSymbolAddress((void**)&fn, g_fn);
    cudaGetSymbolAddress((void**)&r1, g_r1);
    cudaGetSymbolAddress((void**)&r2, g_r2);
    cudaGetSymbolAddress((void**)&wt, g_wt);

    // 1) pre-transpose weights to [CIN][k2][64]
    transpose_w_kernel<<<128, 256>>>(W_up, wt + WT_UP, 128, 49);
    transpose_w_kernel<<<32, 256>>>(W_c2, wt + WT_C2, 64, 9);
    transpose_w_kernel<<<64, 256>>>(W_d1, wt + WT_D1, 128, 9);
    transpose_w_kernel<<<32, 256>>>(W_d2, wt + WT_D2, 64, 9);
    transpose_w_kernel<<<32, 256>>>(W_d3, wt + WT_D3, 64, 9);

    // 2) up branch: conv7x7 + BN + GELU -> bilinear up x2
    conv_main<7, 4, 128, 1, false><<<dim3(3, 6, 32), 256>>>(
        small_x, nullptr, wt + WT_UP, b_up, gup, beup, mup, vup, nullptr, u, h_, w_);
    up2_kernel<<<(R_ELEMS + 255) / 256, 256>>>(u, sm, B_ * C1_, h_, 0);

    // 3) uncertainty maps
    diff_kernel<<<(B_ * h_ * w_ + 255) / 256, 256>>>(sm, x, ds);
    up2_kernel<<<(B_ * H_ * W_ + 255) / 256, 256>>>(in_map, ib, B_, h_, 1);
    up2_kernel<<<(B_ * H_ * W_ + 255) / 256, 256>>>(ds, db, B_, h_, 1);
    scale_bf_kernel<<<dim3(6, 24, 8), 256>>>(x, ib, db, bf);

    // 4) conv chain
    conv_main<3, 8, 64, 0, false><<<dim3(6, 12, 32), 256>>>(
        bf, nullptr, wt + WT_C2, b_c2, nullptr, nullptr, nullptr, nullptr, beta, fn, H_, W_);
    conv_main<3, 8, 128, 1, true><<<dim3(6, 12, 32), 256>>>(
        sm, fn, wt + WT_D1, b_d1, gd1, bed1, md1, vd1, nullptr, r1, H_, W_);
    conv_main<3, 8, 64, 1, false><<<dim3(6, 12, 32), 256>>>(
        r1, nullptr, wt + WT_D2, b_d2, gd2, bed2, md2, vd2, nullptr, r2, H_, W_);
    conv_main<3, 8, 64, 1, false><<<dim3(6, 12, 32), 256>>>(
        r2, nullptr, wt + WT_D3, b_d3, gd3, bed3, md3, vd3, nullptr, (float*)d_out, H_, W_);

    // 5) output head reads r from d_out, writes output_map after it
    conv_out_kernel<<<dim3(6, 24, 8), 256>>>(
        (const float*)d_out, W_out, b_out, (float*)d_out + R_ELEMS);
}

// round 4
// speedup vs baseline: 2.2539x; 2.2539x over previous
#include <cuda_runtime.h>
#include <cuda_bf16.h>
#include <math.h>
#include <stdint.h>

// ---------------- problem constants ----------------
#define B_ 8
#define H_ 192
#define W_ 192
#define h_ 96
#define w_ 96
#define R_ELEMS (B_*64*H_*W_)        // 18,874,368

// weight-chunk table (each chunk = 16KB: 8KB hi + 8KB lo, [n][k] swizzled bf16)
#define CH_UP 0      // 7x7, CG=2 -> 98 chunks
#define CH_C2 98     // 3x3, CG=1 -> 9
#define CH_D1 107    // 3x3, CG=2 -> 18
#define CH_D2 125    // 9
#define CH_D3 134    // 9
#define CH_TOTAL 143

// ---------------- scratch ----------------
__device__ __align__(16) unsigned char g_wbf[CH_TOTAL * 16384];
__device__ float g_u[B_*64*h_*w_];
__device__ float g_small[R_ELEMS];
__device__ float g_diffs[B_*h_*w_];
__device__ float g_inpb[B_*H_*W_];
__device__ float g_diffb[B_*H_*W_];
__device__ float g_bf[R_ELEMS];
__device__ float g_fn[R_ELEMS];
__device__ float g_r1[R_ELEMS];
__device__ float g_r2[R_ELEMS];

// ---------------- helpers ----------------
__device__ __forceinline__ uint32_t smem_u32(const void* p) {
    uint32_t a;
    asm("{ .reg .u64 t; cvta.to.shared.u64 t, %1; cvt.u32.u64 %0, t; }" : "=r"(a) : "l"(p));
    return a;
}
__device__ __forceinline__ void ldm4(uint32_t addr, uint32_t r[4]) {
    asm volatile("ldmatrix.sync.aligned.m8n8.x4.shared.b16 {%0,%1,%2,%3}, [%4];"
                 : "=r"(r[0]), "=r"(r[1]), "=r"(r[2]), "=r"(r[3]) : "r"(addr));
}
__device__ __forceinline__ void mma16816(float c[4], const uint32_t a[4],
                                         uint32_t b0, uint32_t b1) {
    asm volatile(
        "mma.sync.aligned.m16n8k16.row.col.f32.bf16.bf16.f32 "
        "{%0,%1,%2,%3}, {%4,%5,%6,%7}, {%8,%9}, {%0,%1,%2,%3};"
        : "+f"(c[0]), "+f"(c[1]), "+f"(c[2]), "+f"(c[3])
        : "r"(a[0]), "r"(a[1]), "r"(a[2]), "r"(a[3]), "r"(b0), "r"(b1));
}
__device__ __forceinline__ float gelu_exact(float y) {
    return 0.5f * y * (1.0f + erff(y * 0.70710678118654752f));
}
__device__ __forceinline__ uint32_t packbf2(float a, float b) {
    __nv_bfloat16 ha = __float2bfloat16(a), hb = __float2bfloat16(b);
    return (uint32_t)__bfloat16_as_ushort(ha) | ((uint32_t)__bfloat16_as_ushort(hb) << 16);
}

// ---------------- weight prep: OIHW fp32 -> [n][k] swizzled bf16 hi/lo chunks ----------------
__global__ void prep_w(const float* __restrict__ W, unsigned char* __restrict__ dst,
                       int CIN, int KS)
{
    int CG = CIN >> 6;
    int KK = KS * KS;
    int total = KK * CG * 4096;
    for (int idx = blockIdx.x * blockDim.x + threadIdx.x; idx < total;
         idx += gridDim.x * blockDim.x) {
        int chunk = idx >> 12;
        int e = idx & 4095;
        int n = e >> 6, k = e & 63;
        int tap = chunk / CG, cg = chunk - tap * CG;
        float w = W[((size_t)n * CIN + cg * 64 + k) * KK + tap];
        __nv_bfloat16 hb = __float2bfloat16(w);
        __nv_bfloat16 lb = __float2bfloat16(w - __bfloat162float(hb));
        uint32_t off = (uint32_t)n * 128 + ((((k >> 3) ^ (n & 7))) << 4) + (k & 7) * 2;
        unsigned char* base = dst + (size_t)chunk * 16384;
        *(unsigned short*)(base + off)        = __bfloat16_as_ushort(hb);
        *(unsigned short*)(base + 8192 + off) = __bfloat16_as_ushort(lb);
    }
}

// ---------------- HMMA implicit-GEMM conv ----------------
// 128-pixel tile (4y x 32x), all 64 out channels. Halo staged once per cg,
// per-tap A matrices addressed via per-lane ldmatrix pointers into the halo.
// MODE 0: out = beta*(acc+bias)   MODE 1: out = gelu(bn(acc+bias))
template<int KS, int CG, int MODE, bool CONCAT>
__global__ __launch_bounds__(256)
void tconv(const float* __restrict__ inA, const float* __restrict__ inB,
           const uint4* __restrict__ wch, const float* __restrict__ bias,
           const float* __restrict__ gg, const float* __restrict__ bb,
           const float* __restrict__ mm, const float* __restrict__ vv,
           const float* __restrict__ betap, float* __restrict__ out,
           int H, int W)
{
    constexpr int PAD = KS / 2;
    constexpr int IH  = 4 + KS - 1;
    constexpr int IWP = 40;
    constexpr int NPX = IH * IWP;                 // halo pixels
    constexpr int HB  = NPX * 128;                // bytes per halo copy (hi or lo)
    constexpr int OFF_AH = 1024;
    constexpr int OFF_AL = 1024 + HB;
    constexpr int OFF_B  = 1024 + 2 * HB;

    extern __shared__ char smem_raw[];
    char* smem = (char*)(((uintptr_t)smem_raw + 1023) & ~(uintptr_t)1023);
    uint32_t sb = smem_u32(smem);
    float* epi = (float*)smem;                    // 128 floats at offset 0

    int tid = threadIdx.x, wid = tid >> 5, lane = tid & 31;
    int x0 = blockIdx.x * 32, y0 = blockIdx.y * 4, b = blockIdx.z;
    size_t HW = (size_t)H * W;

    // epilogue constants
    if (tid < 64) {
        int c = tid;
        float s, t;
        if (MODE == 1) {
            s = gg[c] * rsqrtf(vv[c] + 1e-5f);
            t = (bias[c] - mm[c]) * s + bb[c];
        } else {
            float bt = *betap;
            s = bt; t = bt * bias[c];
        }
        epi[c] = s; epi[64 + c] = t;
    }

    float acc[8][4];
#pragma unroll
    for (int i = 0; i < 8; i++)
#pragma unroll
        for (int j = 0; j < 4; j++) acc[i][j] = 0.f;

    // per-lane A fragment geometry (fixed across taps)
    int ar = lane & 15, akq = lane >> 4;
    int ap = (wid << 4) + ar;
    int apy = ap >> 5, apx = ap & 31;
    // per-lane B fragment geometry
    int br = lane & 15, bkq = lane >> 4;

    int gctr = 0;
    for (int cg = 0; cg < CG; cg++) {
        __syncthreads();   // protect halo from previous taps' readers

        // ---- stage halo: NPX pixels x 64 chans, fp32 -> bf16 hi/lo ----
        {
            const float* src;
            if (CONCAT) src = (cg ? inB : inA) + (size_t)b * 64 * HW;
            else        src = inA + ((size_t)b * (CG * 64) + cg * 64) * HW;
            constexpr int TOT = NPX * 8;
            for (int item = tid; item < TOT; item += 256) {
                int o  = item / NPX;
                int ph = item - o * NPX;
                int hy = ph / IWP, hx = ph - hy * IWP;
                int gy = y0 + hy - PAD;
                int gx = x0 + hx - 4;
                float v[8];
                if ((unsigned)gy < (unsigned)H && (unsigned)gx < (unsigned)W) {
                    const float* p = src + (size_t)(o * 8) * HW + (size_t)gy * W + gx;
#pragma unroll
                    for (int j = 0; j < 8; j++) v[j] = p[j * HW];
                } else {
#pragma unroll
                    for (int j = 0; j < 8; j++) v[j] = 0.f;
                }
                uint4 hi4, lo4;
                float l[8];
#pragma unroll
                for (int j = 0; j < 8; j++) {
                    __nv_bfloat16 hh = __float2bfloat16(v[j]);
                    l[j] = v[j] - __bfloat162float(hh);
                }
                hi4.x = packbf2(v[0], v[1]); hi4.y = packbf2(v[2], v[3]);
                hi4.z = packbf2(v[4], v[5]); hi4.w = packbf2(v[6], v[7]);
                lo4.x = packbf2(l[0], l[1]); lo4.y = packbf2(l[2], l[3]);
                lo4.z = packbf2(l[4], l[5]); lo4.w = packbf2(l[6], l[7]);
                uint32_t ad = (uint32_t)ph * 128 + (((o ^ (ph & 7))) << 4);
                *(uint4*)(smem + OFF_AH + ad) = hi4;
                *(uint4*)(smem + OFF_AL + ad) = lo4;
            }
        }

        for (int tap = 0; tap < KS * KS; tap++, gctr++) {
            int buf = gctr & 1;
            // ---- stage B chunk (16KB copy) ----
            {
                const uint4* srcB = wch + (size_t)(tap * CG + cg) * 1024;
                uint4* dstB = (uint4*)(smem + OFF_B + buf * 16384);
#pragma unroll
                for (int k = 0; k < 4; k++) dstB[tid + k * 256] = srcB[tid + k * 256];
            }
            __syncthreads();

            int tapy = tap / KS, tapx = tap - tapy * KS;
            int ph = (apy + tapy) * IWP + apx + tapx + (4 - PAD);
            uint32_t arow_h = sb + OFF_AH + (uint32_t)ph * 128;
            uint32_t arow_l = sb + OFF_AL + (uint32_t)ph * 128;
            int asw = ph & 7;
            uint32_t bbase = sb + OFF_B + buf * 16384;

#pragma unroll
            for (int kc = 0; kc < 4; kc++) {
                int acolq = (kc * 2 + akq) ^ asw;
                uint32_t ah[4], al[4];
                ldm4(arow_h + (acolq << 4), ah);
                ldm4(arow_l + (acolq << 4), al);
#pragma unroll
                for (int g = 0; g < 4; g++) {
                    int n = g * 16 + br;
                    uint32_t ba = bbase + (uint32_t)n * 128 + ((((kc * 2 + bkq) ^ (n & 7))) << 4);
                    uint32_t bh[4], bl[4];
                    ldm4(ba, bh);
                    ldm4(ba + 8192, bl);
                    mma16816(acc[2 * g],     ah, bh[0], bh[2]);
                    mma16816(acc[2 * g + 1], ah, bh[1], bh[3]);
                    mma16816(acc[2 * g],     ah, bl[0], bl[2]);
                    mma16816(acc[2 * g + 1], ah, bl[1], bl[3]);
                    mma16816(acc[2 * g],     al, bh[0], bh[2]);
                    mma16816(acc[2 * g + 1], al, bh[1], bh[3]);
                }
            }
        }
    }

    // ---- epilogue: transpose through smem, coalesced NCHW store ----
    __syncthreads();
    float* tb = (float*)(smem + 1024);            // [128][65] fp32 (stride 65: conflict-free)
    {
        int row = lane >> 2, colp = (lane & 3) * 2;
        int p0 = (wid << 4) + row;
#pragma unroll
        for (int t = 0; t < 8; t++) {
            int n0 = t * 8 + colp;
            // scalar stores: stride-65 rows break float2 alignment for odd p0
            tb[p0 * 65 + n0]           = acc[t][0];
            tb[p0 * 65 + n0 + 1]       = acc[t][1];
            tb[(p0 + 8) * 65 + n0]     = acc[t][2];
            tb[(p0 + 8) * 65 + n0 + 1] = acc[t][3];
        }
    }
    __syncthreads();
#pragma unroll 4
    for (int it = 0; it < 32; it++) {
        int item = it * 8 + wid;
        int c = item >> 2, py = item & 3;
        float v = tb[(py * 32 + lane) * 65 + c] * epi[c] + epi[64 + c];
        if (MODE == 1) v = gelu_exact(v);
        out[((size_t)(b * 64 + c) * H + (y0 + py)) * W + x0 + lane] = v;
    }
}

// ---------------- bilinear up x2, align_corners=True, optional sigmoid ----------------
__global__ void up2_kernel(const float* __restrict__ in, float* __restrict__ out,
                           int BC, int n, int do_sigmoid)
{
    int N = 2 * n;
    size_t total = (size_t)BC * N * N;
    size_t idx = (size_t)blockIdx.x * blockDim.x + threadIdx.x;
    if (idx >= total) return;
    int xo = (int)(idx % N);
    size_t r = idx / N;
    int yo = (int)(r % N);
    int bc = (int)(r / N);
    float rr = (float)(n - 1) / (float)(N - 1);
    float sy = yo * rr; int iy0 = (int)sy; float wy = sy - (float)iy0; int iy1 = min(iy0 + 1, n - 1);
    float sx = xo * rr; int ix0 = (int)sx; float wx = sx - (float)ix0; int ix1 = min(ix0 + 1, n - 1);
    const float* p = in + (size_t)bc * n * n;
    float a = p[iy0 * n + ix0], bv = p[iy1 * n + ix0];
    float c = p[iy0 * n + ix1], d = p[iy1 * n + ix1];
    float ra = a * (1.f - wy) + bv * wy;
    float rb = c * (1.f - wy) + d * wy;
    float v  = ra * (1.f - wx) + rb * wx;
    if (do_sigmoid) v = 1.f / (1.f + expf(-v));
    out[idx] = v;
}

// ---------------- AP_MP(small,x) + AP_MP(x,small) at half resolution ----------------
__global__ void diff_kernel(const float* __restrict__ sm, const float* __restrict__ x,
                            float* __restrict__ out)
{
    int idx = blockIdx.x * blockDim.x + threadIdx.x;
    if (idx >= B_ * h_ * w_) return;
    int j = idx % w_;
    int t = idx / w_;
    int i = t % h_;
    int b = t / h_;
    float acc1 = 0.f, acc2 = 0.f;
    size_t base0 = ((size_t)b * 64 * H_ + 2 * i) * W_ + 2 * j;
    for (int c = 0; c < 64; c++) {
        size_t base = base0 + (size_t)c * H_ * W_;
        float2 s0 = *(const float2*)(sm + base);
        float2 s1 = *(const float2*)(sm + base + W_);
        float2 xa = *(const float2*)(x + base);
        float2 xb = *(const float2*)(x + base + W_);
        float as = 0.25f * (s0.x + s0.y + s1.x + s1.y);
        float ms = fmaxf(fmaxf(s0.x, s0.y), fmaxf(s1.x, s1.y));
        float ax = 0.25f * (xa.x + xa.y + xb.x + xb.y);
        float mx = fmaxf(fmaxf(xa.x, xa.y), fmaxf(xb.x, xb.y));
        float d1 = as - mx; acc1 += d1 * d1;
        float d2 = ax - ms; acc2 += d2 * d2;
    }
    out[idx] = sqrtf(acc1) + sqrtf(acc2);
}

// ---------------- b_feature = x * (dilate3(inp)-inp + dilate3(dif)-dif + 1) ----------------
__global__ __launch_bounds__(256)
void scale_bf_kernel(const float* __restrict__ x, const float* __restrict__ inp,
                     const float* __restrict__ dif, float* __restrict__ bf)
{
    int tx = threadIdx.x & 31, ty = threadIdx.x >> 5;
    int gx = blockIdx.x * 32 + tx;
    int gy = blockIdx.y * 8 + ty;
    int b  = blockIdx.z;
    const float* ip = inp + (size_t)b * H_ * W_;
    const float* dp = dif + (size_t)b * H_ * W_;
    float mi = -INFINITY, md = -INFINITY;
    for (int dy = -1; dy <= 1; dy++) {
        int yy = gy + dy; if ((unsigned)yy >= (unsigned)H_) continue;
        for (int dx = -1; dx <= 1; dx++) {
            int xx = gx + dx; if ((unsigned)xx >= (unsigned)W_) continue;
            mi = fmaxf(mi, ip[yy * W_ + xx]);
            md = fmaxf(md, dp[yy * W_ + xx]);
        }
    }
    float s = (mi - ip[gy * W_ + gx]) + (md - dp[gy * W_ + gx]) + 1.0f;
    size_t base = ((size_t)b * 64 * H_ + gy) * W_ + gx;
    for (int c = 0; c < 64; c++) {
        size_t o = base + (size_t)c * H_ * W_;
        bf[o] = x[o] * s;
    }
}

// ---------------- final conv 7x7, 64 -> 1 (fp32) ----------------
__global__ __launch_bounds__(256)
void conv_out_kernel(const float* __restrict__ rin, const float* __restrict__ Wo,
                     const float* __restrict__ bo, float* __restrict__ out)
{
    __shared__ float s_in[8 * 14 * 38];
    __shared__ float s_w[8 * 49];
    int tid = threadIdx.x, tx = tid & 31, ty = tid >> 5;
    int x0 = blockIdx.x * 32, ys = blockIdx.y * 8, b = blockIdx.z;
    float acc = 0.f;
    for (int c0 = 0; c0 < 64; c0 += 8) {
        for (int idx = tid; idx < 8 * 14 * 38; idx += 256) {
            int c = idx / (14 * 38);
            int r = idx - c * (14 * 38);
            int ly = r / 38, lx = r - ly * 38;
            int gy = ys + ly - 3, gx = x0 + lx - 3;
            float v = 0.f;
            if ((unsigned)gy < (unsigned)H_ && (unsigned)gx < (unsigned)W_)
                v = rin[((size_t)(b * 64 + c0 + c) * H_ + gy) * W_ + gx];
            s_in[idx] = v;
        }
        for (int idx = tid; idx < 8 * 49; idx += 256)
            s_w[idx] = Wo[(c0 + idx / 49) * 49 + idx % 49];
        __syncthreads();
#pragma unroll
        for (int c = 0; c < 8; c++)
            for (int ky = 0; ky < 7; ky++)
#pragma unroll
                for (int kx = 0; kx < 7; kx++)
                    acc += s_w[c * 49 + ky * 7 + kx] * s_in[(c * 14 + ty + ky) * 38 + tx + kx];
        __syncthreads();
    }
    out[((size_t)b * H_ + (ys + ty)) * W_ + x0 + tx] = acc + bo[0];
}

// ---------------- launch ----------------
#define SMEM3 (1024 + 2*(6*40*128)  + 32768 + 1024)   // 96256
#define SMEM7 (1024 + 2*(10*40*128) + 32768 + 1024)   // 137216

extern "C" void kernel_launch(void* const* d_in, const int* in_sizes, int n_in,
                              void* d_out, int out_size)
{
    const float* x       = (const float*)d_in[0];
    const float* small_x = (const float*)d_in[1];
    const float* in_map  = (const float*)d_in[2];
    const float* W_up  = (const float*)d_in[3];
    const float* b_up  = (const float*)d_in[4];
    const float* gup   = (const float*)d_in[5];
    const float* beup  = (const float*)d_in[6];
    const float* mup   = (const float*)d_in[7];
    const float* vup   = (const float*)d_in[8];
    const float* W_c2  = (const float*)d_in[9];
    const float* b_c2  = (const float*)d_in[10];
    const float* W_d1  = (const float*)d_in[11];
    const float* b_d1  = (const float*)d_in[12];
    const float* gd1   = (const float*)d_in[13];
    const float* bed1  = (const float*)d_in[14];
    const float* md1   = (const float*)d_in[15];
    const float* vd1   = (const float*)d_in[16];
    const float* W_d2  = (const float*)d_in[17];
    const float* b_d2  = (const float*)d_in[18];
    const float* gd2   = (const float*)d_in[19];
    const float* bed2  = (const float*)d_in[20];
    const float* md2   = (const float*)d_in[21];
    const float* vd2   = (const float*)d_in[22];
    const float* W_d3  = (const float*)d_in[23];
    const float* b_d3  = (const float*)d_in[24];
    const float* gd3   = (const float*)d_in[25];
    const float* bed3  = (const float*)d_in[26];
    const float* md3   = (const float*)d_in[27];
    const float* vd3   = (const float*)d_in[28];
    const float* W_out = (const float*)d_in[29];
    const float* b_out = (const float*)d_in[30];
    const float* beta  = (const float*)d_in[31];

    float *u, *sm, *ds, *ib, *db, *bf, *fn, *r1, *r2;
    unsigned char* wbf;
    cudaGetSymbolAddress((void**)&u,   g_u);
    cudaGetSymbolAddress((void**)&sm,  g_small);
    cudaGetSymbolAddress((void**)&ds,  g_diffs);
    cudaGetSymbolAddress((void**)&ib,  g_inpb);
    cudaGetSymbolAddress((void**)&db,  g_diffb);
    cudaGetSymbolAddress((void**)&bf,  g_bf);
    cudaGetSymbolAddress((void**)&fn,  g_fn);
    cudaGetSymbolAddress((void**)&r1,  g_r1);
    cudaGetSymbolAddress((void**)&r2,  g_r2);
    cudaGetSymbolAddress((void**)&wbf, g_wbf);

    cudaFuncSetAttribute(tconv<7,2,1,false>, cudaFuncAttributeMaxDynamicSharedMemorySize, SMEM7);
    cudaFuncSetAttribute(tconv<3,1,0,false>, cudaFuncAttributeMaxDynamicSharedMemorySize, SMEM3);
    cudaFuncSetAttribute(tconv<3,2,1,true>,  cudaFuncAttributeMaxDynamicSharedMemorySize, SMEM3);
    cudaFuncSetAttribute(tconv<3,1,1,false>, cudaFuncAttributeMaxDynamicSharedMemorySize, SMEM3);

    // 1) weight prep
    prep_w<<<392, 256>>>(W_up, wbf + (size_t)CH_UP * 16384, 128, 7);
    prep_w<<<144, 256>>>(W_c2, wbf + (size_t)CH_C2 * 16384, 64, 3);
    prep_w<<<288, 256>>>(W_d1, wbf + (size_t)CH_D1 * 16384, 128, 3);
    prep_w<<<144, 256>>>(W_d2, wbf + (size_t)CH_D2 * 16384, 64, 3);
    prep_w<<<144, 256>>>(W_d3, wbf + (size_t)CH_D3 * 16384, 64, 3);

    // 2) up branch: conv7x7 + BN + GELU -> bilinear up x2
    tconv<7,2,1,false><<<dim3(3, 24, 8), 256, SMEM7>>>(
        small_x, nullptr, (const uint4*)(wbf + (size_t)CH_UP * 16384),
        b_up, gup, beup, mup, vup, nullptr, u, h_, w_);
    up2_kernel<<<(R_ELEMS + 255) / 256, 256>>>(u, sm, B_ * 64, h_, 0);

    // 3) uncertainty maps
    diff_kernel<<<(B_ * h_ * w_ + 255) / 256, 256>>>(sm, x, ds);
    up2_kernel<<<(B_ * H_ * W_ + 255) / 256, 256>>>(in_map, ib, B_, h_, 1);
    up2_kernel<<<(B_ * H_ * W_ + 255) / 256, 256>>>(ds, db, B_, h_, 1);
    scale_bf_kernel<<<dim3(6, 24, 8), 256>>>(x, ib, db, bf);

    // 4) conv chain (HMMA, 3xBF16)
    tconv<3,1,0,false><<<dim3(6, 48, 8), 256, SMEM3>>>(
        bf, nullptr, (const uint4*)(wbf + (size_t)CH_C2 * 16384),
        b_c2, nullptr, nullptr, nullptr, nullptr, beta, fn, H_, W_);
    tconv<3,2,1,true><<<dim3(6, 48, 8), 256, SMEM3>>>(
        sm, fn, (const uint4*)(wbf + (size_t)CH_D1 * 16384),
        b_d1, gd1, bed1, md1, vd1, nullptr, r1, H_, W_);
    tconv<3,1,1,false><<<dim3(6, 48, 8), 256, SMEM3>>>(
        r1, nullptr, (const uint4*)(wbf + (size_t)CH_D2 * 16384),
        b_d2, gd2, bed2, md2, vd2, nullptr, r2, H_, W_);
    tconv<3,1,1,false><<<dim3(6, 48, 8), 256, SMEM3>>>(
        r2, nullptr, (const uint4*)(wbf + (size_t)CH_D3 * 16384),
        b_d3, gd3, bed3, md3, vd3, nullptr, (float*)d_out, H_, W_);

    // 5) output head reads r from d_out, writes output_map after it
    conv_out_kernel<<<dim3(6, 24, 8), 256>>>(
        (const float*)d_out, W_out, b_out, (float*)d_out + R_ELEMS);
}

// round 5
// speedup vs baseline: 2.5028x; 1.1104x over previous
#include <cuda_runtime.h>
#include <cuda_bf16.h>
#include <math.h>
#include <stdint.h>

// ---------------- problem constants ----------------
#define B_ 8
#define H_ 192
#define W_ 192
#define h_ 96
#define w_ 96
#define R_ELEMS (B_*64*H_*W_)        // 18,874,368

// weight-chunk table (each chunk = 16KB: 8KB hi + 8KB lo, [n][k] swizzled bf16)
#define CH_UP 0      // 7x7, CG=2 -> 98 chunks
#define CH_C2 98     // 3x3, CG=1 -> 9
#define CH_D1 107    // 3x3, CG=2 -> 18
#define CH_D2 125    // 9
#define CH_D3 134    // 9
#define CH_TOTAL 143

// ---------------- scratch ----------------
__device__ __align__(16) unsigned char g_wbf[CH_TOTAL * 16384];
__device__ float g_u[B_*64*h_*w_];
__device__ float g_small[R_ELEMS];
__device__ float g_diffs[B_*h_*w_];
__device__ float g_inpb[B_*H_*W_];
__device__ float g_diffb[B_*H_*W_];
__device__ float g_bf[R_ELEMS];
__device__ float g_fn[R_ELEMS];
__device__ float g_r1[R_ELEMS];
__device__ float g_r2[R_ELEMS];

// ---------------- helpers ----------------
__device__ __forceinline__ uint32_t smem_u32(const void* p) {
    uint32_t a;
    asm("{ .reg .u64 t; cvta.to.shared.u64 t, %1; cvt.u32.u64 %0, t; }" : "=r"(a) : "l"(p));
    return a;
}
__device__ __forceinline__ void ldm4(uint32_t addr, uint32_t r[4]) {
    asm volatile("ldmatrix.sync.aligned.m8n8.x4.shared.b16 {%0,%1,%2,%3}, [%4];"
                 : "=r"(r[0]), "=r"(r[1]), "=r"(r[2]), "=r"(r[3]) : "r"(addr));
}
__device__ __forceinline__ void mma16816(float c[4], const uint32_t a[4],
                                         uint32_t b0, uint32_t b1) {
    asm volatile(
        "mma.sync.aligned.m16n8k16.row.col.f32.bf16.bf16.f32 "
        "{%0,%1,%2,%3}, {%4,%5,%6,%7}, {%8,%9}, {%0,%1,%2,%3};"
        : "+f"(c[0]), "+f"(c[1]), "+f"(c[2]), "+f"(c[3])
        : "r"(a[0]), "r"(a[1]), "r"(a[2]), "r"(a[3]), "r"(b0), "r"(b1));
}
__device__ __forceinline__ void cpa16(uint32_t saddr, const void* g) {
    asm volatile("cp.async.cg.shared.global [%0], [%1], 16;" :: "r"(saddr), "l"(g) : "memory");
}
#define CPA_COMMIT() asm volatile("cp.async.commit_group;" ::: "memory")
#define CPA_WAIT0()  asm volatile("cp.async.wait_group 0;" ::: "memory")

__device__ __forceinline__ float gelu_exact(float y) {
    return 0.5f * y * (1.0f + erff(y * 0.70710678118654752f));
}
__device__ __forceinline__ uint32_t packbf2(float a, float b) {
    __nv_bfloat16 ha = __float2bfloat16(a), hb = __float2bfloat16(b);
    return (uint32_t)__bfloat16_as_ushort(ha) | ((uint32_t)__bfloat16_as_ushort(hb) << 16);
}

// ---------------- weight prep: OIHW fp32 -> [n][k] swizzled bf16 hi/lo chunks ----------------
__global__ void prep_w(const float* __restrict__ W, unsigned char* __restrict__ dst,
                       int CIN, int KS)
{
    int CG = CIN >> 6;
    int KK = KS * KS;
    int total = KK * CG * 4096;
    for (int idx = blockIdx.x * blockDim.x + threadIdx.x; idx < total;
         idx += gridDim.x * blockDim.x) {
        int chunk = idx >> 12;
        int e = idx & 4095;
        int n = e >> 6, k = e & 63;
        int tap = chunk / CG, cg = chunk - tap * CG;
        float w = W[((size_t)n * CIN + cg * 64 + k) * KK + tap];
        __nv_bfloat16 hb = __float2bfloat16(w);
        __nv_bfloat16 lb = __float2bfloat16(w - __bfloat162float(hb));
        uint32_t off = (uint32_t)n * 128 + ((((k >> 3) ^ (n & 7))) << 4) + (k & 7) * 2;
        unsigned char* base = dst + (size_t)chunk * 16384;
        *(unsigned short*)(base + off)        = __bfloat16_as_ushort(hb);
        *(unsigned short*)(base + 8192 + off) = __bfloat16_as_ushort(lb);
    }
}

// ---------------- HMMA implicit-GEMM conv ----------------
// 128-pixel tile (4y x 32x), 64 out channels. Warp tiling: M=32 x N=32.
// Halo staged once per cg; per-tap B chunks prefetched with cp.async.
// MODE 0: out = beta*(acc+bias)   MODE 1: out = gelu(bn(acc+bias))
template<int KS, int CG, int MODE, bool CONCAT>
__global__ __launch_bounds__(256, 2)
void tconv(const float* __restrict__ inA, const float* __restrict__ inB,
           const uint4* __restrict__ wch, const float* __restrict__ bias,
           const float* __restrict__ gg, const float* __restrict__ bb,
           const float* __restrict__ mm, const float* __restrict__ vv,
           const float* __restrict__ betap, float* __restrict__ out,
           int H, int W)
{
    constexpr int PAD = KS / 2;
    constexpr int IH  = 4 + KS - 1;
    constexpr int IWP = 40;
    constexpr int NPX = IH * IWP;                 // halo pixels
    constexpr int HB  = NPX * 128;                // bytes per halo copy (hi or lo)
    constexpr int KK  = KS * KS;
    constexpr int NCH = KK * CG;
    constexpr int OFF_AH = 1024;
    constexpr int OFF_AL = 1024 + HB;
    constexpr int OFF_B  = 1024 + 2 * HB;

    extern __shared__ char smem_raw[];
    char* smem = (char*)(((uintptr_t)smem_raw + 1023) & ~(uintptr_t)1023);
    uint32_t sb = smem_u32(smem);
    float* epi = (float*)smem;                    // 128 floats at offset 0

    int tid = threadIdx.x, wid = tid >> 5, lane = tid & 31;
    int x0 = blockIdx.x * 32, y0 = blockIdx.y * 4, b = blockIdx.z;
    size_t HW = (size_t)H * W;

    // ---- prefetch first B chunk (overlaps epi + halo staging) ----
    {
        const uint4* srcB = wch;                  // chunk 0 = (cg=0, tap=0)
        uint32_t dstB = sb + OFF_B;               // buf 0
#pragma unroll
        for (int k = 0; k < 4; k++)
            cpa16(dstB + (uint32_t)(tid + k * 256) * 16, srcB + tid + k * 256);
        CPA_COMMIT();
    }

    // epilogue constants
    if (tid < 64) {
        int c = tid;
        float s, t;
        if (MODE == 1) {
            s = gg[c] * rsqrtf(vv[c] + 1e-5f);
            t = (bias[c] - mm[c]) * s + bb[c];
        } else {
            float bt = *betap;
            s = bt; t = bt * bias[c];
        }
        epi[c] = s; epi[64 + c] = t;
    }

    float acc0[4][4], acc1[4][4];
#pragma unroll
    for (int i = 0; i < 4; i++)
#pragma unroll
        for (int j = 0; j < 4; j++) { acc0[i][j] = 0.f; acc1[i][j] = 0.f; }

    // warp tiling: mb = pixel-row block (M=32), nh = n-half (N=32)
    int mb = wid >> 1, nh = wid & 1;
    int ar = lane & 15, akq = lane >> 4;
    int br = lane & 15, bkq = lane >> 4;

    int gctr = 0;
    for (int cg = 0; cg < CG; cg++) {
        __syncthreads();   // protect halo from previous taps' readers

        // ---- stage halo: NPX pixels x 64 chans, fp32 -> bf16 hi/lo ----
        {
            const float* src;
            if (CONCAT) src = (cg ? inB : inA) + (size_t)b * 64 * HW;
            else        src = inA + ((size_t)b * (CG * 64) + cg * 64) * HW;
            constexpr int TOT = NPX * 8;
            for (int item = tid; item < TOT; item += 256) {
                int o  = item / NPX;
                int ph = item - o * NPX;
                int hy = ph / IWP, hx = ph - hy * IWP;
                int gy = y0 + hy - PAD;
                int gx = x0 + hx - 4;
                float v[8];
                if ((unsigned)gy < (unsigned)H && (unsigned)gx < (unsigned)W) {
                    const float* p = src + (size_t)(o * 8) * HW + (size_t)gy * W + gx;
#pragma unroll
                    for (int j = 0; j < 8; j++) v[j] = p[j * HW];
                } else {
#pragma unroll
                    for (int j = 0; j < 8; j++) v[j] = 0.f;
                }
                uint4 hi4, lo4;
                float l[8];
#pragma unroll
                for (int j = 0; j < 8; j++) {
                    __nv_bfloat16 hh = __float2bfloat16(v[j]);
                    l[j] = v[j] - __bfloat162float(hh);
                }
                hi4.x = packbf2(v[0], v[1]); hi4.y = packbf2(v[2], v[3]);
                hi4.z = packbf2(v[4], v[5]); hi4.w = packbf2(v[6], v[7]);
                lo4.x = packbf2(l[0], l[1]); lo4.y = packbf2(l[2], l[3]);
                lo4.z = packbf2(l[4], l[5]); lo4.w = packbf2(l[6], l[7]);
                uint32_t ad = (uint32_t)ph * 128 + (((o ^ (ph & 7))) << 4);
                *(uint4*)(smem + OFF_AH + ad) = hi4;
                *(uint4*)(smem + OFF_AL + ad) = lo4;
            }
        }

        for (int tap = 0; tap < KK; tap++, gctr++) {
            int s = gctr & 1;
            CPA_WAIT0();          // current buf's chunk landed
            __syncthreads();      // halo + B visible; prev tap readers done

            // ---- prefetch next chunk into the other buffer (overlaps compute) ----
            if (gctr + 1 < NCH) {
                int nch = (tap + 1 < KK) ? (tap + 1) * CG + cg : (cg + 1);
                const uint4* srcB = wch + (size_t)nch * 1024;
                uint32_t dstB = sb + OFF_B + (s ^ 1) * 16384;
#pragma unroll
                for (int k = 0; k < 4; k++)
                    cpa16(dstB + (uint32_t)(tid + k * 256) * 16, srcB + tid + k * 256);
                CPA_COMMIT();
            }

            // ---- compute tap ----
            int tapy = tap / KS, tapx = tap - tapy * KS;
            int ph0 = (mb + tapy) * IWP + ar + tapx + (4 - PAD);
            int ph1 = ph0 + 16;
            uint32_t ah0r = sb + OFF_AH + (uint32_t)ph0 * 128;
            uint32_t al0r = sb + OFF_AL + (uint32_t)ph0 * 128;
            uint32_t ah1r = sb + OFF_AH + (uint32_t)ph1 * 128;
            uint32_t al1r = sb + OFF_AL + (uint32_t)ph1 * 128;
            int asw0 = ph0 & 7, asw1 = ph1 & 7;
            uint32_t bbase = sb + OFF_B + s * 16384;

#pragma unroll
            for (int kc = 0; kc < 4; kc++) {
                int q0 = ((kc * 2 + akq) ^ asw0) << 4;
                int q1 = ((kc * 2 + akq) ^ asw1) << 4;
                uint32_t ah0[4], al0[4], ah1[4], al1[4];
                ldm4(ah0r + q0, ah0);
                ldm4(al0r + q0, al0);
                ldm4(ah1r + q1, ah1);
                ldm4(al1r + q1, al1);
#pragma unroll
                for (int g = 0; g < 2; g++) {
                    int n = nh * 32 + g * 16 + br;
                    uint32_t ba = bbase + (uint32_t)n * 128 + ((((kc * 2 + bkq) ^ (n & 7))) << 4);
                    uint32_t bh[4], bl[4];
                    ldm4(ba, bh);
                    ldm4(ba + 8192, bl);
                    mma16816(acc0[2 * g],     ah0, bh[0], bh[2]);
                    mma16816(acc0[2 * g + 1], ah0, bh[1], bh[3]);
                    mma16816(acc1[2 * g],     ah1, bh[0], bh[2]);
                    mma16816(acc1[2 * g + 1], ah1, bh[1], bh[3]);
                    mma16816(acc0[2 * g],     ah0, bl[0], bl[2]);
                    mma16816(acc0[2 * g + 1], ah0, bl[1], bl[3]);
                    mma16816(acc1[2 * g],     ah1, bl[0], bl[2]);
                    mma16816(acc1[2 * g + 1], ah1, bl[1], bl[3]);
                    mma16816(acc0[2 * g],     al0, bh[0], bh[2]);
                    mma16816(acc0[2 * g + 1], al0, bh[1], bh[3]);
                    mma16816(acc1[2 * g],     al1, bh[0], bh[2]);
                    mma16816(acc1[2 * g + 1], al1, bh[1], bh[3]);
                }
            }
        }
    }

    // ---- epilogue: transpose through smem, coalesced NCHW store ----
    __syncthreads();
    float* tb = (float*)(smem + 1024);            // [128][65] fp32 (stride 65: conflict-free)
    {
        int row = lane >> 2, colp = (lane & 3) * 2;
#pragma unroll
        for (int j = 0; j < 4; j++) {
            int c = nh * 32 + j * 8 + colp;
            int p0 = mb * 32 + row;
            tb[p0 * 65 + c]            = acc0[j][0];
            tb[p0 * 65 + c + 1]        = acc0[j][1];
            tb[(p0 + 8) * 65 + c]      = acc0[j][2];
            tb[(p0 + 8) * 65 + c + 1]  = acc0[j][3];
            int p1 = p0 + 16;
            tb[p1 * 65 + c]            = acc1[j][0];
            tb[p1 * 65 + c + 1]        = acc1[j][1];
            tb[(p1 + 8) * 65 + c]      = acc1[j][2];
            tb[(p1 + 8) * 65 + c + 1]  = acc1[j][3];
        }
    }
    __syncthreads();
#pragma unroll 4
    for (int it = 0; it < 32; it++) {
        int item = it * 8 + wid;
        int c = item >> 2, py = item & 3;
        float v = tb[(py * 32 + lane) * 65 + c] * epi[c] + epi[64 + c];
        if (MODE == 1) v = gelu_exact(v);
        out[((size_t)(b * 64 + c) * H + (y0 + py)) * W + x0 + lane] = v;
    }
}

// ---------------- bilinear up x2, align_corners=True, optional sigmoid ----------------
__global__ void up2_kernel(const float* __restrict__ in, float* __restrict__ out,
                           int BC, int n, int do_sigmoid)
{
    int N = 2 * n;
    size_t total = (size_t)BC * N * N;
    size_t idx = (size_t)blockIdx.x * blockDim.x + threadIdx.x;
    if (idx >= total) return;
    int xo = (int)(idx % N);
    size_t r = idx / N;
    int yo = (int)(r % N);
    int bc = (int)(r / N);
    float rr = (float)(n - 1) / (float)(N - 1);
    float sy = yo * rr; int iy0 = (int)sy; float wy = sy - (float)iy0; int iy1 = min(iy0 + 1, n - 1);
    float sx = xo * rr; int ix0 = (int)sx; float wx = sx - (float)ix0; int ix1 = min(ix0 + 1, n - 1);
    const float* p = in + (size_t)bc * n * n;
    float a = p[iy0 * n + ix0], bv = p[iy1 * n + ix0];
    float c = p[iy0 * n + ix1], d = p[iy1 * n + ix1];
    float ra = a * (1.f - wy) + bv * wy;
    float rb = c * (1.f - wy) + d * wy;
    float v  = ra * (1.f - wx) + rb * wx;
    if (do_sigmoid) v = 1.f / (1.f + expf(-v));
    out[idx] = v;
}

// ---------------- AP_MP(small,x) + AP_MP(x,small) at half resolution ----------------
__global__ void diff_kernel(const float* __restrict__ sm, const float* __restrict__ x,
                            float* __restrict__ out)
{
    int idx = blockIdx.x * blockDim.x + threadIdx.x;
    if (idx >= B_ * h_ * w_) return;
    int j = idx % w_;
    int t = idx / w_;
    int i = t % h_;
    int b = t / h_;
    float acc1 = 0.f, acc2 = 0.f;
    size_t base0 = ((size_t)b * 64 * H_ + 2 * i) * W_ + 2 * j;
    for (int c = 0; c < 64; c++) {
        size_t base = base0 + (size_t)c * H_ * W_;
        float2 s0 = *(const float2*)(sm + base);
        float2 s1 = *(const float2*)(sm + base + W_);
        float2 xa = *(const float2*)(x + base);
        float2 xb = *(const float2*)(x + base + W_);
        float as = 0.25f * (s0.x + s0.y + s1.x + s1.y);
        float ms = fmaxf(fmaxf(s0.x, s0.y), fmaxf(s1.x, s1.y));
        float ax = 0.25f * (xa.x + xa.y + xb.x + xb.y);
        float mx = fmaxf(fmaxf(xa.x, xa.y), fmaxf(xb.x, xb.y));
        float d1 = as - mx; acc1 += d1 * d1;
        float d2 = ax - ms; acc2 += d2 * d2;
    }
    out[idx] = sqrtf(acc1) + sqrtf(acc2);
}

// ---------------- b_feature = x * (dilate3(inp)-inp + dilate3(dif)-dif + 1) ----------------
__global__ __launch_bounds__(256)
void scale_bf_kernel(const float* __restrict__ x, const float* __restrict__ inp,
                     const float* __restrict__ dif, float* __restrict__ bf)
{
    int tx = threadIdx.x & 31, ty = threadIdx.x >> 5;
    int gx = blockIdx.x * 32 + tx;
    int gy = blockIdx.y * 8 + ty;
    int b  = blockIdx.z;
    const float* ip = inp + (size_t)b * H_ * W_;
    const float* dp = dif + (size_t)b * H_ * W_;
    float mi = -INFINITY, md = -INFINITY;
    for (int dy = -1; dy <= 1; dy++) {
        int yy = gy + dy; if ((unsigned)yy >= (unsigned)H_) continue;
        for (int dx = -1; dx <= 1; dx++) {
            int xx = gx + dx; if ((unsigned)xx >= (unsigned)W_) continue;
            mi = fmaxf(mi, ip[yy * W_ + xx]);
            md = fmaxf(md, dp[yy * W_ + xx]);
        }
    }
    float s = (mi - ip[gy * W_ + gx]) + (md - dp[gy * W_ + gx]) + 1.0f;
    size_t base = ((size_t)b * 64 * H_ + gy) * W_ + gx;
    for (int c = 0; c < 64; c++) {
        size_t o = base + (size_t)c * H_ * W_;
        bf[o] = x[o] * s;
    }
}

// ---------------- final conv 7x7, 64 -> 1 (fp32) ----------------
__global__ __launch_bounds__(256)
void conv_out_kernel(const float* __restrict__ rin, const float* __restrict__ Wo,
                     const float* __restrict__ bo, float* __restrict__ out)
{
    __shared__ float s_in[8 * 14 * 38];
    __shared__ float s_w[8 * 49];
    int tid = threadIdx.x, tx = tid & 31, ty = tid >> 5;
    int x0 = blockIdx.x * 32, ys = blockIdx.y * 8, b = blockIdx.z;
    float acc = 0.f;
    for (int c0 = 0; c0 < 64; c0 += 8) {
        for (int idx = tid; idx < 8 * 14 * 38; idx += 256) {
            int c = idx / (14 * 38);
            int r = idx - c * (14 * 38);
            int ly = r / 38, lx = r - ly * 38;
            int gy = ys + ly - 3, gx = x0 + lx - 3;
            float v = 0.f;
            if ((unsigned)gy < (unsigned)H_ && (unsigned)gx < (unsigned)W_)
                v = rin[((size_t)(b * 64 + c0 + c) * H_ + gy) * W_ + gx];
            s_in[idx] = v;
        }
        for (int idx = tid; idx < 8 * 49; idx += 256)
            s_w[idx] = Wo[(c0 + idx / 49) * 49 + idx % 49];
        __syncthreads();
#pragma unroll
        for (int c = 0; c < 8; c++)
            for (int ky = 0; ky < 7; ky++)
#pragma unroll
                for (int kx = 0; kx < 7; kx++)
                    acc += s_w[c * 49 + ky * 7 + kx] * s_in[(c * 14 + ty + ky) * 38 + tx + kx];
        __syncthreads();
    }
    out[((size_t)b * H_ + (ys + ty)) * W_ + x0 + tx] = acc + bo[0];
}

// ---------------- launch ----------------
#define SMEM3 (1024 + 2*(6*40*128)  + 32768 + 1024)   // 96256
#define SMEM7 (1024 + 2*(10*40*128) + 32768 + 1024)   // 137216

extern "C" void kernel_launch(void* const* d_in, const int* in_sizes, int n_in,
                              void* d_out, int out_size)
{
    const float* x       = (const float*)d_in[0];
    const float* small_x = (const float*)d_in[1];
    const float* in_map  = (const float*)d_in[2];
    const float* W_up  = (const float*)d_in[3];
    const float* b_up  = (const float*)d_in[4];
    const float* gup   = (const float*)d_in[5];
    const float* beup  = (const float*)d_in[6];
    const float* mup   = (const float*)d_in[7];
    const float* vup   = (const float*)d_in[8];
    const float* W_c2  = (const float*)d_in[9];
    const float* b_c2  = (const float*)d_in[10];
    const float* W_d1  = (const float*)d_in[11];
    const float* b_d1  = (const float*)d_in[12];
    const float* gd1   = (const float*)d_in[13];
    const float* bed1  = (const float*)d_in[14];
    const float* md1   = (const float*)d_in[15];
    const float* vd1   = (const float*)d_in[16];
    const float* W_d2  = (const float*)d_in[17];
    const float* b_d2  = (const float*)d_in[18];
    const float* gd2   = (const float*)d_in[19];
    const float* bed2  = (const float*)d_in[20];
    const float* md2   = (const float*)d_in[21];
    const float* vd2   = (const float*)d_in[22];
    const float* W_d3  = (const float*)d_in[23];
    const float* b_d3  = (const float*)d_in[24];
    const float* gd3   = (const float*)d_in[25];
    const float* bed3  = (const float*)d_in[26];
    const float* md3   = (const float*)d_in[27];
    const float* vd3   = (const float*)d_in[28];
    const float* W_out = (const float*)d_in[29];
    const float* b_out = (const float*)d_in[30];
    const float* beta  = (const float*)d_in[31];

    float *u, *sm, *ds, *ib, *db, *bf, *fn, *r1, *r2;
    unsigned char* wbf;
    cudaGetSymbolAddress((void**)&u,   g_u);
    cudaGetSymbolAddress((void**)&sm,  g_small);
    cudaGetSymbolAddress((void**)&ds,  g_diffs);
    cudaGetSymbolAddress((void**)&ib,  g_inpb);
    cudaGetSymbolAddress((void**)&db,  g_diffb);
    cudaGetSymbolAddress((void**)&bf,  g_bf);
    cudaGetSymbolAddress((void**)&fn,  g_fn);
    cudaGetSymbolAddress((void**)&r1,  g_r1);
    cudaGetSymbolAddress((void**)&r2,  g_r2);
    cudaGetSymbolAddress((void**)&wbf, g_wbf);

    cudaFuncSetAttribute(tconv<7,2,1,false>, cudaFuncAttributeMaxDynamicSharedMemorySize, SMEM7);
    cudaFuncSetAttribute(tconv<3,1,0,false>, cudaFuncAttributeMaxDynamicSharedMemorySize, SMEM3);
    cudaFuncSetAttribute(tconv<3,2,1,true>,  cudaFuncAttributeMaxDynamicSharedMemorySize, SMEM3);
    cudaFuncSetAttribute(tconv<3,1,1,false>, cudaFuncAttributeMaxDynamicSharedMemorySize, SMEM3);

    // 1) weight prep
    prep_w<<<392, 256>>>(W_up, wbf + (size_t)CH_UP * 16384, 128, 7);
    prep_w<<<144, 256>>>(W_c2, wbf + (size_t)CH_C2 * 16384, 64, 3);
    prep_w<<<288, 256>>>(W_d1, wbf + (size_t)CH_D1 * 16384, 128, 3);
    prep_w<<<144, 256>>>(W_d2, wbf + (size_t)CH_D2 * 16384, 64, 3);
    prep_w<<<144, 256>>>(W_d3, wbf + (size_t)CH_D3 * 16384, 64, 3);

    // 2) up branch: conv7x7 + BN + GELU -> bilinear up x2
    tconv<7,2,1,false><<<dim3(3, 24, 8), 256, SMEM7>>>(
        small_x, nullptr, (const uint4*)(wbf + (size_t)CH_UP * 16384),
        b_up, gup, beup, mup, vup, nullptr, u, h_, w_);
    up2_kernel<<<(R_ELEMS + 255) / 256, 256>>>(u, sm, B_ * 64, h_, 0);

    // 3) uncertainty maps
    diff_kernel<<<(B_ * h_ * w_ + 255) / 256, 256>>>(sm, x, ds);
    up2_kernel<<<(B_ * H_ * W_ + 255) / 256, 256>>>(in_map, ib, B_, h_, 1);
    up2_kernel<<<(B_ * H_ * W_ + 255) / 256, 256>>>(ds, db, B_, h_, 1);
    scale_bf_kernel<<<dim3(6, 24, 8), 256>>>(x, ib, db, bf);

    // 4) conv chain (HMMA, 3xBF16)
    tconv<3,1,0,false><<<dim3(6, 48, 8), 256, SMEM3>>>(
        bf, nullptr, (const uint4*)(wbf + (size_t)CH_C2 * 16384),
        b_c2, nullptr, nullptr, nullptr, nullptr, beta, fn, H_, W_);
    tconv<3,2,1,true><<<dim3(6, 48, 8), 256, SMEM3>>>(
        sm, fn, (const uint4*)(wbf + (size_t)CH_D1 * 16384),
        b_d1, gd1, bed1, md1, vd1, nullptr, r1, H_, W_);
    tconv<3,1,1,false><<<dim3(6, 48, 8), 256, SMEM3>>>(
        r1, nullptr, (const uint4*)(wbf + (size_t)CH_D2 * 16384),
        b_d2, gd2, bed2, md2, vd2, nullptr, r2, H_, W_);
    tconv<3,1,1,false><<<dim3(6, 48, 8), 256, SMEM3>>>(
        r2, nullptr, (const uint4*)(wbf + (size_t)CH_D3 * 16384),
        b_d3, gd3, bed3, md3, vd3, nullptr, (float*)d_out, H_, W_);

    // 5) output head reads r from d_out, writes output_map after it
    conv_out_kernel<<<dim3(6, 24, 8), 256>>>(
        (const float*)d_out, W_out, b_out, (float*)d_out + R_ELEMS);
}

// round 6
// speedup vs baseline: 3.3336x; 1.3319x over previous
#include <cuda_runtime.h>
#include <cuda_fp16.h>
#include <math.h>
#include <stdint.h>

// ---------------- problem constants ----------------
#define B_ 8
#define H_ 192
#define W_ 192
#define h_ 96
#define w_ 96
#define R_ELEMS (B_*64*H_*W_)        // 18,874,368

// weight-chunk table (each chunk = 16KB: 8KB hi + 8KB lo, [n][k] swizzled fp16)
#define CH_UP 0      // 7x7, CG=2 -> 98 chunks
#define CH_C2 98     // 3x3, CG=1 -> 9
#define CH_D1 107    // 3x3, CG=2 -> 18
#define CH_D2 125    // 9
#define CH_D3 134    // 9
#define CH_TOTAL 143

// ---------------- scratch ----------------
__device__ __align__(16) unsigned char g_wbf[CH_TOTAL * 16384];
__device__ float g_u[B_*64*h_*w_];
__device__ float g_small[R_ELEMS];
__device__ float g_diffs[B_*h_*w_];
__device__ float g_bf[R_ELEMS];
__device__ float g_fn[R_ELEMS];
__device__ float g_r1[R_ELEMS];
__device__ float g_r2[R_ELEMS];

// ---------------- helpers ----------------
__device__ __forceinline__ uint32_t smem_u32(const void* p) {
    uint32_t a;
    asm("{ .reg .u64 t; cvta.to.shared.u64 t, %1; cvt.u32.u64 %0, t; }" : "=r"(a) : "l"(p));
    return a;
}
__device__ __forceinline__ void ldm4(uint32_t addr, uint32_t r[4]) {
    asm volatile("ldmatrix.sync.aligned.m8n8.x4.shared.b16 {%0,%1,%2,%3}, [%4];"
                 : "=r"(r[0]), "=r"(r[1]), "=r"(r[2]), "=r"(r[3]) : "r"(addr));
}
__device__ __forceinline__ void mma16816(float c[4], const uint32_t a[4],
                                         uint32_t b0, uint32_t b1) {
    asm volatile(
        "mma.sync.aligned.m16n8k16.row.col.f32.f16.f16.f32 "
        "{%0,%1,%2,%3}, {%4,%5,%6,%7}, {%8,%9}, {%0,%1,%2,%3};"
        : "+f"(c[0]), "+f"(c[1]), "+f"(c[2]), "+f"(c[3])
        : "r"(a[0]), "r"(a[1]), "r"(a[2]), "r"(a[3]), "r"(b0), "r"(b1));
}
__device__ __forceinline__ void cpa16(uint32_t saddr, const void* g) {
    asm volatile("cp.async.cg.shared.global [%0], [%1], 16;" :: "r"(saddr), "l"(g) : "memory");
}
#define CPA_COMMIT() asm volatile("cp.async.commit_group;" ::: "memory")
#define CPA_WAIT0()  asm volatile("cp.async.wait_group 0;" ::: "memory")

__device__ __forceinline__ float gelu_exact(float y) {
    return 0.5f * y * (1.0f + erff(y * 0.70710678118654752f));
}
__device__ __forceinline__ uint32_t packh2(float a, float b) {
    __half2 h = __floats2half2_rn(a, b);
    return *(uint32_t*)&h;
}

// ---------------- fused weight prep: all 5 conv weight sets ----------------
// OIHW fp32 -> per-chunk [n][k] swizzled fp16 hi/lo (hi at +0, lo at +8192)
__global__ void prep_all(const float* __restrict__ W_up, const float* __restrict__ W_c2,
                         const float* __restrict__ W_d1, const float* __restrict__ W_d2,
                         const float* __restrict__ W_d3, unsigned char* __restrict__ dst)
{
    int total = CH_TOTAL * 4096;
    for (int idx = blockIdx.x * blockDim.x + threadIdx.x; idx < total;
         idx += gridDim.x * blockDim.x) {
        int chunk = idx >> 12;
        int e = idx & 4095;
        int n = e >> 6, k = e & 63;
        const float* W; int CIN, KK, local;
        if (chunk < 98)       { W = W_up; CIN = 128; KK = 49; local = chunk; }
        else if (chunk < 107) { W = W_c2; CIN = 64;  KK = 9;  local = chunk - 98; }
        else if (chunk < 125) { W = W_d1; CIN = 128; KK = 9;  local = chunk - 107; }
        else if (chunk < 134) { W = W_d2; CIN = 64;  KK = 9;  local = chunk - 125; }
        else                  { W = W_d3; CIN = 64;  KK = 9;  local = chunk - 134; }
        int CG = CIN >> 6;
        int tap = local / CG, cg = local - tap * CG;
        float w = W[((size_t)n * CIN + cg * 64 + k) * KK + tap];
        __half hb = __float2half_rn(w);
        __half lb = __float2half_rn(w - __half2float(hb));
        uint32_t off = (uint32_t)n * 128 + ((((k >> 3) ^ (n & 7))) << 4) + (k & 7) * 2;
        unsigned char* base = dst + (size_t)chunk * 16384;
        *(unsigned short*)(base + off)        = __half_as_ushort(hb);
        *(unsigned short*)(base + 8192 + off) = __half_as_ushort(lb);
    }
}

// ---------------- HMMA implicit-GEMM conv (fp16 2-term) ----------------
// 128-pixel tile (4y x 32x), 64 out chans. Warp tile M=32 x N=32.
// A = fp16(x) (single copy). B = fp16 hi + fp16 lo (weights exact).
// acc = A*Bh + A*Bl. MODE 0: beta*(acc+bias)  MODE 1: gelu(bn(acc+bias))
template<int KS, int CG, int MODE, bool CONCAT>
__global__ __launch_bounds__(256, 2)
void tconv(const float* __restrict__ inA, const float* __restrict__ inB,
           const uint4* __restrict__ wch, const float* __restrict__ bias,
           const float* __restrict__ gg, const float* __restrict__ bb,
           const float* __restrict__ mm, const float* __restrict__ vv,
           const float* __restrict__ betap, float* __restrict__ out,
           int H, int W)
{
    constexpr int PAD = KS / 2;
    constexpr int IH  = 4 + KS - 1;
    constexpr int IWP = 40;
    constexpr int NPX = IH * IWP;
    constexpr int HB  = NPX * 128;                // halo bytes (fp16 hi only)
    constexpr int KK  = KS * KS;
    constexpr int NCH = KK * CG;
    constexpr int OFF_A = 1024;
    constexpr int OFF_B = 1024 + HB;

    extern __shared__ char smem_raw[];
    char* smem = (char*)(((uintptr_t)smem_raw + 1023) & ~(uintptr_t)1023);
    uint32_t sb = smem_u32(smem);
    float* epi = (float*)smem;

    int tid = threadIdx.x, wid = tid >> 5, lane = tid & 31;
    int x0 = blockIdx.x * 32, y0 = blockIdx.y * 4, b = blockIdx.z;
    size_t HW = (size_t)H * W;

    // prefetch first B chunk
    {
        const uint4* srcB = wch;
        uint32_t dstB = sb + OFF_B;
#pragma unroll
        for (int k = 0; k < 4; k++)
            cpa16(dstB + (uint32_t)(tid + k * 256) * 16, srcB + tid + k * 256);
        CPA_COMMIT();
    }

    if (tid < 64) {
        int c = tid;
        float s, t;
        if (MODE == 1) {
            s = gg[c] * rsqrtf(vv[c] + 1e-5f);
            t = (bias[c] - mm[c]) * s + bb[c];
        } else {
            float bt = *betap;
            s = bt; t = bt * bias[c];
        }
        epi[c] = s; epi[64 + c] = t;
    }

    float acc0[4][4], acc1[4][4];
#pragma unroll
    for (int i = 0; i < 4; i++)
#pragma unroll
        for (int j = 0; j < 4; j++) { acc0[i][j] = 0.f; acc1[i][j] = 0.f; }

    int mb = wid >> 1, nh = wid & 1;
    int ar = lane & 15, akq = lane >> 4;
    int br = lane & 15, bkq = lane >> 4;

    int gctr = 0;
    for (int cg = 0; cg < CG; cg++) {
        __syncthreads();

        // ---- stage halo: fp16 hi only ----
        {
            const float* src;
            if (CONCAT) src = (cg ? inB : inA) + (size_t)b * 64 * HW;
            else        src = inA + ((size_t)b * (CG * 64) + cg * 64) * HW;
            constexpr int TOT = NPX * 8;
            for (int item = tid; item < TOT; item += 256) {
                int o  = item / NPX;
                int ph = item - o * NPX;
                int hy = ph / IWP, hx = ph - hy * IWP;
                int gy = y0 + hy - PAD;
                int gx = x0 + hx - 4;
                float v[8];
                if ((unsigned)gy < (unsigned)H && (unsigned)gx < (unsigned)W) {
                    const float* p = src + (size_t)(o * 8) * HW + (size_t)gy * W + gx;
#pragma unroll
                    for (int j = 0; j < 8; j++) v[j] = p[j * HW];
                } else {
#pragma unroll
                    for (int j = 0; j < 8; j++) v[j] = 0.f;
                }
                uint4 hi4;
                hi4.x = packh2(v[0], v[1]); hi4.y = packh2(v[2], v[3]);
                hi4.z = packh2(v[4], v[5]); hi4.w = packh2(v[6], v[7]);
                uint32_t ad = (uint32_t)ph * 128 + (((o ^ (ph & 7))) << 4);
                *(uint4*)(smem + OFF_A + ad) = hi4;
            }
        }

        for (int tap = 0; tap < KK; tap++, gctr++) {
            int s = gctr & 1;
            CPA_WAIT0();
            __syncthreads();

            if (gctr + 1 < NCH) {
                int nch = (tap + 1 < KK) ? (tap + 1) * CG + cg : (cg + 1);
                const uint4* srcB = wch + (size_t)nch * 1024;
                uint32_t dstB = sb + OFF_B + (s ^ 1) * 16384;
#pragma unroll
                for (int k = 0; k < 4; k++)
                    cpa16(dstB + (uint32_t)(tid + k * 256) * 16, srcB + tid + k * 256);
                CPA_COMMIT();
            }

            int tapy = tap / KS, tapx = tap - tapy * KS;
            int ph0 = (mb + tapy) * IWP + ar + tapx + (4 - PAD);
            int ph1 = ph0 + 16;
            uint32_t a0r = sb + OFF_A + (uint32_t)ph0 * 128;
            uint32_t a1r = sb + OFF_A + (uint32_t)ph1 * 128;
            int asw0 = ph0 & 7, asw1 = ph1 & 7;
            uint32_t bbase = sb + OFF_B + s * 16384;

#pragma unroll
            for (int kc = 0; kc < 4; kc++) {
                int q0 = ((kc * 2 + akq) ^ asw0) << 4;
                int q1 = ((kc * 2 + akq) ^ asw1) << 4;
                uint32_t a0[4], a1[4];
                ldm4(a0r + q0, a0);
                ldm4(a1r + q1, a1);
#pragma unroll
                for (int g = 0; g < 2; g++) {
                    int n = nh * 32 + g * 16 + br;
                    uint32_t ba = bbase + (uint32_t)n * 128 + ((((kc * 2 + bkq) ^ (n & 7))) << 4);
                    uint32_t bh[4], bl[4];
                    ldm4(ba, bh);
                    ldm4(ba + 8192, bl);
                    mma16816(acc0[2 * g],     a0, bh[0], bh[2]);
                    mma16816(acc0[2 * g + 1], a0, bh[1], bh[3]);
                    mma16816(acc1[2 * g],     a1, bh[0], bh[2]);
                    mma16816(acc1[2 * g + 1], a1, bh[1], bh[3]);
                    mma16816(acc0[2 * g],     a0, bl[0], bl[2]);
                    mma16816(acc0[2 * g + 1], a0, bl[1], bl[3]);
                    mma16816(acc1[2 * g],     a1, bl[0], bl[2]);
                    mma16816(acc1[2 * g + 1], a1, bl[1], bl[3]);
                }
            }
        }
    }

    // ---- epilogue: transpose through smem, coalesced NCHW store ----
    __syncthreads();
    float* tb = (float*)(smem + 1024);            // [128][65] fp32, conflict-free
    {
        int row = lane >> 2, colp = (lane & 3) * 2;
#pragma unroll
        for (int j = 0; j < 4; j++) {
            int c = nh * 32 + j * 8 + colp;
            int p0 = mb * 32 + row;
            tb[p0 * 65 + c]            = acc0[j][0];
            tb[p0 * 65 + c + 1]        = acc0[j][1];
            tb[(p0 + 8) * 65 + c]      = acc0[j][2];
            tb[(p0 + 8) * 65 + c + 1]  = acc0[j][3];
            int p1 = p0 + 16;
            tb[p1 * 65 + c]            = acc1[j][0];
            tb[p1 * 65 + c + 1]        = acc1[j][1];
            tb[(p1 + 8) * 65 + c]      = acc1[j][2];
            tb[(p1 + 8) * 65 + c + 1]  = acc1[j][3];
        }
    }
    __syncthreads();
#pragma unroll 4
    for (int it = 0; it < 32; it++) {
        int item = it * 8 + wid;
        int c = item >> 2, py = item & 3;
        float v = tb[(py * 32 + lane) * 65 + c] * epi[c] + epi[64 + c];
        if (MODE == 1) v = gelu_exact(v);
        out[((size_t)(b * 64 + c) * H + (y0 + py)) * W + x0 + lane] = v;
    }
}

// ---------------- bilinear up x2 (align_corners=True), no sigmoid ----------------
__global__ void up2_kernel(const float* __restrict__ in, float* __restrict__ out,
                           int BC, int n)
{
    int N = 2 * n;
    size_t total = (size_t)BC * N * N;
    size_t idx = (size_t)blockIdx.x * blockDim.x + threadIdx.x;
    if (idx >= total) return;
    int xo = (int)(idx % N);
    size_t r = idx / N;
    int yo = (int)(r % N);
    int bc = (int)(r / N);
    float rr = (float)(n - 1) / (float)(N - 1);
    float sy = yo * rr; int iy0 = (int)sy; float wy = sy - (float)iy0; int iy1 = min(iy0 + 1, n - 1);
    float sx = xo * rr; int ix0 = (int)sx; float wx = sx - (float)ix0; int ix1 = min(ix0 + 1, n - 1);
    const float* p = in + (size_t)bc * n * n;
    float a = p[iy0 * n + ix0], bv = p[iy1 * n + ix0];
    float c = p[iy0 * n + ix1], d = p[iy1 * n + ix1];
    float ra = a * (1.f - wy) + bv * wy;
    float rb = c * (1.f - wy) + d * wy;
    out[idx] = ra * (1.f - wx) + rb * wx;
}

// ---------------- AP_MP(small,x) + AP_MP(x,small) at half resolution ----------------
__global__ void diff_kernel(const float* __restrict__ sm, const float* __restrict__ x,
                            float* __restrict__ out)
{
    int idx = blockIdx.x * blockDim.x + threadIdx.x;
    if (idx >= B_ * h_ * w_) return;
    int j = idx % w_;
    int t = idx / w_;
    int i = t % h_;
    int b = t / h_;
    float acc1 = 0.f, acc2 = 0.f;
    size_t base0 = ((size_t)b * 64 * H_ + 2 * i) * W_ + 2 * j;
    for (int c = 0; c < 64; c++) {
        size_t base = base0 + (size_t)c * H_ * W_;
        float2 s0 = *(const float2*)(sm + base);
        float2 s1 = *(const float2*)(sm + base + W_);
        float2 xa = *(const float2*)(x + base);
        float2 xb = *(const float2*)(x + base + W_);
        float as = 0.25f * (s0.x + s0.y + s1.x + s1.y);
        float ms = fmaxf(fmaxf(s0.x, s0.y), fmaxf(s1.x, s1.y));
        float ax = 0.25f * (xa.x + xa.y + xb.x + xb.y);
        float mx = fmaxf(fmaxf(xa.x, xa.y), fmaxf(xb.x, xb.y));
        float d1 = as - mx; acc1 += d1 * d1;
        float d2 = ax - ms; acc2 += d2 * d2;
    }
    out[idx] = sqrtf(acc1) + sqrtf(acc2);
}

// ---------------- fused: sigmoid(up2(map)) x2 -> dilate3 - map -> scale x -> bf ----------------
__global__ __launch_bounds__(256)
void fused_bf(const float* __restrict__ x, const float* __restrict__ in_map,
              const float* __restrict__ ds, float* __restrict__ bf)
{
    __shared__ float s_i[10 * 34];
    __shared__ float s_d[10 * 34];
    int tid = threadIdx.x;
    int x0 = blockIdx.x * 32, y0 = blockIdx.y * 8, b = blockIdx.z;
    const float rr = 95.f / 191.f;
    const float* pi = in_map + (size_t)b * h_ * w_;
    const float* pd = ds + (size_t)b * h_ * w_;

    for (int item = tid; item < 340; item += 256) {
        int hy = item / 34, hx = item - hy * 34;
        int gy = y0 - 1 + hy, gx = x0 - 1 + hx;
        float vi = -INFINITY, vd = -INFINITY;
        if ((unsigned)gy < (unsigned)H_ && (unsigned)gx < (unsigned)W_) {
            float sy = gy * rr; int iy0 = (int)sy; float wy = sy - (float)iy0;
            int iy1 = min(iy0 + 1, h_ - 1);
            float sx = gx * rr; int ix0 = (int)sx; float wx = sx - (float)ix0;
            int ix1 = min(ix0 + 1, w_ - 1);
            float w00 = (1.f - wy) * (1.f - wx), w01 = (1.f - wy) * wx;
            float w10 = wy * (1.f - wx),         w11 = wy * wx;
            float ui = pi[iy0 * w_ + ix0] * w00 + pi[iy0 * w_ + ix1] * w01
                     + pi[iy1 * w_ + ix0] * w10 + pi[iy1 * w_ + ix1] * w11;
            float ud = pd[iy0 * w_ + ix0] * w00 + pd[iy0 * w_ + ix1] * w01
                     + pd[iy1 * w_ + ix0] * w10 + pd[iy1 * w_ + ix1] * w11;
            vi = 1.f / (1.f + expf(-ui));
            vd = 1.f / (1.f + expf(-ud));
        }
        s_i[item] = vi; s_d[item] = vd;
    }
    __syncthreads();

    int tx = tid & 31, ty = tid >> 5;
    int ci = (ty + 1) * 34 + tx + 1;
    float mi = -INFINITY, md = -INFINITY;
#pragma unroll
    for (int dy = 0; dy < 3; dy++)
#pragma unroll
        for (int dx = 0; dx < 3; dx++) {
            int o = (ty + dy) * 34 + tx + dx;
            mi = fmaxf(mi, s_i[o]);
            md = fmaxf(md, s_d[o]);
        }
    float s = (mi - s_i[ci]) + (md - s_d[ci]) + 1.0f;
    size_t base = ((size_t)(b * 64) * H_ + (y0 + ty)) * W_ + x0 + tx;
    for (int c = 0; c < 64; c++) {
        size_t o = base + (size_t)c * H_ * W_;
        bf[o] = x[o] * s;
    }
}

// ---------------- final conv 7x7, 64 -> 1 (fp32) ----------------
__global__ __launch_bounds__(256)
void conv_out_kernel(const float* __restrict__ rin, const float* __restrict__ Wo,
                     const float* __restrict__ bo, float* __restrict__ out)
{
    __shared__ float s_in[8 * 14 * 38];
    __shared__ float s_w[8 * 49];
    int tid = threadIdx.x, tx = tid & 31, ty = tid >> 5;
    int x0 = blockIdx.x * 32, ys = blockIdx.y * 8, b = blockIdx.z;
    float acc = 0.f;
    for (int c0 = 0; c0 < 64; c0 += 8) {
        for (int idx = tid; idx < 8 * 14 * 38; idx += 256) {
            int c = idx / (14 * 38);
            int r = idx - c * (14 * 38);
            int ly = r / 38, lx = r - ly * 38;
            int gy = ys + ly - 3, gx = x0 + lx - 3;
            float v = 0.f;
            if ((unsigned)gy < (unsigned)H_ && (unsigned)gx < (unsigned)W_)
                v = rin[((size_t)(b * 64 + c0 + c) * H_ + gy) * W_ + gx];
            s_in[idx] = v;
        }
        for (int idx = tid; idx < 8 * 49; idx += 256)
            s_w[idx] = Wo[(c0 + idx / 49) * 49 + idx % 49];
        __syncthreads();
#pragma unroll
        for (int c = 0; c < 8; c++)
            for (int ky = 0; ky < 7; ky++)
#pragma unroll
                for (int kx = 0; kx < 7; kx++)
                    acc += s_w[c * 49 + ky * 7 + kx] * s_in[(c * 14 + ty + ky) * 38 + tx + kx];
        __syncthreads();
    }
    out[((size_t)b * H_ + (ys + ty)) * W_ + x0 + tx] = acc + bo[0];
}

// ---------------- launch ----------------
#define SMEM3 (1024 + 6*40*128  + 2*16384)   // 64512
#define SMEM7 (1024 + 10*40*128 + 2*16384)   // 84992

extern "C" void kernel_launch(void* const* d_in, const int* in_sizes, int n_in,
                              void* d_out, int out_size)
{
    const float* x       = (const float*)d_in[0];
    const float* small_x = (const float*)d_in[1];
    const float* in_map  = (const float*)d_in[2];
    const float* W_up  = (const float*)d_in[3];
    const float* b_up  = (const float*)d_in[4];
    const float* gup   = (const float*)d_in[5];
    const float* beup  = (const float*)d_in[6];
    const float* mup   = (const float*)d_in[7];
    const float* vup   = (const float*)d_in[8];
    const float* W_c2  = (const float*)d_in[9];
    const float* b_c2  = (const float*)d_in[10];
    const float* W_d1  = (const float*)d_in[11];
    const float* b_d1  = (const float*)d_in[12];
    const float* gd1   = (const float*)d_in[13];
    const float* bed1  = (const float*)d_in[14];
    const float* md1   = (const float*)d_in[15];
    const float* vd1   = (const float*)d_in[16];
    const float* W_d2  = (const float*)d_in[17];
    const float* b_d2  = (const float*)d_in[18];
    const float* gd2   = (const float*)d_in[19];
    const float* bed2  = (const float*)d_in[20];
    const float* md2   = (const float*)d_in[21];
    const float* vd2   = (const float*)d_in[22];
    const float* W_d3  = (const float*)d_in[23];
    const float* b_d3  = (const float*)d_in[24];
    const float* gd3   = (const float*)d_in[25];
    const float* bed3  = (const float*)d_in[26];
    const float* md3   = (const float*)d_in[27];
    const float* vd3   = (const float*)d_in[28];
    const float* W_out = (const float*)d_in[29];
    const float* b_out = (const float*)d_in[30];
    const float* beta  = (const float*)d_in[31];

    float *u, *sm, *ds, *bf, *fn, *r1, *r2;
    unsigned char* wbf;
    cudaGetSymbolAddress((void**)&u,   g_u);
    cudaGetSymbolAddress((void**)&sm,  g_small);
    cudaGetSymbolAddress((void**)&ds,  g_diffs);
    cudaGetSymbolAddress((void**)&bf,  g_bf);
    cudaGetSymbolAddress((void**)&fn,  g_fn);
    cudaGetSymbolAddress((void**)&r1,  g_r1);
    cudaGetSymbolAddress((void**)&r2,  g_r2);
    cudaGetSymbolAddress((void**)&wbf, g_wbf);

    cudaFuncSetAttribute(tconv<7,2,1,false>, cudaFuncAttributeMaxDynamicSharedMemorySize, SMEM7);
    cudaFuncSetAttribute(tconv<3,1,0,false>, cudaFuncAttributeMaxDynamicSharedMemorySize, SMEM3);
    cudaFuncSetAttribute(tconv<3,2,1,true>,  cudaFuncAttributeMaxDynamicSharedMemorySize, SMEM3);
    cudaFuncSetAttribute(tconv<3,1,1,false>, cudaFuncAttributeMaxDynamicSharedMemorySize, SMEM3);

    // 1) fused weight prep (fp16 hi/lo, swizzled chunks)
    prep_all<<<1024, 256>>>(W_up, W_c2, W_d1, W_d2, W_d3, wbf);

    // 2) up branch: conv7x7 + BN + GELU -> bilinear up x2
    tconv<7,2,1,false><<<dim3(3, 24, 8), 256, SMEM7>>>(
        small_x, nullptr, (const uint4*)(wbf + (size_t)CH_UP * 16384),
        b_up, gup, beup, mup, vup, nullptr, u, h_, w_);
    up2_kernel<<<(R_ELEMS + 255) / 256, 256>>>(u, sm, B_ * 64, h_);

    // 3) uncertainty maps (fused: up2+sigmoid+dilate+scale)
    diff_kernel<<<(B_ * h_ * w_ + 255) / 256, 256>>>(sm, x, ds);
    fused_bf<<<dim3(6, 24, 8), 256>>>(x, in_map, ds, bf);

    // 4) conv chain (HMMA, fp16 2-term)
    tconv<3,1,0,false><<<dim3(6, 48, 8), 256, SMEM3>>>(
        bf, nullptr, (const uint4*)(wbf + (size_t)CH_C2 * 16384),
        b_c2, nullptr, nullptr, nullptr, nullptr, beta, fn, H_, W_);
    tconv<3,2,1,true><<<dim3(6, 48, 8), 256, SMEM3>>>(
        sm, fn, (const uint4*)(wbf + (size_t)CH_D1 * 16384),
        b_d1, gd1, bed1, md1, vd1, nullptr, r1, H_, W_);
    tconv<3,1,1,false><<<dim3(6, 48, 8), 256, SMEM3>>>(
        r1, nullptr, (const uint4*)(wbf + (size_t)CH_D2 * 16384),
        b_d2, gd2, bed2, md2, vd2, nullptr, r2, H_, W_);
    tconv<3,1,1,false><<<dim3(6, 48, 8), 256, SMEM3>>>(
        r2, nullptr, (const uint4*)(wbf + (size_t)CH_D3 * 16384),
        b_d3, gd3, bed3, md3, vd3, nullptr, (float*)d_out, H_, W_);

    // 5) output head reads r from d_out, writes output_map after it
    conv_out_kernel<<<dim3(6, 24, 8), 256>>>(
        (const float*)d_out, W_out, b_out, (float*)d_out + R_ELEMS);
}

// round 7
// speedup vs baseline: 3.7900x; 1.1369x over previous
#include <cuda_runtime.h>
#include <cuda_fp16.h>
#include <math.h>
#include <stdint.h>

// ---------------- problem constants ----------------
#define B_ 8
#define H_ 192
#define W_ 192
#define h_ 96
#define w_ 96
#define R_ELEMS (B_*64*H_*W_)        // 18,874,368

// weight-chunk table (each chunk = 16KB: 8KB hi + 8KB lo, [n][k] swizzled fp16)
#define CH_UP 0      // 7x7, CG=2 -> 98 chunks
#define CH_C2 98     // 3x3, CG=1 -> 9
#define CH_D1 107    // 3x3, CG=2 -> 18
#define CH_D2 125    // 9
#define CH_D3 134    // 9
#define CH_TOTAL 143

// ---------------- scratch ----------------
__device__ __align__(16) unsigned char g_wbf[CH_TOTAL * 16384];
__device__ float g_u[B_*64*h_*w_];
__device__ float g_small[R_ELEMS];
__device__ float g_diffs[B_*h_*w_];
__device__ float g_bf[R_ELEMS];
__device__ float g_fn[R_ELEMS];
__device__ float g_r1[R_ELEMS];
__device__ float g_r2[R_ELEMS];

// ---------------- helpers ----------------
__device__ __forceinline__ uint32_t smem_u32(const void* p) {
    uint32_t a;
    asm("{ .reg .u64 t; cvta.to.shared.u64 t, %1; cvt.u32.u64 %0, t; }" : "=r"(a) : "l"(p));
    return a;
}
__device__ __forceinline__ void ldm4(uint32_t addr, uint32_t r[4]) {
    asm volatile("ldmatrix.sync.aligned.m8n8.x4.shared.b16 {%0,%1,%2,%3}, [%4];"
                 : "=r"(r[0]), "=r"(r[1]), "=r"(r[2]), "=r"(r[3]) : "r"(addr));
}
__device__ __forceinline__ void mma16816(float c[4], const uint32_t a[4],
                                         uint32_t b0, uint32_t b1) {
    asm volatile(
        "mma.sync.aligned.m16n8k16.row.col.f32.f16.f16.f32 "
        "{%0,%1,%2,%3}, {%4,%5,%6,%7}, {%8,%9}, {%0,%1,%2,%3};"
        : "+f"(c[0]), "+f"(c[1]), "+f"(c[2]), "+f"(c[3])
        : "r"(a[0]), "r"(a[1]), "r"(a[2]), "r"(a[3]), "r"(b0), "r"(b1));
}
__device__ __forceinline__ void cpa16(uint32_t saddr, const void* g) {
    asm volatile("cp.async.cg.shared.global [%0], [%1], 16;" :: "r"(saddr), "l"(g) : "memory");
}
#define CPA_COMMIT() asm volatile("cp.async.commit_group;" ::: "memory")
#define CPA_WAIT0()  asm volatile("cp.async.wait_group 0;" ::: "memory")

__device__ __forceinline__ float gelu_exact(float y) {
    return 0.5f * y * (1.0f + erff(y * 0.70710678118654752f));
}
__device__ __forceinline__ uint32_t packh2(float a, float b) {
    __half2 h = __floats2half2_rn(a, b);
    return *(uint32_t*)&h;
}

// ---------------- fused weight prep: all 5 conv weight sets ----------------
__global__ void prep_all(const float* __restrict__ W_up, const float* __restrict__ W_c2,
                         const float* __restrict__ W_d1, const float* __restrict__ W_d2,
                         const float* __restrict__ W_d3, unsigned char* __restrict__ dst)
{
    int total = CH_TOTAL * 4096;
    for (int idx = blockIdx.x * blockDim.x + threadIdx.x; idx < total;
         idx += gridDim.x * blockDim.x) {
        int chunk = idx >> 12;
        int e = idx & 4095;
        int n = e >> 6, k = e & 63;
        const float* W; int CIN, KK, local;
        if (chunk < 98)       { W = W_up; CIN = 128; KK = 49; local = chunk; }
        else if (chunk < 107) { W = W_c2; CIN = 64;  KK = 9;  local = chunk - 98; }
        else if (chunk < 125) { W = W_d1; CIN = 128; KK = 9;  local = chunk - 107; }
        else if (chunk < 134) { W = W_d2; CIN = 64;  KK = 9;  local = chunk - 125; }
        else                  { W = W_d3; CIN = 64;  KK = 9;  local = chunk - 134; }
        int CG = CIN >> 6;
        int tap = local / CG, cg = local - tap * CG;
        float w = W[((size_t)n * CIN + cg * 64 + k) * KK + tap];
        __half hb = __float2half_rn(w);
        __half lb = __float2half_rn(w - __half2float(hb));
        uint32_t off = (uint32_t)n * 128 + ((((k >> 3) ^ (n & 7))) << 4) + (k & 7) * 2;
        unsigned char* base = dst + (size_t)chunk * 16384;
        *(unsigned short*)(base + off)        = __half_as_ushort(hb);
        *(unsigned short*)(base + 8192 + off) = __half_as_ushort(lb);
    }
}

// ---------------- HMMA implicit-GEMM conv ----------------
// TM rows x 32 px per CTA, 64 out chans.
// TM=8: warp tile m64 x n32 (4 m16-tiles).  TM=4: warp tile m32 x n32.
// NTERM=2: B = hi+lo fp16 (weights exact). NTERM=1: B = hi only.
// MODE 0: beta*(acc+bias)   MODE 1: gelu(bn(acc+bias))
template<int KS, int CG, int TM, int NTERM, int MODE, bool CONCAT>
__global__ __launch_bounds__(256, 2)
void tconv(const float* __restrict__ inA, const float* __restrict__ inB,
           const uint4* __restrict__ wch, const float* __restrict__ bias,
           const float* __restrict__ gg, const float* __restrict__ bb,
           const float* __restrict__ mm, const float* __restrict__ vv,
           const float* __restrict__ betap, float* __restrict__ out,
           int H, int W)
{
    constexpr int PAD = KS / 2;
    constexpr int IH  = TM + KS - 1;
    constexpr int IWP = 40;
    constexpr int NPX = IH * IWP;
    constexpr int KK  = KS * KS;
    constexpr int NCH = KK * CG;
    constexpr int OFF_A = 1024;
    constexpr int OFF_B = 1024 + NPX * 128;
    constexpr int NACC = (TM == 8) ? 16 : 8;

    extern __shared__ char smem_raw[];
    char* smem = (char*)(((uintptr_t)smem_raw + 1023) & ~(uintptr_t)1023);
    uint32_t sb = smem_u32(smem);
    float* epi = (float*)smem;

    int tid = threadIdx.x, wid = tid >> 5, lane = tid & 31;
    int x0 = blockIdx.x * 32, y0 = blockIdx.y * TM, b = blockIdx.z;
    size_t HW = (size_t)H * W;

    // prefetch first B chunk
    {
        const uint4* srcB = wch;
        uint32_t dstB = sb + OFF_B;
#pragma unroll
        for (int k = 0; k < 4; k++)
            cpa16(dstB + (uint32_t)(tid + k * 256) * 16, srcB + tid + k * 256);
        CPA_COMMIT();
    }

    if (tid < 64) {
        int c = tid;
        float s, t;
        if (MODE == 1) {
            s = gg[c] * rsqrtf(vv[c] + 1e-5f);
            t = (bias[c] - mm[c]) * s + bb[c];
        } else {
            float bt = *betap;
            s = bt; t = bt * bias[c];
        }
        epi[c] = s; epi[64 + c] = t;
    }

    float acc[NACC][4];
#pragma unroll
    for (int i = 0; i < NACC; i++)
#pragma unroll
        for (int j = 0; j < 4; j++) acc[i][j] = 0.f;

    int wm = wid >> 1, nh = wid & 1;
    int ar = lane & 15, akq = lane >> 4;
    int br = lane & 15, bkq = lane >> 4;

    int gctr = 0;
    for (int cg = 0; cg < CG; cg++) {
        __syncthreads();

        // ---- stage halo: fp16, [pixel][chan] rows, XOR-16B swizzle ----
        {
            const float* src;
            if (CONCAT) src = (cg ? inB : inA) + (size_t)b * 64 * HW;
            else        src = inA + ((size_t)b * (CG * 64) + cg * 64) * HW;
            constexpr int TOT = NPX * 8;
            for (int item = tid; item < TOT; item += 256) {
                int o  = item / NPX;
                int ph = item - o * NPX;
                int hy = ph / IWP, hx = ph - hy * IWP;
                int gy = y0 + hy - PAD;
                int gx = x0 + hx - 4;
                float v[8];
                if ((unsigned)gy < (unsigned)H && (unsigned)gx < (unsigned)W) {
                    const float* p = src + (size_t)(o * 8) * HW + (size_t)gy * W + gx;
#pragma unroll
                    for (int j = 0; j < 8; j++) v[j] = p[j * HW];
                } else {
#pragma unroll
                    for (int j = 0; j < 8; j++) v[j] = 0.f;
                }
                uint4 hi4;
                hi4.x = packh2(v[0], v[1]); hi4.y = packh2(v[2], v[3]);
                hi4.z = packh2(v[4], v[5]); hi4.w = packh2(v[6], v[7]);
                uint32_t ad = (uint32_t)ph * 128 + (((o ^ (ph & 7))) << 4);
                *(uint4*)(smem + OFF_A + ad) = hi4;
            }
        }

        for (int tap = 0; tap < KK; tap++, gctr++) {
            int s = gctr & 1;
            CPA_WAIT0();
            __syncthreads();

            if (gctr + 1 < NCH) {
                int nch = (tap + 1 < KK) ? (tap + 1) * CG + cg : (cg + 1);
                const uint4* srcB = wch + (size_t)nch * 1024;
                uint32_t dstB = sb + OFF_B + (s ^ 1) * 16384;
#pragma unroll
                for (int k = 0; k < 4; k++)
                    cpa16(dstB + (uint32_t)(tid + k * 256) * 16, srcB + tid + k * 256);
                CPA_COMMIT();
            }

            int tapy = tap / KS, tapx = tap - tapy * KS;
            uint32_t bbase = sb + OFF_B + s * 16384;

            if (TM == 8) {
                // ---- warp tile m64 x n32 ----
#pragma unroll
                for (int kc = 0; kc < 4; kc++) {
                    uint32_t a[4][4];
#pragma unroll
                    for (int t = 0; t < 4; t++) {
                        int y = wm * 2 + (t >> 1);
                        int ph = (y + tapy) * IWP + (t & 1) * 16 + ar + tapx + (4 - PAD);
                        ldm4(sb + OFF_A + (uint32_t)ph * 128
                             + ((((kc * 2 + akq) ^ (ph & 7))) << 4), a[t]);
                    }
#pragma unroll
                    for (int g = 0; g < 2; g++) {
                        int n = nh * 32 + g * 16 + br;
                        uint32_t ba = bbase + (uint32_t)n * 128
                                    + ((((kc * 2 + bkq) ^ (n & 7))) << 4);
                        uint32_t bh[4];
                        ldm4(ba, bh);
#pragma unroll
                        for (int t = 0; t < 4; t++) {
                            mma16816(acc[t * 4 + 2 * g],     a[t], bh[0], bh[2]);
                            mma16816(acc[t * 4 + 2 * g + 1], a[t], bh[1], bh[3]);
                        }
                        if (NTERM == 2) {
                            uint32_t bl[4];
                            ldm4(ba + 8192, bl);
#pragma unroll
                            for (int t = 0; t < 4; t++) {
                                mma16816(acc[t * 4 + 2 * g],     a[t], bl[0], bl[2]);
                                mma16816(acc[t * 4 + 2 * g + 1], a[t], bl[1], bl[3]);
                            }
                        }
                    }
                }
            } else {
                // ---- warp tile m32 x n32 (TM=4) ----
                int ph0 = (wm + tapy) * IWP + ar + tapx + (4 - PAD);
                int ph1 = ph0 + 16;
                uint32_t a0r = sb + OFF_A + (uint32_t)ph0 * 128;
                uint32_t a1r = sb + OFF_A + (uint32_t)ph1 * 128;
                int asw0 = ph0 & 7, asw1 = ph1 & 7;
#pragma unroll
                for (int kc = 0; kc < 4; kc++) {
                    int q0 = ((kc * 2 + akq) ^ asw0) << 4;
                    int q1 = ((kc * 2 + akq) ^ asw1) << 4;
                    uint32_t a0[4], a1[4];
                    ldm4(a0r + q0, a0);
                    ldm4(a1r + q1, a1);
#pragma unroll
                    for (int g = 0; g < 2; g++) {
                        int n = nh * 32 + g * 16 + br;
                        uint32_t ba = bbase + (uint32_t)n * 128
                                    + ((((kc * 2 + bkq) ^ (n & 7))) << 4);
                        uint32_t bh[4];
                        ldm4(ba, bh);
                        mma16816(acc[2 * g],     a0, bh[0], bh[2]);
                        mma16816(acc[2 * g + 1], a0, bh[1], bh[3]);
                        mma16816(acc[4 + 2 * g],     a1, bh[0], bh[2]);
                        mma16816(acc[4 + 2 * g + 1], a1, bh[1], bh[3]);
                        if (NTERM == 2) {
                            uint32_t bl[4];
                            ldm4(ba + 8192, bl);
                            mma16816(acc[2 * g],     a0, bl[0], bl[2]);
                            mma16816(acc[2 * g + 1], a0, bl[1], bl[3]);
                            mma16816(acc[4 + 2 * g],     a1, bl[0], bl[2]);
                            mma16816(acc[4 + 2 * g + 1], a1, bl[1], bl[3]);
                        }
                    }
                }
            }
        }
    }

    // ---- epilogue: transpose through smem, coalesced NCHW store ----
    __syncthreads();
    float* tb = (float*)(smem + 1024);            // [TM*32][65] fp32, conflict-free reads
    {
        int row = lane >> 2, colp = (lane & 3) * 2;
        if (TM == 8) {
#pragma unroll
            for (int t = 0; t < 4; t++) {
                int p0 = wm * 64 + t * 16 + row;
#pragma unroll
                for (int j = 0; j < 4; j++) {
                    int c = nh * 32 + j * 8 + colp;
                    tb[p0 * 65 + c]            = acc[t * 4 + j][0];
                    tb[p0 * 65 + c + 1]        = acc[t * 4 + j][1];
                    tb[(p0 + 8) * 65 + c]      = acc[t * 4 + j][2];
                    tb[(p0 + 8) * 65 + c + 1]  = acc[t * 4 + j][3];
                }
            }
        } else {
#pragma unroll
            for (int j = 0; j < 4; j++) {
                int c = nh * 32 + j * 8 + colp;
                int p0 = wm * 32 + row;
                tb[p0 * 65 + c]            = acc[j][0];
                tb[p0 * 65 + c + 1]        = acc[j][1];
                tb[(p0 + 8) * 65 + c]      = acc[j][2];
                tb[(p0 + 8) * 65 + c + 1]  = acc[j][3];
                int p1 = p0 + 16;
                tb[p1 * 65 + c]            = acc[4 + j][0];
                tb[p1 * 65 + c + 1]        = acc[4 + j][1];
                tb[(p1 + 8) * 65 + c]      = acc[4 + j][2];
                tb[(p1 + 8) * 65 + c + 1]  = acc[4 + j][3];
            }
        }
    }
    __syncthreads();
    constexpr int NIT = TM * 64 / 8;              // items = 64 chans * TM rows / 8 warps
#pragma unroll 4
    for (int it = 0; it < NIT; it++) {
        int item = it * 8 + wid;
        int c = item / TM, py = item % TM;
        float v = tb[(py * 32 + lane) * 65 + c] * epi[c] + epi[64 + c];
        if (MODE == 1) v = gelu_exact(v);
        out[((size_t)(b * 64 + c) * H + (y0 + py)) * W + x0 + lane] = v;
    }
}

// ---------------- bilinear up x2 (align_corners=True) ----------------
__global__ void up2_kernel(const float* __restrict__ in, float* __restrict__ out,
                           int BC, int n)
{
    int N = 2 * n;
    size_t total = (size_t)BC * N * N;
    size_t idx = (size_t)blockIdx.x * blockDim.x + threadIdx.x;
    if (idx >= total) return;
    int xo = (int)(idx % N);
    size_t r = idx / N;
    int yo = (int)(r % N);
    int bc = (int)(r / N);
    float rr = (float)(n - 1) / (float)(N - 1);
    float sy = yo * rr; int iy0 = (int)sy; float wy = sy - (float)iy0; int iy1 = min(iy0 + 1, n - 1);
    float sx = xo * rr; int ix0 = (int)sx; float wx = sx - (float)ix0; int ix1 = min(ix0 + 1, n - 1);
    const float* p = in + (size_t)bc * n * n;
    float a = p[iy0 * n + ix0], bv = p[iy1 * n + ix0];
    float c = p[iy0 * n + ix1], d = p[iy1 * n + ix1];
    float ra = a * (1.f - wy) + bv * wy;
    float rb = c * (1.f - wy) + d * wy;
    out[idx] = ra * (1.f - wx) + rb * wx;
}

// ---------------- AP_MP(small,x) + AP_MP(x,small) at half resolution ----------------
__global__ void diff_kernel(const float* __restrict__ sm, const float* __restrict__ x,
                            float* __restrict__ out)
{
    int idx = blockIdx.x * blockDim.x + threadIdx.x;
    if (idx >= B_ * h_ * w_) return;
    int j = idx % w_;
    int t = idx / w_;
    int i = t % h_;
    int b = t / h_;
    float acc1 = 0.f, acc2 = 0.f;
    size_t base0 = ((size_t)b * 64 * H_ + 2 * i) * W_ + 2 * j;
    for (int c = 0; c < 64; c++) {
        size_t base = base0 + (size_t)c * H_ * W_;
        float2 s0 = *(const float2*)(sm + base);
        float2 s1 = *(const float2*)(sm + base + W_);
        float2 xa = *(const float2*)(x + base);
        float2 xb = *(const float2*)(x + base + W_);
        float as = 0.25f * (s0.x + s0.y + s1.x + s1.y);
        float ms = fmaxf(fmaxf(s0.x, s0.y), fmaxf(s1.x, s1.y));
        float ax = 0.25f * (xa.x + xa.y + xb.x + xb.y);
        float mx = fmaxf(fmaxf(xa.x, xa.y), fmaxf(xb.x, xb.y));
        float d1 = as - mx; acc1 += d1 * d1;
        float d2 = ax - ms; acc2 += d2 * d2;
    }
    out[idx] = sqrtf(acc1) + sqrtf(acc2);
}

// ---------------- fused: sigmoid(up2(map)) x2 -> dilate3 - map -> scale x -> bf ----------------
__global__ __launch_bounds__(256)
void fused_bf(const float* __restrict__ x, const float* __restrict__ in_map,
              const float* __restrict__ ds, float* __restrict__ bf)
{
    __shared__ float s_i[10 * 34];
    __shared__ float s_d[10 * 34];
    int tid = threadIdx.x;
    int x0 = blockIdx.x * 32, y0 = blockIdx.y * 8, b = blockIdx.z;
    const float rr = 95.f / 191.f;
    const float* pi = in_map + (size_t)b * h_ * w_;
    const float* pd = ds + (size_t)b * h_ * w_;

    for (int item = tid; item < 340; item += 256) {
        int hy = item / 34, hx = item - hy * 34;
        int gy = y0 - 1 + hy, gx = x0 - 1 + hx;
        float vi = -INFINITY, vd = -INFINITY;
        if ((unsigned)gy < (unsigned)H_ && (unsigned)gx < (unsigned)W_) {
            float sy = gy * rr; int iy0 = (int)sy; float wy = sy - (float)iy0;
            int iy1 = min(iy0 + 1, h_ - 1);
            float sx = gx * rr; int ix0 = (int)sx; float wx = sx - (float)ix0;
            int ix1 = min(ix0 + 1, w_ - 1);
            float w00 = (1.f - wy) * (1.f - wx), w01 = (1.f - wy) * wx;
            float w10 = wy * (1.f - wx),         w11 = wy * wx;
            float ui = pi[iy0 * w_ + ix0] * w00 + pi[iy0 * w_ + ix1] * w01
                     + pi[iy1 * w_ + ix0] * w10 + pi[iy1 * w_ + ix1] * w11;
            float ud = pd[iy0 * w_ + ix0] * w00 + pd[iy0 * w_ + ix1] * w01
                     + pd[iy1 * w_ + ix0] * w10 + pd[iy1 * w_ + ix1] * w11;
            vi = 1.f / (1.f + expf(-ui));
            vd = 1.f / (1.f + expf(-ud));
        }
        s_i[item] = vi; s_d[item] = vd;
    }
    __syncthreads();

    int tx = tid & 31, ty = tid >> 5;
    int ci = (ty + 1) * 34 + tx + 1;
    float mi = -INFINITY, md = -INFINITY;
#pragma unroll
    for (int dy = 0; dy < 3; dy++)
#pragma unroll
        for (int dx = 0; dx < 3; dx++) {
            int o = (ty + dy) * 34 + tx + dx;
            mi = fmaxf(mi, s_i[o]);
            md = fmaxf(md, s_d[o]);
        }
    float s = (mi - s_i[ci]) + (md - s_d[ci]) + 1.0f;
    size_t base = ((size_t)(b * 64) * H_ + (y0 + ty)) * W_ + x0 + tx;
    for (int c = 0; c < 64; c++) {
        size_t o = base + (size_t)c * H_ * W_;
        bf[o] = x[o] * s;
    }
}

// ---------------- final conv 7x7, 64 -> 1 (fp32) ----------------
__global__ __launch_bounds__(256)
void conv_out_kernel(const float* __restrict__ rin, const float* __restrict__ Wo,
                     const float* __restrict__ bo, float* __restrict__ out)
{
    __shared__ float s_in[8 * 14 * 38];
    __shared__ float s_w[8 * 49];
    int tid = threadIdx.x, tx = tid & 31, ty = tid >> 5;
    int x0 = blockIdx.x * 32, ys = blockIdx.y * 8, b = blockIdx.z;
    float acc = 0.f;
    for (int c0 = 0; c0 < 64; c0 += 8) {
        for (int idx = tid; idx < 8 * 14 * 38; idx += 256) {
            int c = idx / (14 * 38);
            int r = idx - c * (14 * 38);
            int ly = r / 38, lx = r - ly * 38;
            int gy = ys + ly - 3, gx = x0 + lx - 3;
            float v = 0.f;
            if ((unsigned)gy < (unsigned)H_ && (unsigned)gx < (unsigned)W_)
                v = rin[((size_t)(b * 64 + c0 + c) * H_ + gy) * W_ + gx];
            s_in[idx] = v;
        }
        for (int idx = tid; idx < 8 * 49; idx += 256)
            s_w[idx] = Wo[(c0 + idx / 49) * 49 + idx % 49];
        __syncthreads();
#pragma unroll
        for (int c = 0; c < 8; c++)
            for (int ky = 0; ky < 7; ky++)
#pragma unroll
                for (int kx = 0; kx < 7; kx++)
                    acc += s_w[c * 49 + ky * 7 + kx] * s_in[(c * 14 + ty + ky) * 38 + tx + kx];
        __syncthreads();
    }
    out[((size_t)b * H_ + (ys + ty)) * W_ + x0 + tx] = acc + bo[0];
}

// ---------------- launch ----------------
#define SMEMC (1024 + 10*40*128 + 2*16384)   // 84992 (both TM=8/KS=3 and TM=4/KS=7)

extern "C" void kernel_launch(void* const* d_in, const int* in_sizes, int n_in,
                              void* d_out, int out_size)
{
    const float* x       = (const float*)d_in[0];
    const float* small_x = (const float*)d_in[1];
    const float* in_map  = (const float*)d_in[2];
    const float* W_up  = (const float*)d_in[3];
    const float* b_up  = (const float*)d_in[4];
    const float* gup   = (const float*)d_in[5];
    const float* beup  = (const float*)d_in[6];
    const float* mup   = (const float*)d_in[7];
    const float* vup   = (const float*)d_in[8];
    const float* W_c2  = (const float*)d_in[9];
    const float* b_c2  = (const float*)d_in[10];
    const float* W_d1  = (const float*)d_in[11];
    const float* b_d1  = (const float*)d_in[12];
    const float* gd1   = (const float*)d_in[13];
    const float* bed1  = (const float*)d_in[14];
    const float* md1   = (const float*)d_in[15];
    const float* vd1   = (const float*)d_in[16];
    const float* W_d2  = (const float*)d_in[17];
    const float* b_d2  = (const float*)d_in[18];
    const float* gd2   = (const float*)d_in[19];
    const float* bed2  = (const float*)d_in[20];
    const float* md2   = (const float*)d_in[21];
    const float* vd2   = (const float*)d_in[22];
    const float* W_d3  = (const float*)d_in[23];
    const float* b_d3  = (const float*)d_in[24];
    const float* gd3   = (const float*)d_in[25];
    const float* bed3  = (const float*)d_in[26];
    const float* md3   = (const float*)d_in[27];
    const float* vd3   = (const float*)d_in[28];
    const float* W_out = (const float*)d_in[29];
    const float* b_out = (const float*)d_in[30];
    const float* beta  = (const float*)d_in[31];

    float *u, *sm, *ds, *bf, *fn, *r1, *r2;
    unsigned char* wbf;
    cudaGetSymbolAddress((void**)&u,   g_u);
    cudaGetSymbolAddress((void**)&sm,  g_small);
    cudaGetSymbolAddress((void**)&ds,  g_diffs);
    cudaGetSymbolAddress((void**)&bf,  g_bf);
    cudaGetSymbolAddress((void**)&fn,  g_fn);
    cudaGetSymbolAddress((void**)&r1,  g_r1);
    cudaGetSymbolAddress((void**)&r2,  g_r2);
    cudaGetSymbolAddress((void**)&wbf, g_wbf);

    cudaFuncSetAttribute(tconv<7,2,4,1,1,false>, cudaFuncAttributeMaxDynamicSharedMemorySize, SMEMC);
    cudaFuncSetAttribute(tconv<3,1,8,2,0,false>, cudaFuncAttributeMaxDynamicSharedMemorySize, SMEMC);
    cudaFuncSetAttribute(tconv<3,2,8,2,1,true>,  cudaFuncAttributeMaxDynamicSharedMemorySize, SMEMC);
    cudaFuncSetAttribute(tconv<3,1,8,2,1,false>, cudaFuncAttributeMaxDynamicSharedMemorySize, SMEMC);

    // 1) fused weight prep (fp16 hi/lo, swizzled chunks)
    prep_all<<<1024, 256>>>(W_up, W_c2, W_d1, W_d2, W_d3, wbf);

    // 2) up branch: conv7x7 (1-term fp16) + BN + GELU -> bilinear up x2
    tconv<7,2,4,1,1,false><<<dim3(3, 24, 8), 256, SMEMC>>>(
        small_x, nullptr, (const uint4*)(wbf + (size_t)CH_UP * 16384),
        b_up, gup, beup, mup, vup, nullptr, u, h_, w_);
    up2_kernel<<<(R_ELEMS + 255) / 256, 256>>>(u, sm, B_ * 64, h_);

    // 3) uncertainty maps (fused)
    diff_kernel<<<(B_ * h_ * w_ + 255) / 256, 256>>>(sm, x, ds);
    fused_bf<<<dim3(6, 24, 8), 256>>>(x, in_map, ds, bf);

    // 4) conv chain (HMMA, fp16 2-term, m64n32 warp tiles)
    tconv<3,1,8,2,0,false><<<dim3(6, 24, 8), 256, SMEMC>>>(
        bf, nullptr, (const uint4*)(wbf + (size_t)CH_C2 * 16384),
        b_c2, nullptr, nullptr, nullptr, nullptr, beta, fn, H_, W_);
    tconv<3,2,8,2,1,true><<<dim3(6, 24, 8), 256, SMEMC>>>(
        sm, fn, (const uint4*)(wbf + (size_t)CH_D1 * 16384),
        b_d1, gd1, bed1, md1, vd1, nullptr, r1, H_, W_);
    tconv<3,1,8,2,1,false><<<dim3(6, 24, 8), 256, SMEMC>>>(
        r1, nullptr, (const uint4*)(wbf + (size_t)CH_D2 * 16384),
        b_d2, gd2, bed2, md2, vd2, nullptr, r2, H_, W_);
    tconv<3,1,8,2,1,false><<<dim3(6, 24, 8), 256, SMEMC>>>(
        r2, nullptr, (const uint4*)(wbf + (size_t)CH_D3 * 16384),
        b_d3, gd3, bed3, md3, vd3, nullptr, (float*)d_out, H_, W_);

    // 5) output head reads r from d_out, writes output_map after it
    conv_out_kernel<<<dim3(6, 24, 8), 256>>>(
        (const float*)d_out, W_out, b_out, (float*)d_out + R_ELEMS);
}

// round 8
// speedup vs baseline: 4.5086x; 1.1896x over previous
#include <cuda_runtime.h>
#include <cuda_fp16.h>
#include <math.h>
#include <stdint.h>

// ---------------- problem constants ----------------
#define B_ 8
#define H_ 192
#define W_ 192
#define h_ 96
#define w_ 96
#define R_ELEMS (B_*64*H_*W_)        // 18,874,368

// weight-chunk table (each chunk = 16KB: 8KB hi + 8KB lo, [n][k] swizzled fp16)
#define CH_UP 0      // 7x7, CG=2 -> 98 chunks
#define CH_C2 98     // 3x3, CG=1 -> 9
#define CH_D1 107    // 3x3, CG=2 -> 18
#define CH_D2 125    // 9
#define CH_D3 134    // 9
#define CH_TOTAL 143

// ---------------- scratch ----------------
__device__ __align__(16) unsigned char g_wbf[CH_TOTAL * 16384];
__device__ float g_u[B_*64*h_*w_];
__device__ float g_small[R_ELEMS];
__device__ float g_diffs[B_*h_*w_];
__device__ float g_bf[R_ELEMS];
__device__ float g_fn[R_ELEMS];
__device__ float g_r1[R_ELEMS];
__device__ float g_r2[R_ELEMS];

// ---------------- helpers ----------------
__device__ __forceinline__ uint32_t smem_u32(const void* p) {
    uint32_t a;
    asm("{ .reg .u64 t; cvta.to.shared.u64 t, %1; cvt.u32.u64 %0, t; }" : "=r"(a) : "l"(p));
    return a;
}
__device__ __forceinline__ void ldm4(uint32_t addr, uint32_t r[4]) {
    asm volatile("ldmatrix.sync.aligned.m8n8.x4.shared.b16 {%0,%1,%2,%3}, [%4];"
                 : "=r"(r[0]), "=r"(r[1]), "=r"(r[2]), "=r"(r[3]) : "r"(addr));
}
__device__ __forceinline__ void mma16816(float c[4], const uint32_t a[4],
                                         uint32_t b0, uint32_t b1) {
    asm volatile(
        "mma.sync.aligned.m16n8k16.row.col.f32.f16.f16.f32 "
        "{%0,%1,%2,%3}, {%4,%5,%6,%7}, {%8,%9}, {%0,%1,%2,%3};"
        : "+f"(c[0]), "+f"(c[1]), "+f"(c[2]), "+f"(c[3])
        : "r"(a[0]), "r"(a[1]), "r"(a[2]), "r"(a[3]), "r"(b0), "r"(b1));
}
__device__ __forceinline__ void cpa16(uint32_t saddr, const void* g) {
    asm volatile("cp.async.cg.shared.global [%0], [%1], 16;" :: "r"(saddr), "l"(g) : "memory");
}
#define CPA_COMMIT() asm volatile("cp.async.commit_group;" ::: "memory")
#define CPA_WAIT0()  asm volatile("cp.async.wait_group 0;" ::: "memory")

__device__ __forceinline__ float gelu_exact(float y) {
    return 0.5f * y * (1.0f + erff(y * 0.70710678118654752f));
}
__device__ __forceinline__ uint32_t packh2(float a, float b) {
    __half2 h = __floats2half2_rn(a, b);
    return *(uint32_t*)&h;
}

// ---------------- fused weight prep: all 5 conv weight sets ----------------
__global__ void prep_all(const float* __restrict__ W_up, const float* __restrict__ W_c2,
                         const float* __restrict__ W_d1, const float* __restrict__ W_d2,
                         const float* __restrict__ W_d3, unsigned char* __restrict__ dst)
{
    int total = CH_TOTAL * 4096;
    for (int idx = blockIdx.x * blockDim.x + threadIdx.x; idx < total;
         idx += gridDim.x * blockDim.x) {
        int chunk = idx >> 12;
        int e = idx & 4095;
        int n = e >> 6, k = e & 63;
        const float* W; int CIN, KK, local;
        if (chunk < 98)       { W = W_up; CIN = 128; KK = 49; local = chunk; }
        else if (chunk < 107) { W = W_c2; CIN = 64;  KK = 9;  local = chunk - 98; }
        else if (chunk < 125) { W = W_d1; CIN = 128; KK = 9;  local = chunk - 107; }
        else if (chunk < 134) { W = W_d2; CIN = 64;  KK = 9;  local = chunk - 125; }
        else                  { W = W_d3; CIN = 64;  KK = 9;  local = chunk - 134; }
        int CG = CIN >> 6;
        int tap = local / CG, cg = local - tap * CG;
        float w = W[((size_t)n * CIN + cg * 64 + k) * KK + tap];
        __half hb = __float2half_rn(w);
        __half lb = __float2half_rn(w - __half2float(hb));
        uint32_t off = (uint32_t)n * 128 + ((((k >> 3) ^ (n & 7))) << 4) + (k & 7) * 2;
        unsigned char* base = dst + (size_t)chunk * 16384;
        *(unsigned short*)(base + off)        = __half_as_ushort(hb);
        *(unsigned short*)(base + 8192 + off) = __half_as_ushort(lb);
    }
}

// ---------------- HMMA implicit-GEMM conv ----------------
// TM rows x 32 px per CTA, 64 out chans. TM=8: warp tile m64 x n32.
// NTERM=2: B = hi+lo fp16.  NTERM=1: B = hi only (copies 8KB/chunk).
// MODE 0: beta*(acc+bias)   MODE 1: gelu(bn(acc+bias))
template<int KS, int CG, int TM, int NTERM, int MODE, bool CONCAT>
__global__ __launch_bounds__(256, 2)
void tconv(const float* __restrict__ inA, const float* __restrict__ inB,
           const uint4* __restrict__ wch, const float* __restrict__ bias,
           const float* __restrict__ gg, const float* __restrict__ bb,
           const float* __restrict__ mm, const float* __restrict__ vv,
           const float* __restrict__ betap, float* __restrict__ out,
           int H, int W)
{
    constexpr int PAD = KS / 2;
    constexpr int IH  = TM + KS - 1;
    constexpr int IWP = 40;
    constexpr int NPX = IH * IWP;
    constexpr int KK  = KS * KS;
    constexpr int NCH = KK * CG;
    constexpr int OFF_A = 1024;
    constexpr int OFF_B = 1024 + NPX * 128;
    constexpr int BSTRIDE = NTERM * 8192;        // bytes per staged B chunk
    constexpr int BCPY = NTERM * 2;              // 16B items per thread
    constexpr int NACC = (TM == 8) ? 16 : 8;

    extern __shared__ char smem_raw[];
    char* smem = (char*)(((uintptr_t)smem_raw + 1023) & ~(uintptr_t)1023);
    uint32_t sb = smem_u32(smem);
    float* epi = (float*)smem;

    int tid = threadIdx.x, wid = tid >> 5, lane = tid & 31;
    int x0 = blockIdx.x * 32, y0 = blockIdx.y * TM, b = blockIdx.z;
    size_t HW = (size_t)H * W;

    // prefetch first B chunk (hi half only when NTERM==1)
    {
        const uint4* srcB = wch;
        uint32_t dstB = sb + OFF_B;
#pragma unroll
        for (int k = 0; k < BCPY; k++)
            cpa16(dstB + (uint32_t)(tid + k * 256) * 16, srcB + tid + k * 256);
        CPA_COMMIT();
    }

    if (tid < 64) {
        int c = tid;
        float s, t;
        if (MODE == 1) {
            s = gg[c] * rsqrtf(vv[c] + 1e-5f);
            t = (bias[c] - mm[c]) * s + bb[c];
        } else {
            float bt = *betap;
            s = bt; t = bt * bias[c];
        }
        epi[c] = s; epi[64 + c] = t;
    }

    float acc[NACC][4];
#pragma unroll
    for (int i = 0; i < NACC; i++)
#pragma unroll
        for (int j = 0; j < 4; j++) acc[i][j] = 0.f;

    int wm = wid >> 1, nh = wid & 1;
    int ar = lane & 15, akq = lane >> 4;
    int br = lane & 15, bkq = lane >> 4;

    int gctr = 0;
    for (int cg = 0; cg < CG; cg++) {
        __syncthreads();

        // ---- stage halo: fp16, [pixel][chan] rows, XOR-16B swizzle ----
        {
            const float* src;
            if (CONCAT) src = (cg ? inB : inA) + (size_t)b * 64 * HW;
            else        src = inA + ((size_t)b * (CG * 64) + cg * 64) * HW;
            constexpr int TOT = NPX * 8;
            for (int item = tid; item < TOT; item += 256) {
                int o  = item / NPX;
                int ph = item - o * NPX;
                int hy = ph / IWP, hx = ph - hy * IWP;
                int gy = y0 + hy - PAD;
                int gx = x0 + hx - 4;
                float v[8];
                if ((unsigned)gy < (unsigned)H && (unsigned)gx < (unsigned)W) {
                    const float* p = src + (size_t)(o * 8) * HW + (size_t)gy * W + gx;
#pragma unroll
                    for (int j = 0; j < 8; j++) v[j] = p[j * HW];
                } else {
#pragma unroll
                    for (int j = 0; j < 8; j++) v[j] = 0.f;
                }
                uint4 hi4;
                hi4.x = packh2(v[0], v[1]); hi4.y = packh2(v[2], v[3]);
                hi4.z = packh2(v[4], v[5]); hi4.w = packh2(v[6], v[7]);
                uint32_t ad = (uint32_t)ph * 128 + (((o ^ (ph & 7))) << 4);
                *(uint4*)(smem + OFF_A + ad) = hi4;
            }
        }

        for (int tap = 0; tap < KK; tap++, gctr++) {
            int s = gctr & 1;
            CPA_WAIT0();
            __syncthreads();

            if (gctr + 1 < NCH) {
                int nch = (tap + 1 < KK) ? (tap + 1) * CG + cg : (cg + 1);
                const uint4* srcB = wch + (size_t)nch * 1024;
                uint32_t dstB = sb + OFF_B + (s ^ 1) * BSTRIDE;
#pragma unroll
                for (int k = 0; k < BCPY; k++)
                    cpa16(dstB + (uint32_t)(tid + k * 256) * 16, srcB + tid + k * 256);
                CPA_COMMIT();
            }

            int tapy = tap / KS, tapx = tap - tapy * KS;
            uint32_t bbase = sb + OFF_B + s * BSTRIDE;

            if (TM == 8) {
                // ---- warp tile m64 x n32 ----
#pragma unroll
                for (int kc = 0; kc < 4; kc++) {
                    uint32_t a[4][4];
#pragma unroll
                    for (int t = 0; t < 4; t++) {
                        int y = wm * 2 + (t >> 1);
                        int ph = (y + tapy) * IWP + (t & 1) * 16 + ar + tapx + (4 - PAD);
                        ldm4(sb + OFF_A + (uint32_t)ph * 128
                             + ((((kc * 2 + akq) ^ (ph & 7))) << 4), a[t]);
                    }
#pragma unroll
                    for (int g = 0; g < 2; g++) {
                        int n = nh * 32 + g * 16 + br;
                        uint32_t ba = bbase + (uint32_t)n * 128
                                    + ((((kc * 2 + bkq) ^ (n & 7))) << 4);
                        uint32_t bh[4];
                        ldm4(ba, bh);
#pragma unroll
                        for (int t = 0; t < 4; t++) {
                            mma16816(acc[t * 4 + 2 * g],     a[t], bh[0], bh[2]);
                            mma16816(acc[t * 4 + 2 * g + 1], a[t], bh[1], bh[3]);
                        }
                        if (NTERM == 2) {
                            uint32_t bl[4];
                            ldm4(ba + 8192, bl);
#pragma unroll
                            for (int t = 0; t < 4; t++) {
                                mma16816(acc[t * 4 + 2 * g],     a[t], bl[0], bl[2]);
                                mma16816(acc[t * 4 + 2 * g + 1], a[t], bl[1], bl[3]);
                            }
                        }
                    }
                }
            } else {
                // ---- warp tile m32 x n32 (TM=4) ----
                int ph0 = (wm + tapy) * IWP + ar + tapx + (4 - PAD);
                int ph1 = ph0 + 16;
                uint32_t a0r = sb + OFF_A + (uint32_t)ph0 * 128;
                uint32_t a1r = sb + OFF_A + (uint32_t)ph1 * 128;
                int asw0 = ph0 & 7, asw1 = ph1 & 7;
#pragma unroll
                for (int kc = 0; kc < 4; kc++) {
                    int q0 = ((kc * 2 + akq) ^ asw0) << 4;
                    int q1 = ((kc * 2 + akq) ^ asw1) << 4;
                    uint32_t a0[4], a1[4];
                    ldm4(a0r + q0, a0);
                    ldm4(a1r + q1, a1);
#pragma unroll
                    for (int g = 0; g < 2; g++) {
                        int n = nh * 32 + g * 16 + br;
                        uint32_t ba = bbase + (uint32_t)n * 128
                                    + ((((kc * 2 + bkq) ^ (n & 7))) << 4);
                        uint32_t bh[4];
                        ldm4(ba, bh);
                        mma16816(acc[2 * g],     a0, bh[0], bh[2]);
                        mma16816(acc[2 * g + 1], a0, bh[1], bh[3]);
                        mma16816(acc[4 + 2 * g],     a1, bh[0], bh[2]);
                        mma16816(acc[4 + 2 * g + 1], a1, bh[1], bh[3]);
                        if (NTERM == 2) {
                            uint32_t bl[4];
                            ldm4(ba + 8192, bl);
                            mma16816(acc[2 * g],     a0, bl[0], bl[2]);
                            mma16816(acc[2 * g + 1], a0, bl[1], bl[3]);
                            mma16816(acc[4 + 2 * g],     a1, bl[0], bl[2]);
                            mma16816(acc[4 + 2 * g + 1], a1, bl[1], bl[3]);
                        }
                    }
                }
            }
        }
    }

    // ---- epilogue: transpose through smem, coalesced NCHW store ----
    __syncthreads();
    float* tb = (float*)(smem + 1024);            // [TM*32][65] fp32
    {
        int row = lane >> 2, colp = (lane & 3) * 2;
        if (TM == 8) {
#pragma unroll
            for (int t = 0; t < 4; t++) {
                int p0 = wm * 64 + t * 16 + row;
#pragma unroll
                for (int j = 0; j < 4; j++) {
                    int c = nh * 32 + j * 8 + colp;
                    tb[p0 * 65 + c]            = acc[t * 4 + j][0];
                    tb[p0 * 65 + c + 1]        = acc[t * 4 + j][1];
                    tb[(p0 + 8) * 65 + c]      = acc[t * 4 + j][2];
                    tb[(p0 + 8) * 65 + c + 1]  = acc[t * 4 + j][3];
                }
            }
        } else {
#pragma unroll
            for (int j = 0; j < 4; j++) {
                int c = nh * 32 + j * 8 + colp;
                int p0 = wm * 32 + row;
                tb[p0 * 65 + c]            = acc[j][0];
                tb[p0 * 65 + c + 1]        = acc[j][1];
                tb[(p0 + 8) * 65 + c]      = acc[j][2];
                tb[(p0 + 8) * 65 + c + 1]  = acc[j][3];
                int p1 = p0 + 16;
                tb[p1 * 65 + c]            = acc[4 + j][0];
                tb[p1 * 65 + c + 1]        = acc[4 + j][1];
                tb[(p1 + 8) * 65 + c]      = acc[4 + j][2];
                tb[(p1 + 8) * 65 + c + 1]  = acc[4 + j][3];
            }
        }
    }
    __syncthreads();
    constexpr int NIT = TM * 64 / 8;
#pragma unroll 4
    for (int it = 0; it < NIT; it++) {
        int item = it * 8 + wid;
        int c = item / TM, py = item % TM;
        float v = tb[(py * 32 + lane) * 65 + c] * epi[c] + epi[64 + c];
        if (MODE == 1) v = gelu_exact(v);
        out[((size_t)(b * 64 + c) * H + (y0 + py)) * W + x0 + lane] = v;
    }
}

// ---------------- bilinear up x2 (align_corners=True) ----------------
__global__ void up2_kernel(const float* __restrict__ in, float* __restrict__ out,
                           int BC, int n)
{
    int N = 2 * n;
    size_t total = (size_t)BC * N * N;
    size_t idx = (size_t)blockIdx.x * blockDim.x + threadIdx.x;
    if (idx >= total) return;
    int xo = (int)(idx % N);
    size_t r = idx / N;
    int yo = (int)(r % N);
    int bc = (int)(r / N);
    float rr = (float)(n - 1) / (float)(N - 1);
    float sy = yo * rr; int iy0 = (int)sy; float wy = sy - (float)iy0; int iy1 = min(iy0 + 1, n - 1);
    float sx = xo * rr; int ix0 = (int)sx; float wx = sx - (float)ix0; int ix1 = min(ix0 + 1, n - 1);
    const float* p = in + (size_t)bc * n * n;
    float a = p[iy0 * n + ix0], bv = p[iy1 * n + ix0];
    float c = p[iy0 * n + ix1], d = p[iy1 * n + ix1];
    float ra = a * (1.f - wy) + bv * wy;
    float rb = c * (1.f - wy) + d * wy;
    out[idx] = ra * (1.f - wx) + rb * wx;
}

// ---------------- AP_MP(small,x) + AP_MP(x,small) at half resolution ----------------
__global__ void diff_kernel(const float* __restrict__ sm, const float* __restrict__ x,
                            float* __restrict__ out)
{
    int idx = blockIdx.x * blockDim.x + threadIdx.x;
    if (idx >= B_ * h_ * w_) return;
    int j = idx % w_;
    int t = idx / w_;
    int i = t % h_;
    int b = t / h_;
    float acc1 = 0.f, acc2 = 0.f;
    size_t base0 = ((size_t)b * 64 * H_ + 2 * i) * W_ + 2 * j;
    for (int c = 0; c < 64; c++) {
        size_t base = base0 + (size_t)c * H_ * W_;
        float2 s0 = *(const float2*)(sm + base);
        float2 s1 = *(const float2*)(sm + base + W_);
        float2 xa = *(const float2*)(x + base);
        float2 xb = *(const float2*)(x + base + W_);
        float as = 0.25f * (s0.x + s0.y + s1.x + s1.y);
        float ms = fmaxf(fmaxf(s0.x, s0.y), fmaxf(s1.x, s1.y));
        float ax = 0.25f * (xa.x + xa.y + xb.x + xb.y);
        float mx = fmaxf(fmaxf(xa.x, xa.y), fmaxf(xb.x, xb.y));
        float d1 = as - mx; acc1 += d1 * d1;
        float d2 = ax - ms; acc2 += d2 * d2;
    }
    out[idx] = sqrtf(acc1) + sqrtf(acc2);
}

// ---------------- fused: sigmoid(up2(map)) x2 -> dilate3 - map -> scale x -> bf ----------------
__global__ __launch_bounds__(256)
void fused_bf(const float* __restrict__ x, const float* __restrict__ in_map,
              const float* __restrict__ ds, float* __restrict__ bf)
{
    __shared__ float s_i[10 * 34];
    __shared__ float s_d[10 * 34];
    int tid = threadIdx.x;
    int x0 = blockIdx.x * 32, y0 = blockIdx.y * 8, b = blockIdx.z;
    const float rr = 95.f / 191.f;
    const float* pi = in_map + (size_t)b * h_ * w_;
    const float* pd = ds + (size_t)b * h_ * w_;

    for (int item = tid; item < 340; item += 256) {
        int hy = item / 34, hx = item - hy * 34;
        int gy = y0 - 1 + hy, gx = x0 - 1 + hx;
        float vi = -INFINITY, vd = -INFINITY;
        if ((unsigned)gy < (unsigned)H_ && (unsigned)gx < (unsigned)W_) {
            float sy = gy * rr; int iy0 = (int)sy; float wy = sy - (float)iy0;
            int iy1 = min(iy0 + 1, h_ - 1);
            float sx = gx * rr; int ix0 = (int)sx; float wx = sx - (float)ix0;
            int ix1 = min(ix0 + 1, w_ - 1);
            float w00 = (1.f - wy) * (1.f - wx), w01 = (1.f - wy) * wx;
            float w10 = wy * (1.f - wx),         w11 = wy * wx;
            float ui = pi[iy0 * w_ + ix0] * w00 + pi[iy0 * w_ + ix1] * w01
                     + pi[iy1 * w_ + ix0] * w10 + pi[iy1 * w_ + ix1] * w11;
            float ud = pd[iy0 * w_ + ix0] * w00 + pd[iy0 * w_ + ix1] * w01
                     + pd[iy1 * w_ + ix0] * w10 + pd[iy1 * w_ + ix1] * w11;
            vi = 1.f / (1.f + expf(-ui));
            vd = 1.f / (1.f + expf(-ud));
        }
        s_i[item] = vi; s_d[item] = vd;
    }
    __syncthreads();

    int tx = tid & 31, ty = tid >> 5;
    int ci = (ty + 1) * 34 + tx + 1;
    float mi = -INFINITY, md = -INFINITY;
#pragma unroll
    for (int dy = 0; dy < 3; dy++)
#pragma unroll
        for (int dx = 0; dx < 3; dx++) {
            int o = (ty + dy) * 34 + tx + dx;
            mi = fmaxf(mi, s_i[o]);
            md = fmaxf(md, s_d[o]);
        }
    float s = (mi - s_i[ci]) + (md - s_d[ci]) + 1.0f;
    size_t base = ((size_t)(b * 64) * H_ + (y0 + ty)) * W_ + x0 + tx;
    for (int c = 0; c < 64; c++) {
        size_t o = base + (size_t)c * H_ * W_;
        bf[o] = x[o] * s;
    }
}

// ---------------- final conv 7x7, 64 -> 1 (fp32) ----------------
__global__ __launch_bounds__(256)
void conv_out_kernel(const float* __restrict__ rin, const float* __restrict__ Wo,
                     const float* __restrict__ bo, float* __restrict__ out)
{
    __shared__ float s_in[8 * 14 * 38];
    __shared__ float s_w[8 * 49];
    int tid = threadIdx.x, tx = tid & 31, ty = tid >> 5;
    int x0 = blockIdx.x * 32, ys = blockIdx.y * 8, b = blockIdx.z;
    float acc = 0.f;
    for (int c0 = 0; c0 < 64; c0 += 8) {
        for (int idx = tid; idx < 8 * 14 * 38; idx += 256) {
            int c = idx / (14 * 38);
            int r = idx - c * (14 * 38);
            int ly = r / 38, lx = r - ly * 38;
            int gy = ys + ly - 3, gx = x0 + lx - 3;
            float v = 0.f;
            if ((unsigned)gy < (unsigned)H_ && (unsigned)gx < (unsigned)W_)
                v = rin[((size_t)(b * 64 + c0 + c) * H_ + gy) * W_ + gx];
            s_in[idx] = v;
        }
        for (int idx = tid; idx < 8 * 49; idx += 256)
            s_w[idx] = Wo[(c0 + idx / 49) * 49 + idx % 49];
        __syncthreads();
#pragma unroll
        for (int c = 0; c < 8; c++)
            for (int ky = 0; ky < 7; ky++)
#pragma unroll
                for (int kx = 0; kx < 7; kx++)
                    acc += s_w[c * 49 + ky * 7 + kx] * s_in[(c * 14 + ty + ky) * 38 + tx + kx];
        __syncthreads();
    }
    out[((size_t)b * H_ + (ys + ty)) * W_ + x0 + tx] = acc + bo[0];
}

// ---------------- launch ----------------
#define SMEM_UP (1024 + 14*40*128 + 2*8192)   // 89088  (KS=7, TM=8, NTERM=1)
#define SMEM_3  (1024 + 10*40*128 + 2*8192)   // 68608  (KS=3, TM=8, NTERM=1)

extern "C" void kernel_launch(void* const* d_in, const int* in_sizes, int n_in,
                              void* d_out, int out_size)
{
    const float* x       = (const float*)d_in[0];
    const float* small_x = (const float*)d_in[1];
    const float* in_map  = (const float*)d_in[2];
    const float* W_up  = (const float*)d_in[3];
    const float* b_up  = (const float*)d_in[4];
    const float* gup   = (const float*)d_in[5];
    const float* beup  = (const float*)d_in[6];
    const float* mup   = (const float*)d_in[7];
    const float* vup   = (const float*)d_in[8];
    const float* W_c2  = (const float*)d_in[9];
    const float* b_c2  = (const float*)d_in[10];
    const float* W_d1  = (const float*)d_in[11];
    const float* b_d1  = (const float*)d_in[12];
    const float* gd1   = (const float*)d_in[13];
    const float* bed1  = (const float*)d_in[14];
    const float* md1   = (const float*)d_in[15];
    const float* vd1   = (const float*)d_in[16];
    const float* W_d2  = (const float*)d_in[17];
    const float* b_d2  = (const float*)d_in[18];
    const float* gd2   = (const float*)d_in[19];
    const float* bed2  = (const float*)d_in[20];
    const float* md2   = (const float*)d_in[21];
    const float* vd2   = (const float*)d_in[22];
    const float* W_d3  = (const float*)d_in[23];
    const float* b_d3  = (const float*)d_in[24];
    const float* gd3   = (const float*)d_in[25];
    const float* bed3  = (const float*)d_in[26];
    const float* md3   = (const float*)d_in[27];
    const float* vd3   = (const float*)d_in[28];
    const float* W_out = (const float*)d_in[29];
    const float* b_out = (const float*)d_in[30];
    const float* beta  = (const float*)d_in[31];

    float *u, *sm, *ds, *bf, *fn, *r1, *r2;
    unsigned char* wbf;
    cudaGetSymbolAddress((void**)&u,   g_u);
    cudaGetSymbolAddress((void**)&sm,  g_small);
    cudaGetSymbolAddress((void**)&ds,  g_diffs);
    cudaGetSymbolAddress((void**)&bf,  g_bf);
    cudaGetSymbolAddress((void**)&fn,  g_fn);
    cudaGetSymbolAddress((void**)&r1,  g_r1);
    cudaGetSymbolAddress((void**)&r2,  g_r2);
    cudaGetSymbolAddress((void**)&wbf, g_wbf);

    cudaFuncSetAttribute(tconv<7,2,8,1,1,false>, cudaFuncAttributeMaxDynamicSharedMemorySize, SMEM_UP);
    cudaFuncSetAttribute(tconv<3,1,8,1,0,false>, cudaFuncAttributeMaxDynamicSharedMemorySize, SMEM_3);
    cudaFuncSetAttribute(tconv<3,2,8,1,1,true>,  cudaFuncAttributeMaxDynamicSharedMemorySize, SMEM_3);
    cudaFuncSetAttribute(tconv<3,1,8,1,1,false>, cudaFuncAttributeMaxDynamicSharedMemorySize, SMEM_3);

    // 1) fused weight prep
    prep_all<<<1024, 256>>>(W_up, W_c2, W_d1, W_d2, W_d3, wbf);

    // 2) up branch: conv7x7 (1-term fp16, m64 tiles) + BN + GELU -> bilinear up x2
    tconv<7,2,8,1,1,false><<<dim3(3, 12, 8), 256, SMEM_UP>>>(
        small_x, nullptr, (const uint4*)(wbf + (size_t)CH_UP * 16384),
        b_up, gup, beup, mup, vup, nullptr, u, h_, w_);
    up2_kernel<<<(R_ELEMS + 255) / 256, 256>>>(u, sm, B_ * 64, h_);

    // 3) uncertainty maps (fused)
    diff_kernel<<<(B_ * h_ * w_ + 255) / 256, 256>>>(sm, x, ds);
    fused_bf<<<dim3(6, 24, 8), 256>>>(x, in_map, ds, bf);

    // 4) conv chain (HMMA, fp16 1-term, m64n32 warp tiles)
    tconv<3,1,8,1,0,false><<<dim3(6, 24, 8), 256, SMEM_3>>>(
        bf, nullptr, (const uint4*)(wbf + (size_t)CH_C2 * 16384),
        b_c2, nullptr, nullptr, nullptr, nullptr, beta, fn, H_, W_);
    tconv<3,2,8,1,1,true><<<dim3(6, 24, 8), 256, SMEM_3>>>(
        sm, fn, (const uint4*)(wbf + (size_t)CH_D1 * 16384),
        b_d1, gd1, bed1, md1, vd1, nullptr, r1, H_, W_);
    tconv<3,1,8,1,1,false><<<dim3(6, 24, 8), 256, SMEM_3>>>(
        r1, nullptr, (const uint4*)(wbf + (size_t)CH_D2 * 16384),
        b_d2, gd2, bed2, md2, vd2, nullptr, r2, H_, W_);
    tconv<3,1,8,1,1,false><<<dim3(6, 24, 8), 256, SMEM_3>>>(
        r2, nullptr, (const uint4*)(wbf + (size_t)CH_D3 * 16384),
        b_d3, gd3, bed3, md3, vd3, nullptr, (float*)d_out, H_, W_);

    // 5) output head reads r from d_out, writes output_map after it
    conv_out_kernel<<<dim3(6, 24, 8), 256>>>(
        (const float*)d_out, W_out, b_out, (float*)d_out + R_ELEMS);
}

// round 9
// speedup vs baseline: 4.7065x; 1.0439x over previous
#include <cuda_runtime.h>
#include <cuda_fp16.h>
#include <math.h>
#include <stdint.h>

// ---------------- problem constants ----------------
#define B_ 8
#define H_ 192
#define W_ 192
#define h_ 96
#define w_ 96
#define R_ELEMS (B_*64*H_*W_)        // 18,874,368

// weight-chunk table (each chunk = 16KB: 8KB hi + 8KB lo, [n][k] swizzled fp16)
#define CH_UP 0      // 7x7, CG=2 -> 98 chunks
#define CH_C2 98     // 3x3, CG=1 -> 9
#define CH_D1 107    // 3x3, CG=2 -> 18
#define CH_D2 125    // 9
#define CH_D3 134    // 9
#define CH_TOTAL 143

// ---------------- scratch ----------------
__device__ __align__(16) unsigned char g_wbf[CH_TOTAL * 16384];
__device__ float g_u[B_*64*h_*w_];
__device__ float g_small[R_ELEMS];
__device__ float g_diffs[B_*h_*w_];
__device__ float g_bf[R_ELEMS];
__device__ float g_fn[R_ELEMS];
__device__ float g_r1[R_ELEMS];
__device__ float g_r2[R_ELEMS];

// ---------------- helpers ----------------
__device__ __forceinline__ uint32_t smem_u32(const void* p) {
    uint32_t a;
    asm("{ .reg .u64 t; cvta.to.shared.u64 t, %1; cvt.u32.u64 %0, t; }" : "=r"(a) : "l"(p));
    return a;
}
__device__ __forceinline__ void ldm4(uint32_t addr, uint32_t r[4]) {
    asm volatile("ldmatrix.sync.aligned.m8n8.x4.shared.b16 {%0,%1,%2,%3}, [%4];"
                 : "=r"(r[0]), "=r"(r[1]), "=r"(r[2]), "=r"(r[3]) : "r"(addr));
}
__device__ __forceinline__ void mma16816(float c[4], const uint32_t a[4],
                                         uint32_t b0, uint32_t b1) {
    asm volatile(
        "mma.sync.aligned.m16n8k16.row.col.f32.f16.f16.f32 "
        "{%0,%1,%2,%3}, {%4,%5,%6,%7}, {%8,%9}, {%0,%1,%2,%3};"
        : "+f"(c[0]), "+f"(c[1]), "+f"(c[2]), "+f"(c[3])
        : "r"(a[0]), "r"(a[1]), "r"(a[2]), "r"(a[3]), "r"(b0), "r"(b1));
}
__device__ __forceinline__ void cpa16(uint32_t saddr, const void* g) {
    asm volatile("cp.async.cg.shared.global [%0], [%1], 16;" :: "r"(saddr), "l"(g) : "memory");
}
#define CPA_COMMIT() asm volatile("cp.async.commit_group;" ::: "memory")
#define CPA_WAIT0()  asm volatile("cp.async.wait_group 0;" ::: "memory")

__device__ __forceinline__ float gelu_exact(float y) {
    return 0.5f * y * (1.0f + erff(y * 0.70710678118654752f));
}
__device__ __forceinline__ uint32_t packh2(float a, float b) {
    __half2 h = __floats2half2_rn(a, b);
    return *(uint32_t*)&h;
}

// ---------------- fused weight prep: all 5 conv weight sets ----------------
__global__ void prep_all(const float* __restrict__ W_up, const float* __restrict__ W_c2,
                         const float* __restrict__ W_d1, const float* __restrict__ W_d2,
                         const float* __restrict__ W_d3, unsigned char* __restrict__ dst)
{
    int total = CH_TOTAL * 4096;
    for (int idx = blockIdx.x * blockDim.x + threadIdx.x; idx < total;
         idx += gridDim.x * blockDim.x) {
        int chunk = idx >> 12;
        int e = idx & 4095;
        int n = e >> 6, k = e & 63;
        const float* W; int CIN, KK, local;
        if (chunk < 98)       { W = W_up; CIN = 128; KK = 49; local = chunk; }
        else if (chunk < 107) { W = W_c2; CIN = 64;  KK = 9;  local = chunk - 98; }
        else if (chunk < 125) { W = W_d1; CIN = 128; KK = 9;  local = chunk - 107; }
        else if (chunk < 134) { W = W_d2; CIN = 64;  KK = 9;  local = chunk - 125; }
        else                  { W = W_d3; CIN = 64;  KK = 9;  local = chunk - 134; }
        int CG = CIN >> 6;
        int tap = local / CG, cg = local - tap * CG;
        float w = W[((size_t)n * CIN + cg * 64 + k) * KK + tap];
        __half hb = __float2half_rn(w);
        __half lb = __float2half_rn(w - __half2float(hb));
        uint32_t off = (uint32_t)n * 128 + ((((k >> 3) ^ (n & 7))) << 4) + (k & 7) * 2;
        unsigned char* base = dst + (size_t)chunk * 16384;
        *(unsigned short*)(base + off)        = __half_as_ushort(hb);
        *(unsigned short*)(base + 8192 + off) = __half_as_ushort(lb);
    }
}

// ---------------- HMMA implicit-GEMM conv (group-staged weights) ----------------
// TM=8 rows x 32 px per CTA (M=256), 64 out chans; warp tile m64 x n32.
// B = hi-only fp16 chunks; G taps staged per sync (double-buffered groups).
// MODE 0: beta*(acc+bias)   MODE 1: gelu(bn(acc+bias))
template<int KS, int CG, int G, int MODE, bool CONCAT>
__global__ __launch_bounds__(256, 2)
void tconv(const float* __restrict__ inA, const float* __restrict__ inB,
           const uint4* __restrict__ wch, const float* __restrict__ bias,
           const float* __restrict__ gg, const float* __restrict__ bb,
           const float* __restrict__ mm, const float* __restrict__ vv,
           const float* __restrict__ betap, float* __restrict__ out,
           int H, int W)
{
    constexpr int PAD = KS / 2;
    constexpr int TM  = 8;
    constexpr int IH  = TM + KS - 1;
    constexpr int IWP = (KS == 3) ? 34 : 40;
    constexpr int NPX = IH * IWP;
    constexpr int KK  = KS * KS;
    constexpr int GPC = (KK + G - 1) / G;     // groups per cg
    constexpr int NGRP = GPC * CG;
    constexpr int OFF_A = 1024;
    constexpr int OFF_B = 1024 + NPX * 128;
    constexpr int BSTRIDE = G * 8192;

    extern __shared__ char smem_raw[];
    char* smem = (char*)(((uintptr_t)smem_raw + 1023) & ~(uintptr_t)1023);
    uint32_t sb = smem_u32(smem);
    float* epi = (float*)smem;

    int tid = threadIdx.x, wid = tid >> 5, lane = tid & 31;
    int x0 = blockIdx.x * 32, y0 = blockIdx.y * TM, b = blockIdx.z;
    size_t HW = (size_t)H * W;

    // stage flat group fg into buffer buf (hi chunks only, cp.async)
    auto stage_group = [&](int fg, int buf) {
        int cgg = fg / GPC, grp = fg - cgg * GPC;
        int t0 = grp * G;
        int cnt = (KK - t0 < G) ? (KK - t0) : G;
        for (int j = 0; j < cnt; j++) {
            int chunk = (t0 + j) * CG + cgg;
            const uint4* srcB = wch + (size_t)chunk * 1024;
            uint32_t dstB = sb + OFF_B + buf * BSTRIDE + j * 8192;
#pragma unroll
            for (int k = 0; k < 2; k++)
                cpa16(dstB + (uint32_t)(tid + k * 256) * 16, srcB + tid + k * 256);
        }
        CPA_COMMIT();
    };

    stage_group(0, 0);

    if (tid < 64) {
        int c = tid;
        float s, t;
        if (MODE == 1) {
            s = gg[c] * rsqrtf(vv[c] + 1e-5f);
            t = (bias[c] - mm[c]) * s + bb[c];
        } else {
            float bt = *betap;
            s = bt; t = bt * bias[c];
        }
        epi[c] = s; epi[64 + c] = t;
    }

    float acc[16][4];
#pragma unroll
    for (int i = 0; i < 16; i++)
#pragma unroll
        for (int j = 0; j < 4; j++) acc[i][j] = 0.f;

    int wm = wid >> 1, nh = wid & 1;
    int ar = lane & 15, akq = lane >> 4;
    int br = lane & 15, bkq = lane >> 4;

    int fg = 0;
    for (int cg = 0; cg < CG; cg++) {
        __syncthreads();   // previous cg's halo readers done

        // ---- stage halo: fp16, [pixel][chan] rows, XOR-16B swizzle ----
        {
            const float* src;
            if (CONCAT) src = (cg ? inB : inA) + (size_t)b * 64 * HW;
            else        src = inA + ((size_t)b * (CG * 64) + cg * 64) * HW;
            constexpr int TOT = NPX * 8;
            for (int item = tid; item < TOT; item += 256) {
                int o  = item / NPX;
                int ph = item - o * NPX;
                int hy = ph / IWP, hx = ph - hy * IWP;
                int gy = y0 + hy - PAD;
                int gx = x0 + hx - PAD;
                float v[8];
                if ((unsigned)gy < (unsigned)H && (unsigned)gx < (unsigned)W) {
                    const float* p = src + (size_t)(o * 8) * HW + (size_t)gy * W + gx;
#pragma unroll
                    for (int j = 0; j < 8; j++) v[j] = p[j * HW];
                } else {
#pragma unroll
                    for (int j = 0; j < 8; j++) v[j] = 0.f;
                }
                uint4 hi4;
                hi4.x = packh2(v[0], v[1]); hi4.y = packh2(v[2], v[3]);
                hi4.z = packh2(v[4], v[5]); hi4.w = packh2(v[6], v[7]);
                uint32_t ad = (uint32_t)ph * 128 + (((o ^ (ph & 7))) << 4);
                *(uint4*)(smem + OFF_A + ad) = hi4;
            }
        }

        for (int grp = 0; grp < GPC; grp++, fg++) {
            int s = fg & 1;
            CPA_WAIT0();          // this group's chunks landed (all threads' own copies)
            __syncthreads();      // halo + B visible to all; prev group readers done

            if (fg + 1 < NGRP) stage_group(fg + 1, s ^ 1);

            int t0 = grp * G;
#pragma unroll
            for (int j = 0; j < G; j++) {
                int tap = t0 + j;
                if (tap < KK) {
                    int tapy = tap / KS, tapx = tap - tapy * KS;
                    uint32_t bbase = sb + OFF_B + s * BSTRIDE + j * 8192;

                    // ---- warp tile m64 x n32 ----
#pragma unroll
                    for (int kc = 0; kc < 4; kc++) {
                        uint32_t a[4][4];
#pragma unroll
                        for (int t = 0; t < 4; t++) {
                            int y = wm * 2 + (t >> 1);
                            int ph = (y + tapy) * IWP + (t & 1) * 16 + ar + tapx;
                            ldm4(sb + OFF_A + (uint32_t)ph * 128
                                 + ((((kc * 2 + akq) ^ (ph & 7))) << 4), a[t]);
                        }
#pragma unroll
                        for (int g = 0; g < 2; g++) {
                            int n = nh * 32 + g * 16 + br;
                            uint32_t ba = bbase + (uint32_t)n * 128
                                        + ((((kc * 2 + bkq) ^ (n & 7))) << 4);
                            uint32_t bh[4];
                            ldm4(ba, bh);
#pragma unroll
                            for (int t = 0; t < 4; t++) {
                                mma16816(acc[t * 4 + 2 * g],     a[t], bh[0], bh[2]);
                                mma16816(acc[t * 4 + 2 * g + 1], a[t], bh[1], bh[3]);
                            }
                        }
                    }
                }
            }
        }
    }

    // ---- epilogue: transpose through smem, coalesced NCHW store ----
    __syncthreads();
    float* tb = (float*)(smem + 1024);            // [256][65] fp32
    {
        int row = lane >> 2, colp = (lane & 3) * 2;
#pragma unroll
        for (int t = 0; t < 4; t++) {
            int p0 = wm * 64 + t * 16 + row;
#pragma unroll
            for (int j = 0; j < 4; j++) {
                int c = nh * 32 + j * 8 + colp;
                tb[p0 * 65 + c]            = acc[t * 4 + j][0];
                tb[p0 * 65 + c + 1]        = acc[t * 4 + j][1];
                tb[(p0 + 8) * 65 + c]      = acc[t * 4 + j][2];
                tb[(p0 + 8) * 65 + c + 1]  = acc[t * 4 + j][3];
            }
        }
    }
    __syncthreads();
#pragma unroll 4
    for (int it = 0; it < 64; it++) {
        int item = it * 8 + wid;
        int c = item >> 3, py = item & 7;
        float v = tb[(py * 32 + lane) * 65 + c] * epi[c] + epi[64 + c];
        if (MODE == 1) v = gelu_exact(v);
        out[((size_t)(b * 64 + c) * H + (y0 + py)) * W + x0 + lane] = v;
    }
}

// ---------------- bilinear up x2 (align_corners=True) ----------------
__global__ void up2_kernel(const float* __restrict__ in, float* __restrict__ out,
                           int BC, int n)
{
    int N = 2 * n;
    size_t total = (size_t)BC * N * N;
    size_t idx = (size_t)blockIdx.x * blockDim.x + threadIdx.x;
    if (idx >= total) return;
    int xo = (int)(idx % N);
    size_t r = idx / N;
    int yo = (int)(r % N);
    int bc = (int)(r / N);
    float rr = (float)(n - 1) / (float)(N - 1);
    float sy = yo * rr; int iy0 = (int)sy; float wy = sy - (float)iy0; int iy1 = min(iy0 + 1, n - 1);
    float sx = xo * rr; int ix0 = (int)sx; float wx = sx - (float)ix0; int ix1 = min(ix0 + 1, n - 1);
    const float* p = in + (size_t)bc * n * n;
    float a = p[iy0 * n + ix0], bv = p[iy1 * n + ix0];
    float c = p[iy0 * n + ix1], d = p[iy1 * n + ix1];
    float ra = a * (1.f - wy) + bv * wy;
    float rb = c * (1.f - wy) + d * wy;
    out[idx] = ra * (1.f - wx) + rb * wx;
}

// ---------------- AP_MP(small,x) + AP_MP(x,small) at half resolution ----------------
__global__ void diff_kernel(const float* __restrict__ sm, const float* __restrict__ x,
                            float* __restrict__ out)
{
    int idx = blockIdx.x * blockDim.x + threadIdx.x;
    if (idx >= B_ * h_ * w_) return;
    int j = idx % w_;
    int t = idx / w_;
    int i = t % h_;
    int b = t / h_;
    float acc1 = 0.f, acc2 = 0.f;
    size_t base0 = ((size_t)b * 64 * H_ + 2 * i) * W_ + 2 * j;
    for (int c = 0; c < 64; c++) {
        size_t base = base0 + (size_t)c * H_ * W_;
        float2 s0 = *(const float2*)(sm + base);
        float2 s1 = *(const float2*)(sm + base + W_);
        float2 xa = *(const float2*)(x + base);
        float2 xb = *(const float2*)(x + base + W_);
        float as = 0.25f * (s0.x + s0.y + s1.x + s1.y);
        float ms = fmaxf(fmaxf(s0.x, s0.y), fmaxf(s1.x, s1.y));
        float ax = 0.25f * (xa.x + xa.y + xb.x + xb.y);
        float mx = fmaxf(fmaxf(xa.x, xa.y), fmaxf(xb.x, xb.y));
        float d1 = as - mx; acc1 += d1 * d1;
        float d2 = ax - ms; acc2 += d2 * d2;
    }
    out[idx] = sqrtf(acc1) + sqrtf(acc2);
}

// ---------------- fused: sigmoid(up2(map)) x2 -> dilate3 - map -> scale x -> bf ----------------
__global__ __launch_bounds__(256)
void fused_bf(const float* __restrict__ x, const float* __restrict__ in_map,
              const float* __restrict__ ds, float* __restrict__ bf)
{
    __shared__ float s_i[10 * 34];
    __shared__ float s_d[10 * 34];
    int tid = threadIdx.x;
    int x0 = blockIdx.x * 32, y0 = blockIdx.y * 8, b = blockIdx.z;
    const float rr = 95.f / 191.f;
    const float* pi = in_map + (size_t)b * h_ * w_;
    const float* pd = ds + (size_t)b * h_ * w_;

    for (int item = tid; item < 340; item += 256) {
        int hy = item / 34, hx = item - hy * 34;
        int gy = y0 - 1 + hy, gx = x0 - 1 + hx;
        float vi = -INFINITY, vd = -INFINITY;
        if ((unsigned)gy < (unsigned)H_ && (unsigned)gx < (unsigned)W_) {
            float sy = gy * rr; int iy0 = (int)sy; float wy = sy - (float)iy0;
            int iy1 = min(iy0 + 1, h_ - 1);
            float sx = gx * rr; int ix0 = (int)sx; float wx = sx - (float)ix0;
            int ix1 = min(ix0 + 1, w_ - 1);
            float w00 = (1.f - wy) * (1.f - wx), w01 = (1.f - wy) * wx;
            float w10 = wy * (1.f - wx),         w11 = wy * wx;
            float ui = pi[iy0 * w_ + ix0] * w00 + pi[iy0 * w_ + ix1] * w01
                     + pi[iy1 * w_ + ix0] * w10 + pi[iy1 * w_ + ix1] * w11;
            float ud = pd[iy0 * w_ + ix0] * w00 + pd[iy0 * w_ + ix1] * w01
                     + pd[iy1 * w_ + ix0] * w10 + pd[iy1 * w_ + ix1] * w11;
            vi = 1.f / (1.f + expf(-ui));
            vd = 1.f / (1.f + expf(-ud));
        }
        s_i[item] = vi; s_d[item] = vd;
    }
    __syncthreads();

    int tx = tid & 31, ty = tid >> 5;
    int ci = (ty + 1) * 34 + tx + 1;
    float mi = -INFINITY, md = -INFINITY;
#pragma unroll
    for (int dy = 0; dy < 3; dy++)
#pragma unroll
        for (int dx = 0; dx < 3; dx++) {
            int o = (ty + dy) * 34 + tx + dx;
            mi = fmaxf(mi, s_i[o]);
            md = fmaxf(md, s_d[o]);
        }
    float s = (mi - s_i[ci]) + (md - s_d[ci]) + 1.0f;
    size_t base = ((size_t)(b * 64) * H_ + (y0 + ty)) * W_ + x0 + tx;
    for (int c = 0; c < 64; c++) {
        size_t o = base + (size_t)c * H_ * W_;
        bf[o] = x[o] * s;
    }
}

// ---------------- final conv 7x7, 64 -> 1 (fp32) ----------------
__global__ __launch_bounds__(256)
void conv_out_kernel(const float* __restrict__ rin, const float* __restrict__ Wo,
                     const float* __restrict__ bo, float* __restrict__ out)
{
    __shared__ float s_in[8 * 14 * 38];
    __shared__ float s_w[8 * 49];
    int tid = threadIdx.x, tx = tid & 31, ty = tid >> 5;
    int x0 = blockIdx.x * 32, ys = blockIdx.y * 8, b = blockIdx.z;
    float acc = 0.f;
    for (int c0 = 0; c0 < 64; c0 += 8) {
        for (int idx = tid; idx < 8 * 14 * 38; idx += 256) {
            int c = idx / (14 * 38);
            int r = idx - c * (14 * 38);
            int ly = r / 38, lx = r - ly * 38;
            int gy = ys + ly - 3, gx = x0 + lx - 3;
            float v = 0.f;
            if ((unsigned)gy < (unsigned)H_ && (unsigned)gx < (unsigned)W_)
                v = rin[((size_t)(b * 64 + c0 + c) * H_ + gy) * W_ + gx];
            s_in[idx] = v;
        }
        for (int idx = tid; idx < 8 * 49; idx += 256)
            s_w[idx] = Wo[(c0 + idx / 49) * 49 + idx % 49];
        __syncthreads();
#pragma unroll
        for (int c = 0; c < 8; c++)
            for (int ky = 0; ky < 7; ky++)
#pragma unroll
                for (int kx = 0; kx < 7; kx++)
                    acc += s_w[c * 49 + ky * 7 + kx] * s_in[(c * 14 + ty + ky) * 38 + tx + kx];
        __syncthreads();
    }
    out[((size_t)b * H_ + (ys + ty)) * W_ + x0 + tx] = acc + bo[0];
}

// ---------------- launch ----------------
#define SMEM_UP (1024 + 14*40*128 + 2*2*8192)   // 105472  (KS=7, G=2)
#define SMEM_3  (1024 + 10*34*128 + 2*3*8192)   // 93696   (KS=3, G=3)

extern "C" void kernel_launch(void* const* d_in, const int* in_sizes, int n_in,
                              void* d_out, int out_size)
{
    const float* x       = (const float*)d_in[0];
    const float* small_x = (const float*)d_in[1];
    const float* in_map  = (const float*)d_in[2];
    const float* W_up  = (const float*)d_in[3];
    const float* b_up  = (const float*)d_in[4];
    const float* gup   = (const float*)d_in[5];
    const float* beup  = (const float*)d_in[6];
    const float* mup   = (const float*)d_in[7];
    const float* vup   = (const float*)d_in[8];
    const float* W_c2  = (const float*)d_in[9];
    const float* b_c2  = (const float*)d_in[10];
    const float* W_d1  = (const float*)d_in[11];
    const float* b_d1  = (const float*)d_in[12];
    const float* gd1   = (const float*)d_in[13];
    const float* bed1  = (const float*)d_in[14];
    const float* md1   = (const float*)d_in[15];
    const float* vd1   = (const float*)d_in[16];
    const float* W_d2  = (const float*)d_in[17];
    const float* b_d2  = (const float*)d_in[18];
    const float* gd2   = (const float*)d_in[19];
    const float* bed2  = (const float*)d_in[20];
    const float* md2   = (const float*)d_in[21];
    const float* vd2   = (const float*)d_in[22];
    const float* W_d3  = (const float*)d_in[23];
    const float* b_d3  = (const float*)d_in[24];
    const float* gd3   = (const float*)d_in[25];
    const float* bed3  = (const float*)d_in[26];
    const float* md3   = (const float*)d_in[27];
    const float* vd3   = (const float*)d_in[28];
    const float* W_out = (const float*)d_in[29];
    const float* b_out = (const float*)d_in[30];
    const float* beta  = (const float*)d_in[31];

    float *u, *sm, *ds, *bf, *fn, *r1, *r2;
    unsigned char* wbf;
    cudaGetSymbolAddress((void**)&u,   g_u);
    cudaGetSymbolAddress((void**)&sm,  g_small);
    cudaGetSymbolAddress((void**)&ds,  g_diffs);
    cudaGetSymbolAddress((void**)&bf,  g_bf);
    cudaGetSymbolAddress((void**)&fn,  g_fn);
    cudaGetSymbolAddress((void**)&r1,  g_r1);
    cudaGetSymbolAddress((void**)&r2,  g_r2);
    cudaGetSymbolAddress((void**)&wbf, g_wbf);

    cudaFuncSetAttribute(tconv<7,2,2,1,false>, cudaFuncAttributeMaxDynamicSharedMemorySize, SMEM_UP);
    cudaFuncSetAttribute(tconv<3,1,3,0,false>, cudaFuncAttributeMaxDynamicSharedMemorySize, SMEM_3);
    cudaFuncSetAttribute(tconv<3,2,3,1,true>,  cudaFuncAttributeMaxDynamicSharedMemorySize, SMEM_3);
    cudaFuncSetAttribute(tconv<3,1,3,1,false>, cudaFuncAttributeMaxDynamicSharedMemorySize, SMEM_3);

    // 1) fused weight prep
    prep_all<<<1024, 256>>>(W_up, W_c2, W_d1, W_d2, W_d3, wbf);

    // 2) up branch: conv7x7 (1-term fp16, m64 tiles) + BN + GELU -> bilinear up x2
    tconv<7,2,2,1,false><<<dim3(3, 12, 8), 256, SMEM_UP>>>(
        small_x, nullptr, (const uint4*)(wbf + (size_t)CH_UP * 16384),
        b_up, gup, beup, mup, vup, nullptr, u, h_, w_);
    up2_kernel<<<(R_ELEMS + 255) / 256, 256>>>(u, sm, B_ * 64, h_);

    // 3) uncertainty maps (fused)
    diff_kernel<<<(B_ * h_ * w_ + 255) / 256, 256>>>(sm, x, ds);
    fused_bf<<<dim3(6, 24, 8), 256>>>(x, in_map, ds, bf);

    // 4) conv chain (HMMA, fp16 1-term, group-staged weights)
    tconv<3,1,3,0,false><<<dim3(6, 24, 8), 256, SMEM_3>>>(
        bf, nullptr, (const uint4*)(wbf + (size_t)CH_C2 * 16384),
        b_c2, nullptr, nullptr, nullptr, nullptr, beta, fn, H_, W_);
    tconv<3,2,3,1,true><<<dim3(6, 24, 8), 256, SMEM_3>>>(
        sm, fn, (const uint4*)(wbf + (size_t)CH_D1 * 16384),
        b_d1, gd1, bed1, md1, vd1, nullptr, r1, H_, W_);
    tconv<3,1,3,1,false><<<dim3(6, 24, 8), 256, SMEM_3>>>(
        r1, nullptr, (const uint4*)(wbf + (size_t)CH_D2 * 16384),
        b_d2, gd2, bed2, md2, vd2, nullptr, r2, H_, W_);
    tconv<3,1,3,1,false><<<dim3(6, 24, 8), 256, SMEM_3>>>(
        r2, nullptr, (const uint4*)(wbf + (size_t)CH_D3 * 16384),
        b_d3, gd3, bed3, md3, vd3, nullptr, (float*)d_out, H_, W_);

    // 5) output head reads r from d_out, writes output_map after it
    conv_out_kernel<<<dim3(6, 24, 8), 256>>>(
        (const float*)d_out, W_out, b_out, (float*)d_out + R_ELEMS);
}

// round 10
// speedup vs baseline: 5.1688x; 1.0982x over previous
#include <cuda_runtime.h>
#include <cuda_fp16.h>
#include <math.h>
#include <stdint.h>

// ---------------- problem constants ----------------
#define B_ 8
#define H_ 192
#define W_ 192
#define h_ 96
#define w_ 96
#define R_ELEMS (B_*64*H_*W_)        // 18,874,368

// weight-chunk table (each chunk = 16KB: 8KB hi + 8KB lo, [n][k] swizzled fp16)
#define CH_UP 0      // 7x7, CG=2 -> 98 chunks
#define CH_C2 98     // 3x3, CG=1 -> 9
#define CH_D1 107    // 3x3, CG=2 -> 18
#define CH_D2 125    // 9
#define CH_D3 134    // 9
#define CH_TOTAL 143

// ---------------- scratch ----------------
__device__ __align__(16) unsigned char g_wbf[CH_TOTAL * 16384];
__device__ float g_u[B_*64*h_*w_];
__device__ float g_diffs[B_*h_*w_];
__device__ float g_smap[B_*H_*W_];
__device__ float g_fn[R_ELEMS];
__device__ float g_r1[R_ELEMS];
__device__ float g_r2[R_ELEMS];

// ---------------- helpers ----------------
__device__ __forceinline__ uint32_t smem_u32(const void* p) {
    uint32_t a;
    asm("{ .reg .u64 t; cvta.to.shared.u64 t, %1; cvt.u32.u64 %0, t; }" : "=r"(a) : "l"(p));
    return a;
}
__device__ __forceinline__ void ldm4(uint32_t addr, uint32_t r[4]) {
    asm volatile("ldmatrix.sync.aligned.m8n8.x4.shared.b16 {%0,%1,%2,%3}, [%4];"
                 : "=r"(r[0]), "=r"(r[1]), "=r"(r[2]), "=r"(r[3]) : "r"(addr));
}
__device__ __forceinline__ void mma16816(float c[4], const uint32_t a[4],
                                         uint32_t b0, uint32_t b1) {
    asm volatile(
        "mma.sync.aligned.m16n8k16.row.col.f32.f16.f16.f32 "
        "{%0,%1,%2,%3}, {%4,%5,%6,%7}, {%8,%9}, {%0,%1,%2,%3};"
        : "+f"(c[0]), "+f"(c[1]), "+f"(c[2]), "+f"(c[3])
        : "r"(a[0]), "r"(a[1]), "r"(a[2]), "r"(a[3]), "r"(b0), "r"(b1));
}
__device__ __forceinline__ void cpa16(uint32_t saddr, const void* g) {
    asm volatile("cp.async.cg.shared.global [%0], [%1], 16;" :: "r"(saddr), "l"(g) : "memory");
}
#define CPA_COMMIT() asm volatile("cp.async.commit_group;" ::: "memory")
#define CPA_WAIT0()  asm volatile("cp.async.wait_group 0;" ::: "memory")

__device__ __forceinline__ float gelu_exact(float y) {
    return 0.5f * y * (1.0f + erff(y * 0.70710678118654752f));
}
__device__ __forceinline__ uint32_t packh2(float a, float b) {
    __half2 h = __floats2half2_rn(a, b);
    return *(uint32_t*)&h;
}
// bilinear sample matching up2_kernel's exact fp32 expression order
__device__ __forceinline__ float bil96(const float* p, int iy0, int iy1, float wy,
                                       int ix0, int ix1, float wx) {
    float a = p[iy0 * 96 + ix0], b = p[iy1 * 96 + ix0];
    float c = p[iy0 * 96 + ix1], d = p[iy1 * 96 + ix1];
    float ra = a * (1.f - wy) + b * wy;
    float rb = c * (1.f - wy) + d * wy;
    return ra * (1.f - wx) + rb * wx;
}

// ---------------- fused weight prep: all 5 conv weight sets ----------------
__global__ void prep_all(const float* __restrict__ W_up, const float* __restrict__ W_c2,
                         const float* __restrict__ W_d1, const float* __restrict__ W_d2,
                         const float* __restrict__ W_d3, unsigned char* __restrict__ dst)
{
    int total = CH_TOTAL * 4096;
    for (int idx = blockIdx.x * blockDim.x + threadIdx.x; idx < total;
         idx += gridDim.x * blockDim.x) {
        int chunk = idx >> 12;
        int e = idx & 4095;
        int n = e >> 6, k = e & 63;
        const float* W; int CIN, KK, local;
        if (chunk < 98)       { W = W_up; CIN = 128; KK = 49; local = chunk; }
        else if (chunk < 107) { W = W_c2; CIN = 64;  KK = 9;  local = chunk - 98; }
        else if (chunk < 125) { W = W_d1; CIN = 128; KK = 9;  local = chunk - 107; }
        else if (chunk < 134) { W = W_d2; CIN = 64;  KK = 9;  local = chunk - 125; }
        else                  { W = W_d3; CIN = 64;  KK = 9;  local = chunk - 134; }
        int CG = CIN >> 6;
        int tap = local / CG, cg = local - tap * CG;
        float w = W[((size_t)n * CIN + cg * 64 + k) * KK + tap];
        __half hb = __float2half_rn(w);
        __half lb = __float2half_rn(w - __half2float(hb));
        uint32_t off = (uint32_t)n * 128 + ((((k >> 3) ^ (n & 7))) << 4) + (k & 7) * 2;
        unsigned char* base = dst + (size_t)chunk * 16384;
        *(unsigned short*)(base + off)        = __half_as_ushort(hb);
        *(unsigned short*)(base + 8192 + off) = __half_as_ushort(lb);
    }
}

// ---------------- HMMA implicit-GEMM conv (group-staged weights) ----------------
// TM=8 rows x 32 px per CTA (M=256), 64 out chans; warp tile m64 x n32.
// AMODE 0: input = inA[cg].  AMODE 1: input = inA * aux(smap).
// AMODE 2: cg0 = bilinear-up2(aux = u, 96x96), cg1 = inB.
// MODE 0: beta*(acc+bias)   MODE 1: gelu(bn(acc+bias))
template<int KS, int CG, int G, int MODE, int AMODE>
__global__ __launch_bounds__(256, 2)
void tconv(const float* __restrict__ inA, const float* __restrict__ inB,
           const float* __restrict__ aux,
           const uint4* __restrict__ wch, const float* __restrict__ bias,
           const float* __restrict__ gg, const float* __restrict__ bb,
           const float* __restrict__ mm, const float* __restrict__ vv,
           const float* __restrict__ betap, float* __restrict__ out,
           int H, int W)
{
    constexpr int PAD = KS / 2;
    constexpr int TM  = 8;
    constexpr int IH  = TM + KS - 1;
    constexpr int IWP = (KS == 3) ? 34 : 40;
    constexpr int NPX = IH * IWP;
    constexpr int KK  = KS * KS;
    constexpr int GPC = (KK + G - 1) / G;
    constexpr int NGRP = GPC * CG;
    constexpr int OFF_A = 1024;
    constexpr int OFF_B = 1024 + NPX * 128;
    constexpr int BSTRIDE = G * 8192;

    extern __shared__ char smem_raw[];
    char* smem = (char*)(((uintptr_t)smem_raw + 1023) & ~(uintptr_t)1023);
    uint32_t sb = smem_u32(smem);
    float* epi = (float*)smem;

    int tid = threadIdx.x, wid = tid >> 5, lane = tid & 31;
    int x0 = blockIdx.x * 32, y0 = blockIdx.y * TM, b = blockIdx.z;
    size_t HW = (size_t)H * W;

    auto stage_group = [&](int fg, int buf) {
        int cgg = fg / GPC, grp = fg - cgg * GPC;
        int t0 = grp * G;
        int cnt = (KK - t0 < G) ? (KK - t0) : G;
        for (int j = 0; j < cnt; j++) {
            int chunk = (t0 + j) * CG + cgg;
            const uint4* srcB = wch + (size_t)chunk * 1024;
            uint32_t dstB = sb + OFF_B + buf * BSTRIDE + j * 8192;
#pragma unroll
            for (int k = 0; k < 2; k++)
                cpa16(dstB + (uint32_t)(tid + k * 256) * 16, srcB + tid + k * 256);
        }
        CPA_COMMIT();
    };

    stage_group(0, 0);

    if (tid < 64) {
        int c = tid;
        float s, t;
        if (MODE == 1) {
            s = gg[c] * rsqrtf(vv[c] + 1e-5f);
            t = (bias[c] - mm[c]) * s + bb[c];
        } else {
            float bt = *betap;
            s = bt; t = bt * bias[c];
        }
        epi[c] = s; epi[64 + c] = t;
    }

    float acc[16][4];
#pragma unroll
    for (int i = 0; i < 16; i++)
#pragma unroll
        for (int j = 0; j < 4; j++) acc[i][j] = 0.f;

    int wm = wid >> 1, nh = wid & 1;
    int ar = lane & 15, akq = lane >> 4;
    int br = lane & 15, bkq = lane >> 4;

    int fg = 0;
    for (int cg = 0; cg < CG; cg++) {
        __syncthreads();

        // ---- stage halo: fp16, [pixel][chan] rows, XOR-16B swizzle ----
        {
            const float* src = nullptr;
            if (AMODE == 2) { if (cg) src = inB + (size_t)b * 64 * HW; }
            else            src = inA + ((size_t)b * (CG * 64) + cg * 64) * HW;
            constexpr int TOT = NPX * 8;
            const float rr = 95.f / 191.f;
            for (int item = tid; item < TOT; item += 256) {
                int o  = item / NPX;
                int ph = item - o * NPX;
                int hy = ph / IWP, hx = ph - hy * IWP;
                int gy = y0 + hy - PAD;
                int gx = x0 + hx - PAD;
                float v[8];
                bool inb = (unsigned)gy < (unsigned)H && (unsigned)gx < (unsigned)W;
                if (AMODE == 2 && cg == 0) {
                    if (inb) {
                        float sy = gy * rr; int iy0 = (int)sy; float wy = sy - (float)iy0;
                        int iy1 = min(iy0 + 1, 95);
                        float sx = gx * rr; int ix0 = (int)sx; float wx = sx - (float)ix0;
                        int ix1 = min(ix0 + 1, 95);
                        const float* up = aux + (size_t)(b * 64 + o * 8) * 9216;
#pragma unroll
                        for (int j = 0; j < 8; j++)
                            v[j] = bil96(up + j * 9216, iy0, iy1, wy, ix0, ix1, wx);
                    } else {
#pragma unroll
                        for (int j = 0; j < 8; j++) v[j] = 0.f;
                    }
                } else {
                    if (inb) {
                        const float* p = src + (size_t)(o * 8) * HW + (size_t)gy * W + gx;
#pragma unroll
                        for (int j = 0; j < 8; j++) v[j] = p[j * HW];
                        if (AMODE == 1) {
                            float sv = aux[(size_t)b * HW + (size_t)gy * W + gx];
#pragma unroll
                            for (int j = 0; j < 8; j++) v[j] *= sv;
                        }
                    } else {
#pragma unroll
                        for (int j = 0; j < 8; j++) v[j] = 0.f;
                    }
                }
                uint4 hi4;
                hi4.x = packh2(v[0], v[1]); hi4.y = packh2(v[2], v[3]);
                hi4.z = packh2(v[4], v[5]); hi4.w = packh2(v[6], v[7]);
                uint32_t ad = (uint32_t)ph * 128 + (((o ^ (ph & 7))) << 4);
                *(uint4*)(smem + OFF_A + ad) = hi4;
            }
        }

        for (int grp = 0; grp < GPC; grp++, fg++) {
            int s = fg & 1;
            CPA_WAIT0();
            __syncthreads();

            if (fg + 1 < NGRP) stage_group(fg + 1, s ^ 1);

            int t0 = grp * G;
#pragma unroll
            for (int j = 0; j < G; j++) {
                int tap = t0 + j;
                if (tap < KK) {
                    int tapy = tap / KS, tapx = tap - tapy * KS;
                    uint32_t bbase = sb + OFF_B + s * BSTRIDE + j * 8192;
#pragma unroll
                    for (int kc = 0; kc < 4; kc++) {
                        uint32_t a[4][4];
#pragma unroll
                        for (int t = 0; t < 4; t++) {
                            int y = wm * 2 + (t >> 1);
                            int ph = (y + tapy) * IWP + (t & 1) * 16 + ar + tapx;
                            ldm4(sb + OFF_A + (uint32_t)ph * 128
                                 + ((((kc * 2 + akq) ^ (ph & 7))) << 4), a[t]);
                        }
#pragma unroll
                        for (int g = 0; g < 2; g++) {
                            int n = nh * 32 + g * 16 + br;
                            uint32_t ba = bbase + (uint32_t)n * 128
                                        + ((((kc * 2 + bkq) ^ (n & 7))) << 4);
                            uint32_t bh[4];
                            ldm4(ba, bh);
#pragma unroll
                            for (int t = 0; t < 4; t++) {
                                mma16816(acc[t * 4 + 2 * g],     a[t], bh[0], bh[2]);
                                mma16816(acc[t * 4 + 2 * g + 1], a[t], bh[1], bh[3]);
                            }
                        }
                    }
                }
            }
        }
    }

    // ---- epilogue ----
    __syncthreads();
    float* tb = (float*)(smem + 1024);
    {
        int row = lane >> 2, colp = (lane & 3) * 2;
#pragma unroll
        for (int t = 0; t < 4; t++) {
            int p0 = wm * 64 + t * 16 + row;
#pragma unroll
            for (int j = 0; j < 4; j++) {
                int c = nh * 32 + j * 8 + colp;
                tb[p0 * 65 + c]            = acc[t * 4 + j][0];
                tb[p0 * 65 + c + 1]        = acc[t * 4 + j][1];
                tb[(p0 + 8) * 65 + c]      = acc[t * 4 + j][2];
                tb[(p0 + 8) * 65 + c + 1]  = acc[t * 4 + j][3];
            }
        }
    }
    __syncthreads();
#pragma unroll 4
    for (int it = 0; it < 64; it++) {
        int item = it * 8 + wid;
        int c = item >> 3, py = item & 7;
        float v = tb[(py * 32 + lane) * 65 + c] * epi[c] + epi[64 + c];
        if (MODE == 1) v = gelu_exact(v);
        out[((size_t)(b * 64 + c) * H + (y0 + py)) * W + x0 + lane] = v;
    }
}

// ---------------- AP_MP diff with inline up2(u) (bit-identical to up2+diff) ----------------
__global__ void diff_kernel(const float* __restrict__ u, const float* __restrict__ x,
                            float* __restrict__ out)
{
    int idx = blockIdx.x * blockDim.x + threadIdx.x;
    if (idx >= B_ * h_ * w_) return;
    int j = idx % w_;
    int t = idx / w_;
    int i = t % h_;
    int b = t / h_;
    const float rr = 95.f / 191.f;
    float syA = (2 * i) * rr;     int iyA0 = (int)syA; float wyA = syA - (float)iyA0; int iyA1 = min(iyA0 + 1, 95);
    float syB = (2 * i + 1) * rr; int iyB0 = (int)syB; float wyB = syB - (float)iyB0; int iyB1 = min(iyB0 + 1, 95);
    float sxA = (2 * j) * rr;     int ixA0 = (int)sxA; float wxA = sxA - (float)ixA0; int ixA1 = min(ixA0 + 1, 95);
    float sxB = (2 * j + 1) * rr; int ixB0 = (int)sxB; float wxB = sxB - (float)ixB0; int ixB1 = min(ixB0 + 1, 95);

    float acc1 = 0.f, acc2 = 0.f;
    size_t base0 = ((size_t)b * 64 * H_ + 2 * i) * W_ + 2 * j;
    for (int c = 0; c < 64; c++) {
        const float* uc = u + (size_t)(b * 64 + c) * 9216;
        float s00 = bil96(uc, iyA0, iyA1, wyA, ixA0, ixA1, wxA);
        float s01 = bil96(uc, iyA0, iyA1, wyA, ixB0, ixB1, wxB);
        float s10 = bil96(uc, iyB0, iyB1, wyB, ixA0, ixA1, wxA);
        float s11 = bil96(uc, iyB0, iyB1, wyB, ixB0, ixB1, wxB);
        float as = 0.25f * (s00 + s01 + s10 + s11);
        float ms = fmaxf(fmaxf(s00, s01), fmaxf(s10, s11));

        size_t base = base0 + (size_t)c * H_ * W_;
        float2 xa = *(const float2*)(x + base);
        float2 xb = *(const float2*)(x + base + W_);
        float ax = 0.25f * (xa.x + xa.y + xb.x + xb.y);
        float mx = fmaxf(fmaxf(xa.x, xa.y), fmaxf(xb.x, xb.y));
        float d1 = as - mx; acc1 += d1 * d1;
        float d2 = ax - ms; acc2 += d2 * d2;
    }
    out[idx] = sqrtf(acc1) + sqrtf(acc2);
}

// ---------------- smap: sigmoid(up2(map)) x2 -> (dilate3-map)+(dilate3-map)+1 ----------------
__global__ __launch_bounds__(256)
void smap_kernel(const float* __restrict__ in_map, const float* __restrict__ ds,
                 float* __restrict__ smap)
{
    __shared__ float s_i[10 * 34];
    __shared__ float s_d[10 * 34];
    int tid = threadIdx.x;
    int x0 = blockIdx.x * 32, y0 = blockIdx.y * 8, b = blockIdx.z;
    const float rr = 95.f / 191.f;
    const float* pi = in_map + (size_t)b * h_ * w_;
    const float* pd = ds + (size_t)b * h_ * w_;

    for (int item = tid; item < 340; item += 256) {
        int hy = item / 34, hx = item - hy * 34;
        int gy = y0 - 1 + hy, gx = x0 - 1 + hx;
        float vi = -INFINITY, vd = -INFINITY;
        if ((unsigned)gy < (unsigned)H_ && (unsigned)gx < (unsigned)W_) {
            float sy = gy * rr; int iy0 = (int)sy; float wy = sy - (float)iy0;
            int iy1 = min(iy0 + 1, h_ - 1);
            float sx = gx * rr; int ix0 = (int)sx; float wx = sx - (float)ix0;
            int ix1 = min(ix0 + 1, w_ - 1);
            float w00 = (1.f - wy) * (1.f - wx), w01 = (1.f - wy) * wx;
            float w10 = wy * (1.f - wx),         w11 = wy * wx;
            float ui = pi[iy0 * w_ + ix0] * w00 + pi[iy0 * w_ + ix1] * w01
                     + pi[iy1 * w_ + ix0] * w10 + pi[iy1 * w_ + ix1] * w11;
            float ud = pd[iy0 * w_ + ix0] * w00 + pd[iy0 * w_ + ix1] * w01
                     + pd[iy1 * w_ + ix0] * w10 + pd[iy1 * w_ + ix1] * w11;
            vi = 1.f / (1.f + expf(-ui));
            vd = 1.f / (1.f + expf(-ud));
        }
        s_i[item] = vi; s_d[item] = vd;
    }
    __syncthreads();

    int tx = tid & 31, ty = tid >> 5;
    int ci = (ty + 1) * 34 + tx + 1;
    float mi = -INFINITY, md = -INFINITY;
#pragma unroll
    for (int dy = 0; dy < 3; dy++)
#pragma unroll
        for (int dx = 0; dx < 3; dx++) {
            int o = (ty + dy) * 34 + tx + dx;
            mi = fmaxf(mi, s_i[o]);
            md = fmaxf(md, s_d[o]);
        }
    float s = (mi - s_i[ci]) + (md - s_d[ci]) + 1.0f;
    smap[((size_t)b * H_ + (y0 + ty)) * W_ + x0 + tx] = s;
}

// ---------------- final conv 7x7, 64 -> 1 (fp32), 4 px/thread ----------------
__global__ __launch_bounds__(256)
void conv_out_kernel(const float* __restrict__ rin, const float* __restrict__ Wo,
                     const float* __restrict__ bo, float* __restrict__ out)
{
    extern __shared__ float s_in[];            // 8 x 22 x 70
    __shared__ float s_w[8 * 49];
    int tid = threadIdx.x, tx = tid & 31, ty = tid >> 5;
    int x0 = blockIdx.x * 64, ys = blockIdx.y * 16, b = blockIdx.z;
    float a0 = 0.f, a1 = 0.f, a2 = 0.f, a3 = 0.f;
    for (int c0 = 0; c0 < 64; c0 += 8) {
        __syncthreads();
        for (int idx = tid; idx < 8 * 22 * 70; idx += 256) {
            int c = idx / (22 * 70);
            int r = idx - c * (22 * 70);
            int ly = r / 70, lx = r - ly * 70;
            int gy = ys + ly - 3, gx = x0 + lx - 3;
            float v = 0.f;
            if ((unsigned)gy < (unsigned)H_ && (unsigned)gx < (unsigned)W_)
                v = rin[((size_t)(b * 64 + c0 + c) * H_ + gy) * W_ + gx];
            s_in[idx] = v;
        }
        for (int idx = tid; idx < 8 * 49; idx += 256)
            s_w[idx] = Wo[(c0 + idx / 49) * 49 + idx % 49];
        __syncthreads();
#pragma unroll
        for (int c = 0; c < 8; c++)
            for (int ky = 0; ky < 7; ky++) {
                int r0 = (c * 22 + ty + ky) * 70;
                int r1 = (c * 22 + ty + 8 + ky) * 70;
#pragma unroll
                for (int kx = 0; kx < 7; kx++) {
                    float w = s_w[c * 49 + ky * 7 + kx];
                    a0 += w * s_in[r0 + tx + kx];
                    a1 += w * s_in[r0 + tx + 32 + kx];
                    a2 += w * s_in[r1 + tx + kx];
                    a3 += w * s_in[r1 + tx + 32 + kx];
                }
            }
    }
    float bv = bo[0];
    out[((size_t)b * H_ + (ys + ty))     * W_ + x0 + tx]      = a0 + bv;
    out[((size_t)b * H_ + (ys + ty))     * W_ + x0 + tx + 32] = a1 + bv;
    out[((size_t)b * H_ + (ys + ty + 8)) * W_ + x0 + tx]      = a2 + bv;
    out[((size_t)b * H_ + (ys + ty + 8)) * W_ + x0 + tx + 32] = a3 + bv;
}

// ---------------- launch ----------------
#define SMEM_UP (1024 + 14*40*128 + 2*2*8192)   // 105472  (KS=7, G=2)
#define SMEM_3  (1024 + 10*34*128 + 2*3*8192)   // 93696   (KS=3, G=3)
#define SMEM_CO (8*22*70*4)                     // 49280

extern "C" void kernel_launch(void* const* d_in, const int* in_sizes, int n_in,
                              void* d_out, int out_size)
{
    const float* x       = (const float*)d_in[0];
    const float* small_x = (const float*)d_in[1];
    const float* in_map  = (const float*)d_in[2];
    const float* W_up  = (const float*)d_in[3];
    const float* b_up  = (const float*)d_in[4];
    const float* gup   = (const float*)d_in[5];
    const float* beup  = (const float*)d_in[6];
    const float* mup   = (const float*)d_in[7];
    const float* vup   = (const float*)d_in[8];
    const float* W_c2  = (const float*)d_in[9];
    const float* b_c2  = (const float*)d_in[10];
    const float* W_d1  = (const float*)d_in[11];
    const float* b_d1  = (const float*)d_in[12];
    const float* gd1   = (const float*)d_in[13];
    const float* bed1  = (const float*)d_in[14];
    const float* md1   = (const float*)d_in[15];
    const float* vd1   = (const float*)d_in[16];
    const float* W_d2  = (const float*)d_in[17];
    const float* b_d2  = (const float*)d_in[18];
    const float* gd2   = (const float*)d_in[19];
    const float* bed2  = (const float*)d_in[20];
    const float* md2   = (const float*)d_in[21];
    const float* vd2   = (const float*)d_in[22];
    const float* W_d3  = (const float*)d_in[23];
    const float* b_d3  = (const float*)d_in[24];
    const float* gd3   = (const float*)d_in[25];
    const float* bed3  = (const float*)d_in[26];
    const float* md3   = (const float*)d_in[27];
    const float* vd3   = (const float*)d_in[28];
    const float* W_out = (const float*)d_in[29];
    const float* b_out = (const float*)d_in[30];
    const float* beta  = (const float*)d_in[31];

    float *u, *ds, *sp, *fn, *r1, *r2;
    unsigned char* wbf;
    cudaGetSymbolAddress((void**)&u,   g_u);
    cudaGetSymbolAddress((void**)&ds,  g_diffs);
    cudaGetSymbolAddress((void**)&sp,  g_smap);
    cudaGetSymbolAddress((void**)&fn,  g_fn);
    cudaGetSymbolAddress((void**)&r1,  g_r1);
    cudaGetSymbolAddress((void**)&r2,  g_r2);
    cudaGetSymbolAddress((void**)&wbf, g_wbf);

    cudaFuncSetAttribute(tconv<7,2,2,1,0>, cudaFuncAttributeMaxDynamicSharedMemorySize, SMEM_UP);
    cudaFuncSetAttribute(tconv<3,1,3,0,1>, cudaFuncAttributeMaxDynamicSharedMemorySize, SMEM_3);
    cudaFuncSetAttribute(tconv<3,2,3,1,2>, cudaFuncAttributeMaxDynamicSharedMemorySize, SMEM_3);
    cudaFuncSetAttribute(tconv<3,1,3,1,0>, cudaFuncAttributeMaxDynamicSharedMemorySize, SMEM_3);
    cudaFuncSetAttribute(conv_out_kernel,  cudaFuncAttributeMaxDynamicSharedMemorySize, SMEM_CO);

    // 1) fused weight prep
    prep_all<<<1024, 256>>>(W_up, W_c2, W_d1, W_d2, W_d3, wbf);

    // 2) up branch: conv7x7 + BN + GELU -> u (96x96); up2 now fused downstream
    tconv<7,2,2,1,0><<<dim3(3, 12, 8), 256, SMEM_UP>>>(
        small_x, nullptr, nullptr, (const uint4*)(wbf + (size_t)CH_UP * 16384),
        b_up, gup, beup, mup, vup, nullptr, u, h_, w_);

    // 3) uncertainty maps: diff reads u directly; smap = dilation map
    diff_kernel<<<(B_ * h_ * w_ + 255) / 256, 256>>>(u, x, ds);
    smap_kernel<<<dim3(6, 24, 8), 256>>>(in_map, ds, sp);

    // 4) conv chain (HMMA fp16, group-staged weights)
    tconv<3,1,3,0,1><<<dim3(6, 24, 8), 256, SMEM_3>>>(
        x, nullptr, sp, (const uint4*)(wbf + (size_t)CH_C2 * 16384),
        b_c2, nullptr, nullptr, nullptr, nullptr, beta, fn, H_, W_);
    tconv<3,2,3,1,2><<<dim3(6, 24, 8), 256, SMEM_3>>>(
        nullptr, fn, u, (const uint4*)(wbf + (size_t)CH_D1 * 16384),
        b_d1, gd1, bed1, md1, vd1, nullptr, r1, H_, W_);
    tconv<3,1,3,1,0><<<dim3(6, 24, 8), 256, SMEM_3>>>(
        r1, nullptr, nullptr, (const uint4*)(wbf + (size_t)CH_D2 * 16384),
        b_d2, gd2, bed2, md2, vd2, nullptr, r2, H_, W_);
    tconv<3,1,3,1,0><<<dim3(6, 24, 8), 256, SMEM_3>>>(
        r2, nullptr, nullptr, (const uint4*)(wbf + (size_t)CH_D3 * 16384),
        b_d3, gd3, bed3, md3, vd3, nullptr, (float*)d_out, H_, W_);

    // 5) output head (4 px/thread, single wave)
    conv_out_kernel<<<dim3(3, 12, 8), 256, SMEM_CO>>>(
        (const float*)d_out, W_out, b_out, (float*)d_out + R_ELEMS);
}

// round 11
// speedup vs baseline: 5.5399x; 1.0718x over previous
#include <cuda_runtime.h>
#include <cuda_fp16.h>
#include <math.h>
#include <stdint.h>

// ---------------- problem constants ----------------
#define B_ 8
#define H_ 192
#define W_ 192
#define h_ 96
#define w_ 96
#define R_ELEMS (B_*64*H_*W_)        // 18,874,368

// weight-chunk table (each chunk = 16KB: 8KB hi + 8KB lo, [n][k] swizzled fp16)
#define CH_UP 0      // 7x7, CG=2 -> 98 chunks
#define CH_C2 98     // 3x3, CG=1 -> 9
#define CH_D1 107    // 3x3, CG=2 -> 18
#define CH_D2 125    // 9
#define CH_D3 134    // 9
#define CH_TOTAL 143

// ---------------- scratch ----------------
__device__ __align__(16) unsigned char g_wbf[CH_TOTAL * 16384];
__device__ float g_u[B_*64*h_*w_];
__device__ float g_diffs[B_*h_*w_];
__device__ float g_smap[B_*H_*W_];
__device__ __align__(16) __half g_fn16[R_ELEMS];   // NHWC fp16
__device__ __align__(16) __half g_r116[R_ELEMS];   // NHWC fp16
__device__ __align__(16) __half g_r216[R_ELEMS];   // NHWC fp16

// ---------------- helpers ----------------
__device__ __forceinline__ uint32_t smem_u32(const void* p) {
    uint32_t a;
    asm("{ .reg .u64 t; cvta.to.shared.u64 t, %1; cvt.u32.u64 %0, t; }" : "=r"(a) : "l"(p));
    return a;
}
__device__ __forceinline__ void ldm4(uint32_t addr, uint32_t r[4]) {
    asm volatile("ldmatrix.sync.aligned.m8n8.x4.shared.b16 {%0,%1,%2,%3}, [%4];"
                 : "=r"(r[0]), "=r"(r[1]), "=r"(r[2]), "=r"(r[3]) : "r"(addr));
}
__device__ __forceinline__ void mma16816(float c[4], const uint32_t a[4],
                                         uint32_t b0, uint32_t b1) {
    asm volatile(
        "mma.sync.aligned.m16n8k16.row.col.f32.f16.f16.f32 "
        "{%0,%1,%2,%3}, {%4,%5,%6,%7}, {%8,%9}, {%0,%1,%2,%3};"
        : "+f"(c[0]), "+f"(c[1]), "+f"(c[2]), "+f"(c[3])
        : "r"(a[0]), "r"(a[1]), "r"(a[2]), "r"(a[3]), "r"(b0), "r"(b1));
}
__device__ __forceinline__ void cpa16(uint32_t saddr, const void* g) {
    asm volatile("cp.async.cg.shared.global [%0], [%1], 16;" :: "r"(saddr), "l"(g) : "memory");
}
#define CPA_COMMIT() asm volatile("cp.async.commit_group;" ::: "memory")
#define CPA_WAIT0()  asm volatile("cp.async.wait_group 0;" ::: "memory")

__device__ __forceinline__ float gelu_exact(float y) {
    return 0.5f * y * (1.0f + erff(y * 0.70710678118654752f));
}
__device__ __forceinline__ uint32_t packh2(float a, float b) {
    __half2 h = __floats2half2_rn(a, b);
    return *(uint32_t*)&h;
}
// bilinear sample matching the original up2_kernel's exact fp32 expression order
__device__ __forceinline__ float bil96(const float* p, int iy0, int iy1, float wy,
                                       int ix0, int ix1, float wx) {
    float a = p[iy0 * 96 + ix0], b = p[iy1 * 96 + ix0];
    float c = p[iy0 * 96 + ix1], d = p[iy1 * 96 + ix1];
    float ra = a * (1.f - wy) + b * wy;
    float rb = c * (1.f - wy) + d * wy;
    return ra * (1.f - wx) + rb * wx;
}

// ---------------- fused weight prep: all 5 conv weight sets ----------------
__global__ void prep_all(const float* __restrict__ W_up, const float* __restrict__ W_c2,
                         const float* __restrict__ W_d1, const float* __restrict__ W_d2,
                         const float* __restrict__ W_d3, unsigned char* __restrict__ dst)
{
    int total = CH_TOTAL * 4096;
    for (int idx = blockIdx.x * blockDim.x + threadIdx.x; idx < total;
         idx += gridDim.x * blockDim.x) {
        int chunk = idx >> 12;
        int e = idx & 4095;
        int n = e >> 6, k = e & 63;
        const float* W; int CIN, KK, local;
        if (chunk < 98)       { W = W_up; CIN = 128; KK = 49; local = chunk; }
        else if (chunk < 107) { W = W_c2; CIN = 64;  KK = 9;  local = chunk - 98; }
        else if (chunk < 125) { W = W_d1; CIN = 128; KK = 9;  local = chunk - 107; }
        else if (chunk < 134) { W = W_d2; CIN = 64;  KK = 9;  local = chunk - 125; }
        else                  { W = W_d3; CIN = 64;  KK = 9;  local = chunk - 134; }
        int CG = CIN >> 6;
        int tap = local / CG, cg = local - tap * CG;
        float w = W[((size_t)n * CIN + cg * 64 + k) * KK + tap];
        __half hb = __float2half_rn(w);
        __half lb = __float2half_rn(w - __half2float(hb));
        uint32_t off = (uint32_t)n * 128 + ((((k >> 3) ^ (n & 7))) << 4) + (k & 7) * 2;
        unsigned char* base = dst + (size_t)chunk * 16384;
        *(unsigned short*)(base + off)        = __half_as_ushort(hb);
        *(unsigned short*)(base + 8192 + off) = __half_as_ushort(lb);
    }
}

// ---------------- HMMA implicit-GEMM conv (group-staged weights) ----------------
// TM=8 rows x 32 px per CTA (M=256), 64 out chans; warp tile m64 x n32.
// AMODE 0: input = inA (fp32 NCHW).  AMODE 1: inA * aux(smap).
// AMODE 2: cg0 = bilinear-up2(aux = u), cg1 = inH (fp16 NHWC).
// AMODE 3: input = inH (fp16 NHWC).
// MODE 0: beta*(acc+bias)   MODE 1: gelu(bn(acc+bias))
// OUTF 0: fp32 NCHW (outF)  OUTF 1: fp16 NHWC (outH)
template<int KS, int CG, int G, int MODE, int AMODE, int OUTF>
__global__ __launch_bounds__(256, 2)
void tconv(const float* __restrict__ inA, const __half* __restrict__ inH,
           const float* __restrict__ aux,
           const uint4* __restrict__ wch, const float* __restrict__ bias,
           const float* __restrict__ gg, const float* __restrict__ bb,
           const float* __restrict__ mm, const float* __restrict__ vv,
           const float* __restrict__ betap,
           float* __restrict__ outF, __half* __restrict__ outH,
           int H, int W)
{
    constexpr int PAD = KS / 2;
    constexpr int TM  = 8;
    constexpr int IH  = TM + KS - 1;
    constexpr int IWP = (KS == 3) ? 34 : 40;
    constexpr int NPX = IH * IWP;
    constexpr int KK  = KS * KS;
    constexpr int GPC = (KK + G - 1) / G;
    constexpr int NGRP = GPC * CG;
    constexpr int OFF_A = 1024;
    constexpr int OFF_B = 1024 + NPX * 128;
    constexpr int BSTRIDE = G * 8192;

    extern __shared__ char smem_raw[];
    char* smem = (char*)(((uintptr_t)smem_raw + 1023) & ~(uintptr_t)1023);
    uint32_t sb = smem_u32(smem);
    float* epi = (float*)smem;

    int tid = threadIdx.x, wid = tid >> 5, lane = tid & 31;
    int x0 = blockIdx.x * 32, y0 = blockIdx.y * TM, b = blockIdx.z;
    size_t HW = (size_t)H * W;

    auto stage_group = [&](int fg, int buf) {
        int cgg = fg / GPC, grp = fg - cgg * GPC;
        int t0 = grp * G;
        int cnt = (KK - t0 < G) ? (KK - t0) : G;
        for (int j = 0; j < cnt; j++) {
            int chunk = (t0 + j) * CG + cgg;
            const uint4* srcB = wch + (size_t)chunk * 1024;
            uint32_t dstB = sb + OFF_B + buf * BSTRIDE + j * 8192;
#pragma unroll
            for (int k = 0; k < 2; k++)
                cpa16(dstB + (uint32_t)(tid + k * 256) * 16, srcB + tid + k * 256);
        }
        CPA_COMMIT();
    };

    stage_group(0, 0);

    if (tid < 64) {
        int c = tid;
        float s, t;
        if (MODE == 1) {
            s = gg[c] * rsqrtf(vv[c] + 1e-5f);
            t = (bias[c] - mm[c]) * s + bb[c];
        } else {
            float bt = *betap;
            s = bt; t = bt * bias[c];
        }
        epi[c] = s; epi[64 + c] = t;
    }

    float acc[16][4];
#pragma unroll
    for (int i = 0; i < 16; i++)
#pragma unroll
        for (int j = 0; j < 4; j++) acc[i][j] = 0.f;

    int wm = wid >> 1, nh = wid & 1;
    int ar = lane & 15, akq = lane >> 4;
    int br = lane & 15, bkq = lane >> 4;

    int fg = 0;
    for (int cg = 0; cg < CG; cg++) {
        __syncthreads();

        // ---- stage halo ----
        constexpr int TOT = NPX * 8;
        bool h16 = (AMODE == 3) || (AMODE == 2 && CG == 2);
        if (h16 && (AMODE == 3 || cg == 1)) {
            // fp16 NHWC: 1 LDG.128 + 1 STS.128 per item, o-fastest for coalescing
            for (int item = tid; item < TOT; item += 256) {
                int ph = item >> 3, o = item & 7;
                int hy = ph / IWP, hx = ph - hy * IWP;
                int gy = y0 + hy - PAD;
                int gx = x0 + hx - PAD;
                uint4 val = make_uint4(0, 0, 0, 0);
                if ((unsigned)gy < (unsigned)H && (unsigned)gx < (unsigned)W)
                    val = *(const uint4*)(inH + ((((size_t)b * H + gy) * W + gx) << 6) + o * 8);
                uint32_t ad = (uint32_t)ph * 128 + (((o ^ (ph & 7))) << 4);
                *(uint4*)(smem + OFF_A + ad) = val;
            }
        } else {
            const float* src = nullptr;
            if (AMODE != 2) src = inA + ((size_t)b * (CG * 64) + cg * 64) * HW;
            const float rr = 95.f / 191.f;
            for (int item = tid; item < TOT; item += 256) {
                int o  = item / NPX;
                int ph = item - o * NPX;
                int hy = ph / IWP, hx = ph - hy * IWP;
                int gy = y0 + hy - PAD;
                int gx = x0 + hx - PAD;
                float v[8];
                bool inb = (unsigned)gy < (unsigned)H && (unsigned)gx < (unsigned)W;
                if (AMODE == 2) {
                    if (inb) {
                        float sy = gy * rr; int iy0 = (int)sy; float wy = sy - (float)iy0;
                        int iy1 = min(iy0 + 1, 95);
                        float sx = gx * rr; int ix0 = (int)sx; float wx = sx - (float)ix0;
                        int ix1 = min(ix0 + 1, 95);
                        const float* up = aux + (size_t)(b * 64 + o * 8) * 9216;
#pragma unroll
                        for (int j = 0; j < 8; j++)
                            v[j] = bil96(up + j * 9216, iy0, iy1, wy, ix0, ix1, wx);
                    } else {
#pragma unroll
                        for (int j = 0; j < 8; j++) v[j] = 0.f;
                    }
                } else {
                    if (inb) {
                        const float* p = src + (size_t)(o * 8) * HW + (size_t)gy * W + gx;
#pragma unroll
                        for (int j = 0; j < 8; j++) v[j] = p[j * HW];
                        if (AMODE == 1) {
                            float sv = aux[(size_t)b * HW + (size_t)gy * W + gx];
#pragma unroll
                            for (int j = 0; j < 8; j++) v[j] *= sv;
                        }
                    } else {
#pragma unroll
                        for (int j = 0; j < 8; j++) v[j] = 0.f;
                    }
                }
                uint4 hi4;
                hi4.x = packh2(v[0], v[1]); hi4.y = packh2(v[2], v[3]);
                hi4.z = packh2(v[4], v[5]); hi4.w = packh2(v[6], v[7]);
                uint32_t ad = (uint32_t)ph * 128 + (((o ^ (ph & 7))) << 4);
                *(uint4*)(smem + OFF_A + ad) = hi4;
            }
        }

        for (int grp = 0; grp < GPC; grp++, fg++) {
            int s = fg & 1;
            CPA_WAIT0();
            __syncthreads();

            if (fg + 1 < NGRP) stage_group(fg + 1, s ^ 1);

            int t0 = grp * G;
#pragma unroll
            for (int j = 0; j < G; j++) {
                int tap = t0 + j;
                if (tap < KK) {
                    int tapy = tap / KS, tapx = tap - tapy * KS;
                    uint32_t bbase = sb + OFF_B + s * BSTRIDE + j * 8192;
#pragma unroll
                    for (int kc = 0; kc < 4; kc++) {
                        uint32_t a[4][4];
#pragma unroll
                        for (int t = 0; t < 4; t++) {
                            int y = wm * 2 + (t >> 1);
                            int ph = (y + tapy) * IWP + (t & 1) * 16 + ar + tapx;
                            ldm4(sb + OFF_A + (uint32_t)ph * 128
                                 + ((((kc * 2 + akq) ^ (ph & 7))) << 4), a[t]);
                        }
#pragma unroll
                        for (int g = 0; g < 2; g++) {
                            int n = nh * 32 + g * 16 + br;
                            uint32_t ba = bbase + (uint32_t)n * 128
                                        + ((((kc * 2 + bkq) ^ (n & 7))) << 4);
                            uint32_t bh[4];
                            ldm4(ba, bh);
#pragma unroll
                            for (int t = 0; t < 4; t++) {
                                mma16816(acc[t * 4 + 2 * g],     a[t], bh[0], bh[2]);
                                mma16816(acc[t * 4 + 2 * g + 1], a[t], bh[1], bh[3]);
                            }
                        }
                    }
                }
            }
        }
    }

    // ---- epilogue ----
    __syncthreads();
    float* tb = (float*)(smem + 1024);
    {
        int row = lane >> 2, colp = (lane & 3) * 2;
#pragma unroll
        for (int t = 0; t < 4; t++) {
            int p0 = wm * 64 + t * 16 + row;
#pragma unroll
            for (int j = 0; j < 4; j++) {
                int c = nh * 32 + j * 8 + colp;
                tb[p0 * 65 + c]            = acc[t * 4 + j][0];
                tb[p0 * 65 + c + 1]        = acc[t * 4 + j][1];
                tb[(p0 + 8) * 65 + c]      = acc[t * 4 + j][2];
                tb[(p0 + 8) * 65 + c + 1]  = acc[t * 4 + j][3];
            }
        }
    }
    __syncthreads();
    if (OUTF == 0) {
#pragma unroll 4
        for (int it = 0; it < 64; it++) {
            int item = it * 8 + wid;
            int c = item >> 3, py = item & 7;
            float v = tb[(py * 32 + lane) * 65 + c] * epi[c] + epi[64 + c];
            if (MODE == 1) v = gelu_exact(v);
            outF[((size_t)(b * 64 + c) * H + (y0 + py)) * W + x0 + lane] = v;
        }
    } else {
        // fp16 NHWC: 8 threads per pixel (8 chans each), 128B/pixel contiguous
#pragma unroll
        for (int it = 0; it < 8; it++) {
            int item = it * 256 + tid;          // 2048 items
            int px = item >> 3, grp = item & 7;
            float vs[8];
#pragma unroll
            for (int j = 0; j < 8; j++) {
                int c = grp * 8 + j;
                float v = tb[px * 65 + c] * epi[c] + epi[64 + c];
                if (MODE == 1) v = gelu_exact(v);
                vs[j] = v;
            }
            uint4 pk;
            pk.x = packh2(vs[0], vs[1]); pk.y = packh2(vs[2], vs[3]);
            pk.z = packh2(vs[4], vs[5]); pk.w = packh2(vs[6], vs[7]);
            int py = px >> 5, xx = px & 31;
            *(uint4*)(outH + ((((size_t)b * H + y0 + py) * W + x0 + xx) << 6) + grp * 8) = pk;
        }
    }
}

// ---------------- AP_MP diff with inline up2(u) ----------------
__global__ void diff_kernel(const float* __restrict__ u, const float* __restrict__ x,
                            float* __restrict__ out)
{
    int idx = blockIdx.x * blockDim.x + threadIdx.x;
    if (idx >= B_ * h_ * w_) return;
    int j = idx % w_;
    int t = idx / w_;
    int i = t % h_;
    int b = t / h_;
    const float rr = 95.f / 191.f;
    float syA = (2 * i) * rr;     int iyA0 = (int)syA; float wyA = syA - (float)iyA0; int iyA1 = min(iyA0 + 1, 95);
    float syB = (2 * i + 1) * rr; int iyB0 = (int)syB; float wyB = syB - (float)iyB0; int iyB1 = min(iyB0 + 1, 95);
    float sxA = (2 * j) * rr;     int ixA0 = (int)sxA; float wxA = sxA - (float)ixA0; int ixA1 = min(ixA0 + 1, 95);
    float sxB = (2 * j + 1) * rr; int ixB0 = (int)sxB; float wxB = sxB - (float)ixB0; int ixB1 = min(ixB0 + 1, 95);

    float acc1 = 0.f, acc2 = 0.f;
    size_t base0 = ((size_t)b * 64 * H_ + 2 * i) * W_ + 2 * j;
    for (int c = 0; c < 64; c++) {
        const float* uc = u + (size_t)(b * 64 + c) * 9216;
        float s00 = bil96(uc, iyA0, iyA1, wyA, ixA0, ixA1, wxA);
        float s01 = bil96(uc, iyA0, iyA1, wyA, ixB0, ixB1, wxB);
        float s10 = bil96(uc, iyB0, iyB1, wyB, ixA0, ixA1, wxA);
        float s11 = bil96(uc, iyB0, iyB1, wyB, ixB0, ixB1, wxB);
        float as = 0.25f * (s00 + s01 + s10 + s11);
        float ms = fmaxf(fmaxf(s00, s01), fmaxf(s10, s11));

        size_t base = base0 + (size_t)c * H_ * W_;
        float2 xa = *(const float2*)(x + base);
        float2 xb = *(const float2*)(x + base + W_);
        float ax = 0.25f * (xa.x + xa.y + xb.x + xb.y);
        float mx = fmaxf(fmaxf(xa.x, xa.y), fmaxf(xb.x, xb.y));
        float d1 = as - mx; acc1 += d1 * d1;
        float d2 = ax - ms; acc2 += d2 * d2;
    }
    out[idx] = sqrtf(acc1) + sqrtf(acc2);
}

// ---------------- smap: sigmoid(up2(map)) x2 -> (dilate3-map)x2 + 1 ----------------
__global__ __launch_bounds__(256)
void smap_kernel(const float* __restrict__ in_map, const float* __restrict__ ds,
                 float* __restrict__ smap)
{
    __shared__ float s_i[10 * 34];
    __shared__ float s_d[10 * 34];
    int tid = threadIdx.x;
    int x0 = blockIdx.x * 32, y0 = blockIdx.y * 8, b = blockIdx.z;
    const float rr = 95.f / 191.f;
    const float* pi = in_map + (size_t)b * h_ * w_;
    const float* pd = ds + (size_t)b * h_ * w_;

    for (int item = tid; item < 340; item += 256) {
        int hy = item / 34, hx = item - hy * 34;
        int gy = y0 - 1 + hy, gx = x0 - 1 + hx;
        float vi = -INFINITY, vd = -INFINITY;
        if ((unsigned)gy < (unsigned)H_ && (unsigned)gx < (unsigned)W_) {
            float sy = gy * rr; int iy0 = (int)sy; float wy = sy - (float)iy0;
            int iy1 = min(iy0 + 1, h_ - 1);
            float sx = gx * rr; int ix0 = (int)sx; float wx = sx - (float)ix0;
            int ix1 = min(ix0 + 1, w_ - 1);
            float w00 = (1.f - wy) * (1.f - wx), w01 = (1.f - wy) * wx;
            float w10 = wy * (1.f - wx),         w11 = wy * wx;
            float ui = pi[iy0 * w_ + ix0] * w00 + pi[iy0 * w_ + ix1] * w01
                     + pi[iy1 * w_ + ix0] * w10 + pi[iy1 * w_ + ix1] * w11;
            float ud = pd[iy0 * w_ + ix0] * w00 + pd[iy0 * w_ + ix1] * w01
                     + pd[iy1 * w_ + ix0] * w10 + pd[iy1 * w_ + ix1] * w11;
            vi = 1.f / (1.f + expf(-ui));
            vd = 1.f / (1.f + expf(-ud));
        }
        s_i[item] = vi; s_d[item] = vd;
    }
    __syncthreads();

    int tx = tid & 31, ty = tid >> 5;
    int ci = (ty + 1) * 34 + tx + 1;
    float mi = -INFINITY, md = -INFINITY;
#pragma unroll
    for (int dy = 0; dy < 3; dy++)
#pragma unroll
        for (int dx = 0; dx < 3; dx++) {
            int o = (ty + dy) * 34 + tx + dx;
            mi = fmaxf(mi, s_i[o]);
            md = fmaxf(md, s_d[o]);
        }
    float s = (mi - s_i[ci]) + (md - s_d[ci]) + 1.0f;
    smap[((size_t)b * H_ + (y0 + ty)) * W_ + x0 + tx] = s;
}

// ---------------- final conv 7x7, 64 -> 1 (fp32), 4 px/thread ----------------
__global__ __launch_bounds__(256)
void conv_out_kernel(const float* __restrict__ rin, const float* __restrict__ Wo,
                     const float* __restrict__ bo, float* __restrict__ out)
{
    extern __shared__ float s_in[];            // 8 x 22 x 70
    __shared__ float s_w[8 * 49];
    int tid = threadIdx.x, tx = tid & 31, ty = tid >> 5;
    int x0 = blockIdx.x * 64, ys = blockIdx.y * 16, b = blockIdx.z;
    float a0 = 0.f, a1 = 0.f, a2 = 0.f, a3 = 0.f;
    for (int c0 = 0; c0 < 64; c0 += 8) {
        __syncthreads();
        for (int idx = tid; idx < 8 * 22 * 70; idx += 256) {
            int c = idx / (22 * 70);
            int r = idx - c * (22 * 70);
            int ly = r / 70, lx = r - ly * 70;
            int gy = ys + ly - 3, gx = x0 + lx - 3;
            float v = 0.f;
            if ((unsigned)gy < (unsigned)H_ && (unsigned)gx < (unsigned)W_)
                v = rin[((size_t)(b * 64 + c0 + c) * H_ + gy) * W_ + gx];
            s_in[idx] = v;
        }
        for (int idx = tid; idx < 8 * 49; idx += 256)
            s_w[idx] = Wo[(c0 + idx / 49) * 49 + idx % 49];
        __syncthreads();
#pragma unroll
        for (int c = 0; c < 8; c++)
            for (int ky = 0; ky < 7; ky++) {
                int r0 = (c * 22 + ty + ky) * 70;
                int r1 = (c * 22 + ty + 8 + ky) * 70;
#pragma unroll
                for (int kx = 0; kx < 7; kx++) {
                    float w = s_w[c * 49 + ky * 7 + kx];
                    a0 += w * s_in[r0 + tx + kx];
                    a1 += w * s_in[r0 + tx + 32 + kx];
                    a2 += w * s_in[r1 + tx + kx];
                    a3 += w * s_in[r1 + tx + 32 + kx];
                }
            }
    }
    float bv = bo[0];
    out[((size_t)b * H_ + (ys + ty))     * W_ + x0 + tx]      = a0 + bv;
    out[((size_t)b * H_ + (ys + ty))     * W_ + x0 + tx + 32] = a1 + bv;
    out[((size_t)b * H_ + (ys + ty + 8)) * W_ + x0 + tx]      = a2 + bv;
    out[((size_t)b * H_ + (ys + ty + 8)) * W_ + x0 + tx + 32] = a3 + bv;
}

// ---------------- launch ----------------
#define SMEM_UP (1024 + 14*40*128 + 2*2*8192)   // 105472  (KS=7, G=2)
#define SMEM_3  (1024 + 10*34*128 + 2*3*8192)   // 93696   (KS=3, G=3)
#define SMEM_CO (8*22*70*4)                     // 49280

extern "C" void kernel_launch(void* const* d_in, const int* in_sizes, int n_in,
                              void* d_out, int out_size)
{
    const float* x       = (const float*)d_in[0];
    const float* small_x = (const float*)d_in[1];
    const float* in_map  = (const float*)d_in[2];
    const float* W_up  = (const float*)d_in[3];
    const float* b_up  = (const float*)d_in[4];
    const float* gup   = (const float*)d_in[5];
    const float* beup  = (const float*)d_in[6];
    const float* mup   = (const float*)d_in[7];
    const float* vup   = (const float*)d_in[8];
    const float* W_c2  = (const float*)d_in[9];
    const float* b_c2  = (const float*)d_in[10];
    const float* W_d1  = (const float*)d_in[11];
    const float* b_d1  = (const float*)d_in[12];
    const float* gd1   = (const float*)d_in[13];
    const float* bed1  = (const float*)d_in[14];
    const float* md1   = (const float*)d_in[15];
    const float* vd1   = (const float*)d_in[16];
    const float* W_d2  = (const float*)d_in[17];
    const float* b_d2  = (const float*)d_in[18];
    const float* gd2   = (const float*)d_in[19];
    const float* bed2  = (const float*)d_in[20];
    const float* md2   = (const float*)d_in[21];
    const float* vd2   = (const float*)d_in[22];
    const float* W_d3  = (const float*)d_in[23];
    const float* b_d3  = (const float*)d_in[24];
    const float* gd3   = (const float*)d_in[25];
    const float* bed3  = (const float*)d_in[26];
    const float* md3   = (const float*)d_in[27];
    const float* vd3   = (const float*)d_in[28];
    const float* W_out = (const float*)d_in[29];
    const float* b_out = (const float*)d_in[30];
    const float* beta  = (const float*)d_in[31];

    float *u, *ds, *sp;
    __half *fn16, *r116, *r216;
    unsigned char* wbf;
    cudaGetSymbolAddress((void**)&u,    g_u);
    cudaGetSymbolAddress((void**)&ds,   g_diffs);
    cudaGetSymbolAddress((void**)&sp,   g_smap);
    cudaGetSymbolAddress((void**)&fn16, g_fn16);
    cudaGetSymbolAddress((void**)&r116, g_r116);
    cudaGetSymbolAddress((void**)&r216, g_r216);
    cudaGetSymbolAddress((void**)&wbf,  g_wbf);

    cudaFuncSetAttribute(tconv<7,2,2,1,0,0>, cudaFuncAttributeMaxDynamicSharedMemorySize, SMEM_UP);
    cudaFuncSetAttribute(tconv<3,1,3,0,1,1>, cudaFuncAttributeMaxDynamicSharedMemorySize, SMEM_3);
    cudaFuncSetAttribute(tconv<3,2,3,1,2,1>, cudaFuncAttributeMaxDynamicSharedMemorySize, SMEM_3);
    cudaFuncSetAttribute(tconv<3,1,3,1,3,1>, cudaFuncAttributeMaxDynamicSharedMemorySize, SMEM_3);
    cudaFuncSetAttribute(tconv<3,1,3,1,3,0>, cudaFuncAttributeMaxDynamicSharedMemorySize, SMEM_3);
    cudaFuncSetAttribute(conv_out_kernel,    cudaFuncAttributeMaxDynamicSharedMemorySize, SMEM_CO);

    // 1) fused weight prep
    prep_all<<<1024, 256>>>(W_up, W_c2, W_d1, W_d2, W_d3, wbf);

    // 2) up branch: conv7x7 + BN + GELU -> u (96x96 fp32)
    tconv<7,2,2,1,0,0><<<dim3(3, 12, 8), 256, SMEM_UP>>>(
        small_x, nullptr, nullptr, (const uint4*)(wbf + (size_t)CH_UP * 16384),
        b_up, gup, beup, mup, vup, nullptr, u, nullptr, h_, w_);

    // 3) uncertainty maps
    diff_kernel<<<(B_ * h_ * w_ + 255) / 256, 256>>>(u, x, ds);
    smap_kernel<<<dim3(6, 24, 8), 256>>>(in_map, ds, sp);

    // 4) conv chain (HMMA fp16; inter-layer buffers fp16 NHWC)
    tconv<3,1,3,0,1,1><<<dim3(6, 24, 8), 256, SMEM_3>>>(
        x, nullptr, sp, (const uint4*)(wbf + (size_t)CH_C2 * 16384),
        b_c2, nullptr, nullptr, nullptr, nullptr, beta, nullptr, fn16, H_, W_);
    tconv<3,2,3,1,2,1><<<dim3(6, 24, 8), 256, SMEM_3>>>(
        nullptr, fn16, u, (const uint4*)(wbf + (size_t)CH_D1 * 16384),
        b_d1, gd1, bed1, md1, vd1, nullptr, nullptr, r116, H_, W_);
    tconv<3,1,3,1,3,1><<<dim3(6, 24, 8), 256, SMEM_3>>>(
        nullptr, r116, nullptr, (const uint4*)(wbf + (size_t)CH_D2 * 16384),
        b_d2, gd2, bed2, md2, vd2, nullptr, nullptr, r216, H_, W_);
    tconv<3,1,3,1,3,0><<<dim3(6, 24, 8), 256, SMEM_3>>>(
        nullptr, r216, nullptr, (const uint4*)(wbf + (size_t)CH_D3 * 16384),
        b_d3, gd3, bed3, md3, vd3, nullptr, (float*)d_out, nullptr, H_, W_);

    // 5) output head (reads r from d_out, writes output_map after it)
    conv_out_kernel<<<dim3(3, 12, 8), 256, SMEM_CO>>>(
        (const float*)d_out, W_out, b_out, (float*)d_out + R_ELEMS);
}

// round 12
// speedup vs baseline: 5.5864x; 1.0084x over previous
#include <cuda_runtime.h>
#include <cuda_fp16.h>
#include <math.h>
#include <stdint.h>

// ---------------- problem constants ----------------
#define B_ 8
#define H_ 192
#define W_ 192
#define h_ 96
#define w_ 96
#define R_ELEMS (B_*64*H_*W_)        // 18,874,368

// weight-chunk table (each chunk = 16KB: 8KB hi + 8KB lo, [n][k] swizzled fp16)
#define CH_UP 0      // 7x7, CG=2 -> 98 chunks
#define CH_C2 98     // 3x3, CG=1 -> 9
#define CH_D1 107    // 3x3, CG=2 -> 18
#define CH_D2 125    // 9
#define CH_D3 134    // 9
#define CH_TOTAL 143

// ---------------- scratch ----------------
__device__ __align__(16) unsigned char g_wbf[CH_TOTAL * 16384];
__device__ float g_u[B_*64*h_*w_];
__device__ float g_diffs[B_*h_*w_];
__device__ float g_smap[B_*H_*W_];
__device__ __align__(16) __half g_fn16[R_ELEMS];   // NHWC fp16
__device__ __align__(16) __half g_r116[R_ELEMS];   // NHWC fp16
__device__ __align__(16) __half g_r216[R_ELEMS];   // NHWC fp16

// ---------------- helpers ----------------
__device__ __forceinline__ uint32_t smem_u32(const void* p) {
    uint32_t a;
    asm("{ .reg .u64 t; cvta.to.shared.u64 t, %1; cvt.u32.u64 %0, t; }" : "=r"(a) : "l"(p));
    return a;
}
__device__ __forceinline__ void ldm4(uint32_t addr, uint32_t r[4]) {
    asm volatile("ldmatrix.sync.aligned.m8n8.x4.shared.b16 {%0,%1,%2,%3}, [%4];"
                 : "=r"(r[0]), "=r"(r[1]), "=r"(r[2]), "=r"(r[3]) : "r"(addr));
}
__device__ __forceinline__ void mma16816(float c[4], const uint32_t a[4],
                                         uint32_t b0, uint32_t b1) {
    asm volatile(
        "mma.sync.aligned.m16n8k16.row.col.f32.f16.f16.f32 "
        "{%0,%1,%2,%3}, {%4,%5,%6,%7}, {%8,%9}, {%0,%1,%2,%3};"
        : "+f"(c[0]), "+f"(c[1]), "+f"(c[2]), "+f"(c[3])
        : "r"(a[0]), "r"(a[1]), "r"(a[2]), "r"(a[3]), "r"(b0), "r"(b1));
}
__device__ __forceinline__ void cpa16(uint32_t saddr, const void* g) {
    asm volatile("cp.async.cg.shared.global [%0], [%1], 16;" :: "r"(saddr), "l"(g) : "memory");
}
__device__ __forceinline__ void cpa4(uint32_t saddr, const void* g) {
    asm volatile("cp.async.ca.shared.global [%0], [%1], 4;" :: "r"(saddr), "l"(g) : "memory");
}
#define CPA_COMMIT() asm volatile("cp.async.commit_group;" ::: "memory")
#define CPA_WAIT0()  asm volatile("cp.async.wait_group 0;" ::: "memory")

__device__ __forceinline__ float gelu_exact(float y) {
    return 0.5f * y * (1.0f + erff(y * 0.70710678118654752f));
}
__device__ __forceinline__ uint32_t packh2(float a, float b) {
    __half2 h = __floats2half2_rn(a, b);
    return *(uint32_t*)&h;
}
// bilinear sample matching the original up2_kernel's exact fp32 expression order
__device__ __forceinline__ float bil96(const float* p, int iy0, int iy1, float wy,
                                       int ix0, int ix1, float wx) {
    float a = p[iy0 * 96 + ix0], b = p[iy1 * 96 + ix0];
    float c = p[iy0 * 96 + ix1], d = p[iy1 * 96 + ix1];
    float ra = a * (1.f - wy) + b * wy;
    float rb = c * (1.f - wy) + d * wy;
    return ra * (1.f - wx) + rb * wx;
}

// ---------------- fused weight prep: all 5 conv weight sets ----------------
__global__ void prep_all(const float* __restrict__ W_up, const float* __restrict__ W_c2,
                         const float* __restrict__ W_d1, const float* __restrict__ W_d2,
                         const float* __restrict__ W_d3, unsigned char* __restrict__ dst)
{
    int total = CH_TOTAL * 4096;
    for (int idx = blockIdx.x * blockDim.x + threadIdx.x; idx < total;
         idx += gridDim.x * blockDim.x) {
        int chunk = idx >> 12;
        int e = idx & 4095;
        int n = e >> 6, k = e & 63;
        const float* W; int CIN, KK, local;
        if (chunk < 98)       { W = W_up; CIN = 128; KK = 49; local = chunk; }
        else if (chunk < 107) { W = W_c2; CIN = 64;  KK = 9;  local = chunk - 98; }
        else if (chunk < 125) { W = W_d1; CIN = 128; KK = 9;  local = chunk - 107; }
        else if (chunk < 134) { W = W_d2; CIN = 64;  KK = 9;  local = chunk - 125; }
        else                  { W = W_d3; CIN = 64;  KK = 9;  local = chunk - 134; }
        int CG = CIN >> 6;
        int tap = local / CG, cg = local - tap * CG;
        float w = W[((size_t)n * CIN + cg * 64 + k) * KK + tap];
        __half hb = __float2half_rn(w);
        __half lb = __float2half_rn(w - __half2float(hb));
        uint32_t off = (uint32_t)n * 128 + ((((k >> 3) ^ (n & 7))) << 4) + (k & 7) * 2;
        unsigned char* base = dst + (size_t)chunk * 16384;
        *(unsigned short*)(base + off)        = __half_as_ushort(hb);
        *(unsigned short*)(base + 8192 + off) = __half_as_ushort(lb);
    }
}

// ---------------- HMMA implicit-GEMM conv (group-staged weights) ----------------
// TM=8 rows x 32 px per CTA (M=256), 64 out chans; warp tile m64 x n32.
// AMODE 0: input = inA (fp32 NCHW).  AMODE 1: inA * aux(smap).
// AMODE 2: cg0 = bilinear-up2(aux = u), cg1 = inH (fp16 NHWC).
// AMODE 3: input = inH (fp16 NHWC).
// MODE 0: beta*(acc+bias)   MODE 1: gelu(bn(acc+bias))
// OUTF 0: fp32 NCHW (outF)  OUTF 1: fp16 NHWC (outH)
template<int KS, int CG, int G, int MODE, int AMODE, int OUTF>
__global__ __launch_bounds__(256, 2)
void tconv(const float* __restrict__ inA, const __half* __restrict__ inH,
           const float* __restrict__ aux,
           const uint4* __restrict__ wch, const float* __restrict__ bias,
           const float* __restrict__ gg, const float* __restrict__ bb,
           const float* __restrict__ mm, const float* __restrict__ vv,
           const float* __restrict__ betap,
           float* __restrict__ outF, __half* __restrict__ outH,
           int H, int W)
{
    constexpr int PAD = KS / 2;
    constexpr int TM  = 8;
    constexpr int IH  = TM + KS - 1;
    constexpr int IWP = (KS == 3) ? 34 : 40;
    constexpr int NPX = IH * IWP;
    constexpr int KK  = KS * KS;
    constexpr int GPC = (KK + G - 1) / G;
    constexpr int NGRP = GPC * CG;
    constexpr int OFF_A = 1024;
    constexpr int OFF_B = 1024 + NPX * 128;
    constexpr int BSTRIDE = G * 8192;

    extern __shared__ char smem_raw[];
    char* smem = (char*)(((uintptr_t)smem_raw + 1023) & ~(uintptr_t)1023);
    uint32_t sb = smem_u32(smem);
    float* epi = (float*)smem;

    int tid = threadIdx.x, wid = tid >> 5, lane = tid & 31;
    int x0 = blockIdx.x * 32, y0 = blockIdx.y * TM, b = blockIdx.z;
    size_t HW = (size_t)H * W;

    auto stage_group = [&](int fg, int buf) {
        int cgg = fg / GPC, grp = fg - cgg * GPC;
        int t0 = grp * G;
        int cnt = (KK - t0 < G) ? (KK - t0) : G;
        for (int j = 0; j < cnt; j++) {
            int chunk = (t0 + j) * CG + cgg;
            const uint4* srcB = wch + (size_t)chunk * 1024;
            uint32_t dstB = sb + OFF_B + buf * BSTRIDE + j * 8192;
#pragma unroll
            for (int k = 0; k < 2; k++)
                cpa16(dstB + (uint32_t)(tid + k * 256) * 16, srcB + tid + k * 256);
        }
        CPA_COMMIT();
    };

    stage_group(0, 0);

    if (tid < 64) {
        int c = tid;
        float s, t;
        if (MODE == 1) {
            s = gg[c] * rsqrtf(vv[c] + 1e-5f);
            t = (bias[c] - mm[c]) * s + bb[c];
        } else {
            float bt = *betap;
            s = bt; t = bt * bias[c];
        }
        epi[c] = s; epi[64 + c] = t;
    }

    float acc[16][4];
#pragma unroll
    for (int i = 0; i < 16; i++)
#pragma unroll
        for (int j = 0; j < 4; j++) acc[i][j] = 0.f;

    int wm = wid >> 1, nh = wid & 1;
    int ar = lane & 15, akq = lane >> 4;
    int br = lane & 15, bkq = lane >> 4;

    int fg = 0;
    for (int cg = 0; cg < CG; cg++) {
        __syncthreads();

        // ---- stage halo ----
        constexpr int TOT = NPX * 8;
        bool h16 = (AMODE == 3) || (AMODE == 2 && CG == 2);
        if (h16 && (AMODE == 3 || cg == 1)) {
            for (int item = tid; item < TOT; item += 256) {
                int ph = item >> 3, o = item & 7;
                int hy = ph / IWP, hx = ph - hy * IWP;
                int gy = y0 + hy - PAD;
                int gx = x0 + hx - PAD;
                uint4 val = make_uint4(0, 0, 0, 0);
                if ((unsigned)gy < (unsigned)H && (unsigned)gx < (unsigned)W)
                    val = *(const uint4*)(inH + ((((size_t)b * H + gy) * W + gx) << 6) + o * 8);
                uint32_t ad = (uint32_t)ph * 128 + (((o ^ (ph & 7))) << 4);
                *(uint4*)(smem + OFF_A + ad) = val;
            }
        } else {
            const float* src = nullptr;
            if (AMODE != 2) src = inA + ((size_t)b * (CG * 64) + cg * 64) * HW;
            const float rr = 95.f / 191.f;
            for (int item = tid; item < TOT; item += 256) {
                int o  = item / NPX;
                int ph = item - o * NPX;
                int hy = ph / IWP, hx = ph - hy * IWP;
                int gy = y0 + hy - PAD;
                int gx = x0 + hx - PAD;
                float v[8];
                bool inb = (unsigned)gy < (unsigned)H && (unsigned)gx < (unsigned)W;
                if (AMODE == 2) {
                    if (inb) {
                        float sy = gy * rr; int iy0 = (int)sy; float wy = sy - (float)iy0;
                        int iy1 = min(iy0 + 1, 95);
                        float sx = gx * rr; int ix0 = (int)sx; float wx = sx - (float)ix0;
                        int ix1 = min(ix0 + 1, 95);
                        const float* up = aux + (size_t)(b * 64 + o * 8) * 9216;
#pragma unroll
                        for (int j = 0; j < 8; j++)
                            v[j] = bil96(up + j * 9216, iy0, iy1, wy, ix0, ix1, wx);
                    } else {
#pragma unroll
                        for (int j = 0; j < 8; j++) v[j] = 0.f;
                    }
                } else {
                    if (inb) {
                        const float* p = src + (size_t)(o * 8) * HW + (size_t)gy * W + gx;
#pragma unroll
                        for (int j = 0; j < 8; j++) v[j] = p[j * HW];
                        if (AMODE == 1) {
                            float sv = aux[(size_t)b * HW + (size_t)gy * W + gx];
#pragma unroll
                            for (int j = 0; j < 8; j++) v[j] *= sv;
                        }
                    } else {
#pragma unroll
                        for (int j = 0; j < 8; j++) v[j] = 0.f;
                    }
                }
                uint4 hi4;
                hi4.x = packh2(v[0], v[1]); hi4.y = packh2(v[2], v[3]);
                hi4.z = packh2(v[4], v[5]); hi4.w = packh2(v[6], v[7]);
                uint32_t ad = (uint32_t)ph * 128 + (((o ^ (ph & 7))) << 4);
                *(uint4*)(smem + OFF_A + ad) = hi4;
            }
        }

        for (int grp = 0; grp < GPC; grp++, fg++) {
            int s = fg & 1;
            CPA_WAIT0();
            __syncthreads();

            if (fg + 1 < NGRP) stage_group(fg + 1, s ^ 1);

            int t0 = grp * G;
#pragma unroll
            for (int j = 0; j < G; j++) {
                int tap = t0 + j;
                if (tap < KK) {
                    int tapy = tap / KS, tapx = tap - tapy * KS;
                    uint32_t bbase = sb + OFF_B + s * BSTRIDE + j * 8192;
#pragma unroll
                    for (int kc = 0; kc < 4; kc++) {
                        uint32_t a[4][4];
#pragma unroll
                        for (int t = 0; t < 4; t++) {
                            int y = wm * 2 + (t >> 1);
                            int ph = (y + tapy) * IWP + (t & 1) * 16 + ar + tapx;
                            ldm4(sb + OFF_A + (uint32_t)ph * 128
                                 + ((((kc * 2 + akq) ^ (ph & 7))) << 4), a[t]);
                        }
#pragma unroll
                        for (int g = 0; g < 2; g++) {
                            int n = nh * 32 + g * 16 + br;
                            uint32_t ba = bbase + (uint32_t)n * 128
                                        + ((((kc * 2 + bkq) ^ (n & 7))) << 4);
                            uint32_t bh[4];
                            ldm4(ba, bh);
#pragma unroll
                            for (int t = 0; t < 4; t++) {
                                mma16816(acc[t * 4 + 2 * g],     a[t], bh[0], bh[2]);
                                mma16816(acc[t * 4 + 2 * g + 1], a[t], bh[1], bh[3]);
                            }
                        }
                    }
                }
            }
        }
    }

    // ---- epilogue ----
    __syncthreads();
    float* tb = (float*)(smem + 1024);
    {
        int row = lane >> 2, colp = (lane & 3) * 2;
#pragma unroll
        for (int t = 0; t < 4; t++) {
            int p0 = wm * 64 + t * 16 + row;
#pragma unroll
            for (int j = 0; j < 4; j++) {
                int c = nh * 32 + j * 8 + colp;
                tb[p0 * 65 + c]            = acc[t * 4 + j][0];
                tb[p0 * 65 + c + 1]        = acc[t * 4 + j][1];
                tb[(p0 + 8) * 65 + c]      = acc[t * 4 + j][2];
                tb[(p0 + 8) * 65 + c + 1]  = acc[t * 4 + j][3];
            }
        }
    }
    __syncthreads();
    if (OUTF == 0) {
#pragma unroll 4
        for (int it = 0; it < 64; it++) {
            int item = it * 8 + wid;
            int c = item >> 3, py = item & 7;
            float v = tb[(py * 32 + lane) * 65 + c] * epi[c] + epi[64 + c];
            if (MODE == 1) v = gelu_exact(v);
            outF[((size_t)(b * 64 + c) * H + (y0 + py)) * W + x0 + lane] = v;
        }
    } else {
#pragma unroll
        for (int it = 0; it < 8; it++) {
            int item = it * 256 + tid;
            int px = item >> 3, grp = item & 7;
            float vs[8];
#pragma unroll
            for (int j = 0; j < 8; j++) {
                int c = grp * 8 + j;
                float v = tb[px * 65 + c] * epi[c] + epi[64 + c];
                if (MODE == 1) v = gelu_exact(v);
                vs[j] = v;
            }
            uint4 pk;
            pk.x = packh2(vs[0], vs[1]); pk.y = packh2(vs[2], vs[3]);
            pk.z = packh2(vs[4], vs[5]); pk.w = packh2(vs[6], vs[7]);
            int py = px >> 5, xx = px & 31;
            *(uint4*)(outH + ((((size_t)b * H + y0 + py) * W + x0 + xx) << 6) + grp * 8) = pk;
        }
    }
}

// ---------------- AP_MP diff with inline up2(u), 2 outputs/thread ----------------
__global__ void diff_kernel(const float* __restrict__ u, const float* __restrict__ x,
                            float* __restrict__ out)
{
    int idx = blockIdx.x * blockDim.x + threadIdx.x;
    if (idx >= B_ * h_ * (w_ / 2)) return;
    int jp = idx % (w_ / 2);
    int t = idx / (w_ / 2);
    int i = t % h_;
    int b = t / h_;
    int j0 = 2 * jp;               // outputs j0, j0+1
    const float rr = 95.f / 191.f;

    float syA = (2 * i) * rr;     int iyA0 = (int)syA; float wyA = syA - (float)iyA0; int iyA1 = min(iyA0 + 1, 95);
    float syB = (2 * i + 1) * rr; int iyB0 = (int)syB; float wyB = syB - (float)iyB0; int iyB1 = min(iyB0 + 1, 95);

    // per-output x coordinates
    float sxA0 = (2 * j0) * rr;     int ixA00 = (int)sxA0; float wxA0 = sxA0 - (float)ixA00; int ixA01 = min(ixA00 + 1, 95);
    float sxB0 = (2 * j0 + 1) * rr; int ixB00 = (int)sxB0; float wxB0 = sxB0 - (float)ixB00; int ixB01 = min(ixB00 + 1, 95);
    float sxA1 = (2 * j0 + 2) * rr; int ixA10 = (int)sxA1; float wxA1 = sxA1 - (float)ixA10; int ixA11 = min(ixA10 + 1, 95);
    float sxB1 = (2 * j0 + 3) * rr; int ixB10 = (int)sxB1; float wxB1 = sxB1 - (float)ixB10; int ixB11 = min(ixB10 + 1, 95);

    float a1_0 = 0.f, a2_0 = 0.f, a1_1 = 0.f, a2_1 = 0.f;
    size_t base0 = ((size_t)b * 64 * H_ + 2 * i) * W_ + 4 * jp;
    for (int c = 0; c < 64; c++) {
        const float* uc = u + (size_t)(b * 64 + c) * 9216;
        size_t base = base0 + (size_t)c * H_ * W_;
        float4 xr0 = *(const float4*)(x + base);
        float4 xr1 = *(const float4*)(x + base + W_);

        // ---- output j0 ----
        {
            float s00 = bil96(uc, iyA0, iyA1, wyA, ixA00, ixA01, wxA0);
            float s01 = bil96(uc, iyA0, iyA1, wyA, ixB00, ixB01, wxB0);
            float s10 = bil96(uc, iyB0, iyB1, wyB, ixA00, ixA01, wxA0);
            float s11 = bil96(uc, iyB0, iyB1, wyB, ixB00, ixB01, wxB0);
            float as = 0.25f * (s00 + s01 + s10 + s11);
            float ms = fmaxf(fmaxf(s00, s01), fmaxf(s10, s11));
            float ax = 0.25f * (xr0.x + xr0.y + xr1.x + xr1.y);
            float mx = fmaxf(fmaxf(xr0.x, xr0.y), fmaxf(xr1.x, xr1.y));
            float d1 = as - mx; a1_0 += d1 * d1;
            float d2 = ax - ms; a2_0 += d2 * d2;
        }
        // ---- output j0+1 ----
        {
            float s00 = bil96(uc, iyA0, iyA1, wyA, ixA10, ixA11, wxA1);
            float s01 = bil96(uc, iyA0, iyA1, wyA, ixB10, ixB11, wxB1);
            float s10 = bil96(uc, iyB0, iyB1, wyB, ixA10, ixA11, wxA1);
            float s11 = bil96(uc, iyB0, iyB1, wyB, ixB10, ixB11, wxB1);
            float as = 0.25f * (s00 + s01 + s10 + s11);
            float ms = fmaxf(fmaxf(s00, s01), fmaxf(s10, s11));
            float ax = 0.25f * (xr0.z + xr0.w + xr1.z + xr1.w);
            float mx = fmaxf(fmaxf(xr0.z, xr0.w), fmaxf(xr1.z, xr1.w));
            float d1 = as - mx; a1_1 += d1 * d1;
            float d2 = ax - ms; a2_1 += d2 * d2;
        }
    }
    size_t ob = ((size_t)b * h_ + i) * w_ + j0;
    out[ob]     = sqrtf(a1_0) + sqrtf(a2_0);
    out[ob + 1] = sqrtf(a1_1) + sqrtf(a2_1);
}

// ---------------- smap: sigmoid(up2(map)) x2 -> (dilate3-map)x2 + 1 ----------------
__global__ __launch_bounds__(256)
void smap_kernel(const float* __restrict__ in_map, const float* __restrict__ ds,
                 float* __restrict__ smap)
{
    __shared__ float s_i[10 * 34];
    __shared__ float s_d[10 * 34];
    int tid = threadIdx.x;
    int x0 = blockIdx.x * 32, y0 = blockIdx.y * 8, b = blockIdx.z;
    const float rr = 95.f / 191.f;
    const float* pi = in_map + (size_t)b * h_ * w_;
    const float* pd = ds + (size_t)b * h_ * w_;

    for (int item = tid; item < 340; item += 256) {
        int hy = item / 34, hx = item - hy * 34;
        int gy = y0 - 1 + hy, gx = x0 - 1 + hx;
        float vi = -INFINITY, vd = -INFINITY;
        if ((unsigned)gy < (unsigned)H_ && (unsigned)gx < (unsigned)W_) {
            float sy = gy * rr; int iy0 = (int)sy; float wy = sy - (float)iy0;
            int iy1 = min(iy0 + 1, h_ - 1);
            float sx = gx * rr; int ix0 = (int)sx; float wx = sx - (float)ix0;
            int ix1 = min(ix0 + 1, w_ - 1);
            float w00 = (1.f - wy) * (1.f - wx), w01 = (1.f - wy) * wx;
            float w10 = wy * (1.f - wx),         w11 = wy * wx;
            float ui = pi[iy0 * w_ + ix0] * w00 + pi[iy0 * w_ + ix1] * w01
                     + pi[iy1 * w_ + ix0] * w10 + pi[iy1 * w_ + ix1] * w11;
            float ud = pd[iy0 * w_ + ix0] * w00 + pd[iy0 * w_ + ix1] * w01
                     + pd[iy1 * w_ + ix0] * w10 + pd[iy1 * w_ + ix1] * w11;
            vi = 1.f / (1.f + expf(-ui));
            vd = 1.f / (1.f + expf(-ud));
        }
        s_i[item] = vi; s_d[item] = vd;
    }
    __syncthreads();

    int tx = tid & 31, ty = tid >> 5;
    int ci = (ty + 1) * 34 + tx + 1;
    float mi = -INFINITY, md = -INFINITY;
#pragma unroll
    for (int dy = 0; dy < 3; dy++)
#pragma unroll
        for (int dx = 0; dx < 3; dx++) {
            int o = (ty + dy) * 34 + tx + dx;
            mi = fmaxf(mi, s_i[o]);
            md = fmaxf(md, s_d[o]);
        }
    float s = (mi - s_i[ci]) + (md - s_d[ci]) + 1.0f;
    smap[((size_t)b * H_ + (y0 + ty)) * W_ + x0 + tx] = s;
}

// ---------------- final conv 7x7, 64 -> 1 (fp32), double-buffered cp.async ----------------
__global__ __launch_bounds__(256)
void conv_out_kernel(const float* __restrict__ rin, const float* __restrict__ Wo,
                     const float* __restrict__ bo, float* __restrict__ out)
{
    extern __shared__ float s_dyn[];           // 2 x (8*22*70)
    __shared__ float s_w[64 * 49];
    constexpr int BUFE = 8 * 22 * 70;          // 12320 floats
    uint32_t sdb = smem_u32(s_dyn);

    int tid = threadIdx.x, tx = tid & 31, ty = tid >> 5;
    int x0 = blockIdx.x * 64, ys = blockIdx.y * 16, b = blockIdx.z;

    // stage all weights once
    for (int idx = tid; idx < 64 * 49; idx += 256)
        s_w[idx] = Wo[idx];

    auto stage = [&](int c0, int buf) {
        float* dst = s_dyn + buf * BUFE;
        uint32_t dbase = sdb + (uint32_t)buf * BUFE * 4;
        for (int idx = tid; idx < BUFE; idx += 256) {
            int c = idx / (22 * 70);
            int r = idx - c * (22 * 70);
            int ly = r / 70, lx = r - ly * 70;
            int gy = ys + ly - 3, gx = x0 + lx - 3;
            if ((unsigned)gy < (unsigned)H_ && (unsigned)gx < (unsigned)W_)
                cpa4(dbase + (uint32_t)idx * 4,
                     rin + ((size_t)(b * 64 + c0 + c) * H_ + gy) * W_ + gx);
            else
                dst[idx] = 0.f;
        }
        CPA_COMMIT();
    };

    stage(0, 0);
    CPA_WAIT0();
    __syncthreads();

    float a0 = 0.f, a1 = 0.f, a2 = 0.f, a3 = 0.f;
    for (int it = 0; it < 8; it++) {
        int buf = it & 1;
        if (it + 1 < 8) stage((it + 1) * 8, buf ^ 1);
        const float* cur = s_dyn + buf * BUFE;
#pragma unroll
        for (int c = 0; c < 8; c++)
            for (int ky = 0; ky < 7; ky++) {
                int r0 = (c * 22 + ty + ky) * 70;
                int r1 = (c * 22 + ty + 8 + ky) * 70;
#pragma unroll
                for (int kx = 0; kx < 7; kx++) {
                    float w = s_w[(it * 8 + c) * 49 + ky * 7 + kx];
                    a0 += w * cur[r0 + tx + kx];
                    a1 += w * cur[r0 + tx + 32 + kx];
                    a2 += w * cur[r1 + tx + kx];
                    a3 += w * cur[r1 + tx + 32 + kx];
                }
            }
        CPA_WAIT0();
        __syncthreads();
    }
    float bv = bo[0];
    out[((size_t)b * H_ + (ys + ty))     * W_ + x0 + tx]      = a0 + bv;
    out[((size_t)b * H_ + (ys + ty))     * W_ + x0 + tx + 32] = a1 + bv;
    out[((size_t)b * H_ + (ys + ty + 8)) * W_ + x0 + tx]      = a2 + bv;
    out[((size_t)b * H_ + (ys + ty + 8)) * W_ + x0 + tx + 32] = a3 + bv;
}

// ---------------- launch ----------------
#define SMEM_UP (1024 + 14*40*128 + 2*2*8192)   // 105472  (KS=7, G=2)
#define SMEM_3  (1024 + 10*34*128 + 2*3*8192)   // 93696   (KS=3, G=3)
#define SMEM_CO (2*8*22*70*4)                   // 98560

extern "C" void kernel_launch(void* const* d_in, const int* in_sizes, int n_in,
                              void* d_out, int out_size)
{
    const float* x       = (const float*)d_in[0];
    const float* small_x = (const float*)d_in[1];
    const float* in_map  = (const float*)d_in[2];
    const float* W_up  = (const float*)d_in[3];
    const float* b_up  = (const float*)d_in[4];
    const float* gup   = (const float*)d_in[5];
    const float* beup  = (const float*)d_in[6];
    const float* mup   = (const float*)d_in[7];
    const float* vup   = (const float*)d_in[8];
    const float* W_c2  = (const float*)d_in[9];
    const float* b_c2  = (const float*)d_in[10];
    const float* W_d1  = (const float*)d_in[11];
    const float* b_d1  = (const float*)d_in[12];
    const float* gd1   = (const float*)d_in[13];
    const float* bed1  = (const float*)d_in[14];
    const float* md1   = (const float*)d_in[15];
    const float* vd1   = (const float*)d_in[16];
    const float* W_d2  = (const float*)d_in[17];
    const float* b_d2  = (const float*)d_in[18];
    const float* gd2   = (const float*)d_in[19];
    const float* bed2  = (const float*)d_in[20];
    const float* md2   = (const float*)d_in[21];
    const float* vd2   = (const float*)d_in[22];
    const float* W_d3  = (const float*)d_in[23];
    const float* b_d3  = (const float*)d_in[24];
    const float* gd3   = (const float*)d_in[25];
    const float* bed3  = (const float*)d_in[26];
    const float* md3   = (const float*)d_in[27];
    const float* vd3   = (const float*)d_in[28];
    const float* W_out = (const float*)d_in[29];
    const float* b_out = (const float*)d_in[30];
    const float* beta  = (const float*)d_in[31];

    float *u, *ds, *sp;
    __half *fn16, *r116, *r216;
    unsigned char* wbf;
    cudaGetSymbolAddress((void**)&u,    g_u);
    cudaGetSymbolAddress((void**)&ds,   g_diffs);
    cudaGetSymbolAddress((void**)&sp,   g_smap);
    cudaGetSymbolAddress((void**)&fn16, g_fn16);
    cudaGetSymbolAddress((void**)&r116, g_r116);
    cudaGetSymbolAddress((void**)&r216, g_r216);
    cudaGetSymbolAddress((void**)&wbf,  g_wbf);

    cudaFuncSetAttribute(tconv<7,2,2,1,0,0>, cudaFuncAttributeMaxDynamicSharedMemorySize, SMEM_UP);
    cudaFuncSetAttribute(tconv<3,1,3,0,1,1>, cudaFuncAttributeMaxDynamicSharedMemorySize, SMEM_3);
    cudaFuncSetAttribute(tconv<3,2,3,1,2,1>, cudaFuncAttributeMaxDynamicSharedMemorySize, SMEM_3);
    cudaFuncSetAttribute(tconv<3,1,3,1,3,1>, cudaFuncAttributeMaxDynamicSharedMemorySize, SMEM_3);
    cudaFuncSetAttribute(tconv<3,1,3,1,3,0>, cudaFuncAttributeMaxDynamicSharedMemorySize, SMEM_3);
    cudaFuncSetAttribute(conv_out_kernel,    cudaFuncAttributeMaxDynamicSharedMemorySize, SMEM_CO);

    // 1) fused weight prep
    prep_all<<<1024, 256>>>(W_up, W_c2, W_d1, W_d2, W_d3, wbf);

    // 2) up branch: conv7x7 + BN + GELU -> u (96x96 fp32)
    tconv<7,2,2,1,0,0><<<dim3(3, 12, 8), 256, SMEM_UP>>>(
        small_x, nullptr, nullptr, (const uint4*)(wbf + (size_t)CH_UP * 16384),
        b_up, gup, beup, mup, vup, nullptr, u, nullptr, h_, w_);

    // 3) uncertainty maps
    diff_kernel<<<(B_ * h_ * (w_ / 2) + 255) / 256, 256>>>(u, x, ds);
    smap_kernel<<<dim3(6, 24, 8), 256>>>(in_map, ds, sp);

    // 4) conv chain (HMMA fp16; inter-layer buffers fp16 NHWC)
    tconv<3,1,3,0,1,1><<<dim3(6, 24, 8), 256, SMEM_3>>>(
        x, nullptr, sp, (const uint4*)(wbf + (size_t)CH_C2 * 16384),
        b_c2, nullptr, nullptr, nullptr, nullptr, beta, nullptr, fn16, H_, W_);
    tconv<3,2,3,1,2,1><<<dim3(6, 24, 8), 256, SMEM_3>>>(
        nullptr, fn16, u, (const uint4*)(wbf + (size_t)CH_D1 * 16384),
        b_d1, gd1, bed1, md1, vd1, nullptr, nullptr, r116, H_, W_);
    tconv<3,1,3,1,3,1><<<dim3(6, 24, 8), 256, SMEM_3>>>(
        nullptr, r116, nullptr, (const uint4*)(wbf + (size_t)CH_D2 * 16384),
        b_d2, gd2, bed2, md2, vd2, nullptr, nullptr, r216, H_, W_);
    tconv<3,1,3,1,3,0><<<dim3(6, 24, 8), 256, SMEM_3>>>(
        nullptr, r216, nullptr, (const uint4*)(wbf + (size_t)CH_D3 * 16384),
        b_d3, gd3, bed3, md3, vd3, nullptr, (float*)d_out, nullptr, H_, W_);

    // 5) output head (reads r from d_out, writes output_map after it)
    conv_out_kernel<<<dim3(3, 12, 8), 256, SMEM_CO>>>(
        (const float*)d_out, W_out, b_out, (float*)d_out + R_ELEMS);
}

// round 13
// speedup vs baseline: 5.8770x; 1.0520x over previous
#include <cuda_runtime.h>
#include <cuda_fp16.h>
#include <math.h>
#include <stdint.h>

// ---------------- problem constants ----------------
#define B_ 8
#define H_ 192
#define W_ 192
#define h_ 96
#define w_ 96
#define R_ELEMS (B_*64*H_*W_)        // 18,874,368

// weight-chunk table (each chunk = 16KB: 8KB hi + 8KB lo, [n][k] swizzled fp16)
#define CH_UP 0      // 7x7, CG=2 -> 98 chunks
#define CH_C2 98     // 3x3, CG=1 -> 9
#define CH_D1 107    // 3x3, CG=2 -> 18
#define CH_D2 125    // 9
#define CH_D3 134    // 9
#define CH_TOTAL 143

// ---------------- scratch ----------------
__device__ __align__(16) unsigned char g_wbf[CH_TOTAL * 16384];
__device__ float g_u[B_*64*h_*w_];
__device__ float g_diffs[B_*h_*w_];
__device__ float g_smap[B_*H_*W_];
__device__ __align__(16) __half g_fn16[R_ELEMS];   // NHWC fp16
__device__ __align__(16) __half g_r116[R_ELEMS];   // NHWC fp16
__device__ __align__(16) __half g_r216[R_ELEMS];   // NHWC fp16

// ---------------- helpers ----------------
__device__ __forceinline__ uint32_t smem_u32(const void* p) {
    uint32_t a;
    asm("{ .reg .u64 t; cvta.to.shared.u64 t, %1; cvt.u32.u64 %0, t; }" : "=r"(a) : "l"(p));
    return a;
}
__device__ __forceinline__ void ldm4(uint32_t addr, uint32_t r[4]) {
    asm volatile("ldmatrix.sync.aligned.m8n8.x4.shared.b16 {%0,%1,%2,%3}, [%4];"
                 : "=r"(r[0]), "=r"(r[1]), "=r"(r[2]), "=r"(r[3]) : "r"(addr));
}
__device__ __forceinline__ void mma16816(float c[4], const uint32_t a[4],
                                         uint32_t b0, uint32_t b1) {
    asm volatile(
        "mma.sync.aligned.m16n8k16.row.col.f32.f16.f16.f32 "
        "{%0,%1,%2,%3}, {%4,%5,%6,%7}, {%8,%9}, {%0,%1,%2,%3};"
        : "+f"(c[0]), "+f"(c[1]), "+f"(c[2]), "+f"(c[3])
        : "r"(a[0]), "r"(a[1]), "r"(a[2]), "r"(a[3]), "r"(b0), "r"(b1));
}
__device__ __forceinline__ void cpa16(uint32_t saddr, const void* g) {
    asm volatile("cp.async.cg.shared.global [%0], [%1], 16;" :: "r"(saddr), "l"(g) : "memory");
}
__device__ __forceinline__ void cpa4(uint32_t saddr, const void* g) {
    asm volatile("cp.async.ca.shared.global [%0], [%1], 4;" :: "r"(saddr), "l"(g) : "memory");
}
#define CPA_COMMIT() asm volatile("cp.async.commit_group;" ::: "memory")
#define CPA_WAIT0()  asm volatile("cp.async.wait_group 0;" ::: "memory")

__device__ __forceinline__ float gelu_exact(float y) {
    return 0.5f * y * (1.0f + erff(y * 0.70710678118654752f));
}
__device__ __forceinline__ uint32_t packh2(float a, float b) {
    __half2 h = __floats2half2_rn(a, b);
    return *(uint32_t*)&h;
}
// bilinear sample matching the original up2_kernel's exact fp32 expression order
__device__ __forceinline__ float bil96(const float* p, int iy0, int iy1, float wy,
                                       int ix0, int ix1, float wx) {
    float a = p[iy0 * 96 + ix0], b = p[iy1 * 96 + ix0];
    float c = p[iy0 * 96 + ix1], d = p[iy1 * 96 + ix1];
    float ra = a * (1.f - wy) + b * wy;
    float rb = c * (1.f - wy) + d * wy;
    return ra * (1.f - wx) + rb * wx;
}

// ---------------- fused weight prep: all 5 conv weight sets ----------------
__global__ void prep_all(const float* __restrict__ W_up, const float* __restrict__ W_c2,
                         const float* __restrict__ W_d1, const float* __restrict__ W_d2,
                         const float* __restrict__ W_d3, unsigned char* __restrict__ dst)
{
    int total = CH_TOTAL * 4096;
    for (int idx = blockIdx.x * blockDim.x + threadIdx.x; idx < total;
         idx += gridDim.x * blockDim.x) {
        int chunk = idx >> 12;
        int e = idx & 4095;
        int n = e >> 6, k = e & 63;
        const float* W; int CIN, KK, local;
        if (chunk < 98)       { W = W_up; CIN = 128; KK = 49; local = chunk; }
        else if (chunk < 107) { W = W_c2; CIN = 64;  KK = 9;  local = chunk - 98; }
        else if (chunk < 125) { W = W_d1; CIN = 128; KK = 9;  local = chunk - 107; }
        else if (chunk < 134) { W = W_d2; CIN = 64;  KK = 9;  local = chunk - 125; }
        else                  { W = W_d3; CIN = 64;  KK = 9;  local = chunk - 134; }
        int CG = CIN >> 6;
        int tap = local / CG, cg = local - tap * CG;
        float w = W[((size_t)n * CIN + cg * 64 + k) * KK + tap];
        __half hb = __float2half_rn(w);
        __half lb = __float2half_rn(w - __half2float(hb));
        uint32_t off = (uint32_t)n * 128 + ((((k >> 3) ^ (n & 7))) << 4) + (k & 7) * 2;
        unsigned char* base = dst + (size_t)chunk * 16384;
        *(unsigned short*)(base + off)        = __half_as_ushort(hb);
        *(unsigned short*)(base + 8192 + off) = __half_as_ushort(lb);
    }
}

// ---------------- HMMA implicit-GEMM conv (group-staged weights) ----------------
// TM=8 rows x 32 px per CTA (M=256), 64 out chans; warp tile m64 x n32.
// AMODE 0: input = inA (fp32 NCHW).  AMODE 1: inA * aux(smap).
// AMODE 2: cg0 = bilinear-up2(aux = u), cg1 = inH (fp16 NHWC).
// AMODE 3: input = inH (fp16 NHWC).
// MODE 0: beta*(acc+bias)   MODE 1: gelu(bn(acc+bias))
// OUTF 0: fp32 NCHW (outF)  OUTF 1: fp16 NHWC (outH)
template<int KS, int CG, int G, int MODE, int AMODE, int OUTF>
__global__ __launch_bounds__(256, 2)
void tconv(const float* __restrict__ inA, const __half* __restrict__ inH,
           const float* __restrict__ aux,
           const uint4* __restrict__ wch, const float* __restrict__ bias,
           const float* __restrict__ gg, const float* __restrict__ bb,
           const float* __restrict__ mm, const float* __restrict__ vv,
           const float* __restrict__ betap,
           float* __restrict__ outF, __half* __restrict__ outH,
           int H, int W)
{
    constexpr int PAD = KS / 2;
    constexpr int TM  = 8;
    constexpr int IH  = TM + KS - 1;
    constexpr int IWP = (KS == 3) ? 34 : 40;
    constexpr int NPX = IH * IWP;
    constexpr int KK  = KS * KS;
    constexpr int GPC = (KK + G - 1) / G;
    constexpr int NGRP = GPC * CG;
    constexpr int OFF_A = 1024;
    constexpr int OFF_B = 1024 + NPX * 128;
    constexpr int BSTRIDE = G * 8192;

    extern __shared__ char smem_raw[];
    char* smem = (char*)(((uintptr_t)smem_raw + 1023) & ~(uintptr_t)1023);
    uint32_t sb = smem_u32(smem);
    float* epi = (float*)smem;

    int tid = threadIdx.x, wid = tid >> 5, lane = tid & 31;
    int x0 = blockIdx.x * 32, y0 = blockIdx.y * TM, b = blockIdx.z;
    size_t HW = (size_t)H * W;

    auto stage_group = [&](int fg, int buf) {
        int cgg = fg / GPC, grp = fg - cgg * GPC;
        int t0 = grp * G;
        int cnt = (KK - t0 < G) ? (KK - t0) : G;
        for (int j = 0; j < cnt; j++) {
            int chunk = (t0 + j) * CG + cgg;
            const uint4* srcB = wch + (size_t)chunk * 1024;
            uint32_t dstB = sb + OFF_B + buf * BSTRIDE + j * 8192;
#pragma unroll
            for (int k = 0; k < 2; k++)
                cpa16(dstB + (uint32_t)(tid + k * 256) * 16, srcB + tid + k * 256);
        }
        CPA_COMMIT();
    };

    stage_group(0, 0);

    if (tid < 64) {
        int c = tid;
        float s, t;
        if (MODE == 1) {
            s = gg[c] * rsqrtf(vv[c] + 1e-5f);
            t = (bias[c] - mm[c]) * s + bb[c];
        } else {
            float bt = *betap;
            s = bt; t = bt * bias[c];
        }
        epi[c] = s; epi[64 + c] = t;
    }

    float acc[16][4];
#pragma unroll
    for (int i = 0; i < 16; i++)
#pragma unroll
        for (int j = 0; j < 4; j++) acc[i][j] = 0.f;

    int wm = wid >> 1, nh = wid & 1;
    int ar = lane & 15, akq = lane >> 4;
    int br = lane & 15, bkq = lane >> 4;

    int fg = 0;
    for (int cg = 0; cg < CG; cg++) {
        __syncthreads();

        // ---- stage halo ----
        constexpr int TOT = NPX * 8;
        bool h16 = (AMODE == 3) || (AMODE == 2 && CG == 2);
        if (h16 && (AMODE == 3 || cg == 1)) {
            for (int item = tid; item < TOT; item += 256) {
                int ph = item >> 3, o = item & 7;
                int hy = ph / IWP, hx = ph - hy * IWP;
                int gy = y0 + hy - PAD;
                int gx = x0 + hx - PAD;
                uint4 val = make_uint4(0, 0, 0, 0);
                if ((unsigned)gy < (unsigned)H && (unsigned)gx < (unsigned)W)
                    val = *(const uint4*)(inH + ((((size_t)b * H + gy) * W + gx) << 6) + o * 8);
                uint32_t ad = (uint32_t)ph * 128 + (((o ^ (ph & 7))) << 4);
                *(uint4*)(smem + OFF_A + ad) = val;
            }
        } else {
            const float* src = nullptr;
            if (AMODE != 2) src = inA + ((size_t)b * (CG * 64) + cg * 64) * HW;
            const float rr = 95.f / 191.f;
            for (int item = tid; item < TOT; item += 256) {
                int o  = item / NPX;
                int ph = item - o * NPX;
                int hy = ph / IWP, hx = ph - hy * IWP;
                int gy = y0 + hy - PAD;
                int gx = x0 + hx - PAD;
                float v[8];
                bool inb = (unsigned)gy < (unsigned)H && (unsigned)gx < (unsigned)W;
                if (AMODE == 2) {
                    if (inb) {
                        float sy = gy * rr; int iy0 = (int)sy; float wy = sy - (float)iy0;
                        int iy1 = min(iy0 + 1, 95);
                        float sx = gx * rr; int ix0 = (int)sx; float wx = sx - (float)ix0;
                        int ix1 = min(ix0 + 1, 95);
                        const float* up = aux + (size_t)(b * 64 + o * 8) * 9216;
#pragma unroll
                        for (int j = 0; j < 8; j++)
                            v[j] = bil96(up + j * 9216, iy0, iy1, wy, ix0, ix1, wx);
                    } else {
#pragma unroll
                        for (int j = 0; j < 8; j++) v[j] = 0.f;
                    }
                } else {
                    if (inb) {
                        const float* p = src + (size_t)(o * 8) * HW + (size_t)gy * W + gx;
#pragma unroll
                        for (int j = 0; j < 8; j++) v[j] = p[j * HW];
                        if (AMODE == 1) {
                            float sv = aux[(size_t)b * HW + (size_t)gy * W + gx];
#pragma unroll
                            for (int j = 0; j < 8; j++) v[j] *= sv;
                        }
                    } else {
#pragma unroll
                        for (int j = 0; j < 8; j++) v[j] = 0.f;
                    }
                }
                uint4 hi4;
                hi4.x = packh2(v[0], v[1]); hi4.y = packh2(v[2], v[3]);
                hi4.z = packh2(v[4], v[5]); hi4.w = packh2(v[6], v[7]);
                uint32_t ad = (uint32_t)ph * 128 + (((o ^ (ph & 7))) << 4);
                *(uint4*)(smem + OFF_A + ad) = hi4;
            }
        }

        for (int grp = 0; grp < GPC; grp++, fg++) {
            int s = fg & 1;
            CPA_WAIT0();
            __syncthreads();

            if (fg + 1 < NGRP) stage_group(fg + 1, s ^ 1);

            int t0 = grp * G;
#pragma unroll
            for (int j = 0; j < G; j++) {
                int tap = t0 + j;
                if (tap < KK) {
                    int tapy = tap / KS, tapx = tap - tapy * KS;
                    uint32_t bbase = sb + OFF_B + s * BSTRIDE + j * 8192;
#pragma unroll
                    for (int kc = 0; kc < 4; kc++) {
                        uint32_t a[4][4];
#pragma unroll
                        for (int t = 0; t < 4; t++) {
                            int y = wm * 2 + (t >> 1);
                            int ph = (y + tapy) * IWP + (t & 1) * 16 + ar + tapx;
                            ldm4(sb + OFF_A + (uint32_t)ph * 128
                                 + ((((kc * 2 + akq) ^ (ph & 7))) << 4), a[t]);
                        }
#pragma unroll
                        for (int g = 0; g < 2; g++) {
                            int n = nh * 32 + g * 16 + br;
                            uint32_t ba = bbase + (uint32_t)n * 128
                                        + ((((kc * 2 + bkq) ^ (n & 7))) << 4);
                            uint32_t bh[4];
                            ldm4(ba, bh);
#pragma unroll
                            for (int t = 0; t < 4; t++) {
                                mma16816(acc[t * 4 + 2 * g],     a[t], bh[0], bh[2]);
                                mma16816(acc[t * 4 + 2 * g + 1], a[t], bh[1], bh[3]);
                            }
                        }
                    }
                }
            }
        }
    }

    // ---- epilogue ----
    __syncthreads();
    float* tb = (float*)(smem + 1024);
    {
        int row = lane >> 2, colp = (lane & 3) * 2;
#pragma unroll
        for (int t = 0; t < 4; t++) {
            int p0 = wm * 64 + t * 16 + row;
#pragma unroll
            for (int j = 0; j < 4; j++) {
                int c = nh * 32 + j * 8 + colp;
                tb[p0 * 65 + c]            = acc[t * 4 + j][0];
                tb[p0 * 65 + c + 1]        = acc[t * 4 + j][1];
                tb[(p0 + 8) * 65 + c]      = acc[t * 4 + j][2];
                tb[(p0 + 8) * 65 + c + 1]  = acc[t * 4 + j][3];
            }
        }
    }
    __syncthreads();
    if (OUTF == 0) {
#pragma unroll 4
        for (int it = 0; it < 64; it++) {
            int item = it * 8 + wid;
            int c = item >> 3, py = item & 7;
            float v = tb[(py * 32 + lane) * 65 + c] * epi[c] + epi[64 + c];
            if (MODE == 1) v = gelu_exact(v);
            outF[((size_t)(b * 64 + c) * H + (y0 + py)) * W + x0 + lane] = v;
        }
    } else {
#pragma unroll
        for (int it = 0; it < 8; it++) {
            int item = it * 256 + tid;
            int px = item >> 3, grp = item & 7;
            float vs[8];
#pragma unroll
            for (int j = 0; j < 8; j++) {
                int c = grp * 8 + j;
                float v = tb[px * 65 + c] * epi[c] + epi[64 + c];
                if (MODE == 1) v = gelu_exact(v);
                vs[j] = v;
            }
            uint4 pk;
            pk.x = packh2(vs[0], vs[1]); pk.y = packh2(vs[2], vs[3]);
            pk.z = packh2(vs[4], vs[5]); pk.w = packh2(vs[6], vs[7]);
            int py = px >> 5, xx = px & 31;
            *(uint4*)(outH + ((((size_t)b * H + y0 + py) * W + x0 + xx) << 6) + grp * 8) = pk;
        }
    }
}

// ---------------- AP_MP diff with inline up2(u), 2 outputs/thread ----------------
__global__ void diff_kernel(const float* __restrict__ u, const float* __restrict__ x,
                            float* __restrict__ out)
{
    int idx = blockIdx.x * blockDim.x + threadIdx.x;
    if (idx >= B_ * h_ * (w_ / 2)) return;
    int jp = idx % (w_ / 2);
    int t = idx / (w_ / 2);
    int i = t % h_;
    int b = t / h_;
    int j0 = 2 * jp;
    const float rr = 95.f / 191.f;

    float syA = (2 * i) * rr;     int iyA0 = (int)syA; float wyA = syA - (float)iyA0; int iyA1 = min(iyA0 + 1, 95);
    float syB = (2 * i + 1) * rr; int iyB0 = (int)syB; float wyB = syB - (float)iyB0; int iyB1 = min(iyB0 + 1, 95);

    float sxA0 = (2 * j0) * rr;     int ixA00 = (int)sxA0; float wxA0 = sxA0 - (float)ixA00; int ixA01 = min(ixA00 + 1, 95);
    float sxB0 = (2 * j0 + 1) * rr; int ixB00 = (int)sxB0; float wxB0 = sxB0 - (float)ixB00; int ixB01 = min(ixB00 + 1, 95);
    float sxA1 = (2 * j0 + 2) * rr; int ixA10 = (int)sxA1; float wxA1 = sxA1 - (float)ixA10; int ixA11 = min(ixA10 + 1, 95);
    float sxB1 = (2 * j0 + 3) * rr; int ixB10 = (int)sxB1; float wxB1 = sxB1 - (float)ixB10; int ixB11 = min(ixB10 + 1, 95);

    float a1_0 = 0.f, a2_0 = 0.f, a1_1 = 0.f, a2_1 = 0.f;
    size_t base0 = ((size_t)b * 64 * H_ + 2 * i) * W_ + 4 * jp;
    for (int c = 0; c < 64; c++) {
        const float* uc = u + (size_t)(b * 64 + c) * 9216;
        size_t base = base0 + (size_t)c * H_ * W_;
        float4 xr0 = *(const float4*)(x + base);
        float4 xr1 = *(const float4*)(x + base + W_);

        {
            float s00 = bil96(uc, iyA0, iyA1, wyA, ixA00, ixA01, wxA0);
            float s01 = bil96(uc, iyA0, iyA1, wyA, ixB00, ixB01, wxB0);
            float s10 = bil96(uc, iyB0, iyB1, wyB, ixA00, ixA01, wxA0);
            float s11 = bil96(uc, iyB0, iyB1, wyB, ixB00, ixB01, wxB0);
            float as = 0.25f * (s00 + s01 + s10 + s11);
            float ms = fmaxf(fmaxf(s00, s01), fmaxf(s10, s11));
            float ax = 0.25f * (xr0.x + xr0.y + xr1.x + xr1.y);
            float mx = fmaxf(fmaxf(xr0.x, xr0.y), fmaxf(xr1.x, xr1.y));
            float d1 = as - mx; a1_0 += d1 * d1;
            float d2 = ax - ms; a2_0 += d2 * d2;
        }
        {
            float s00 = bil96(uc, iyA0, iyA1, wyA, ixA10, ixA11, wxA1);
            float s01 = bil96(uc, iyA0, iyA1, wyA, ixB10, ixB11, wxB1);
            float s10 = bil96(uc, iyB0, iyB1, wyB, ixA10, ixA11, wxA1);
            float s11 = bil96(uc, iyB0, iyB1, wyB, ixB10, ixB11, wxB1);
            float as = 0.25f * (s00 + s01 + s10 + s11);
            float ms = fmaxf(fmaxf(s00, s01), fmaxf(s10, s11));
            float ax = 0.25f * (xr0.z + xr0.w + xr1.z + xr1.w);
            float mx = fmaxf(fmaxf(xr0.z, xr0.w), fmaxf(xr1.z, xr1.w));
            float d1 = as - mx; a1_1 += d1 * d1;
            float d2 = ax - ms; a2_1 += d2 * d2;
        }
    }
    size_t ob = ((size_t)b * h_ + i) * w_ + j0;
    out[ob]     = sqrtf(a1_0) + sqrtf(a2_0);
    out[ob + 1] = sqrtf(a1_1) + sqrtf(a2_1);
}

// ---------------- smap: sigmoid(up2(map)) x2 -> (dilate3-map)x2 + 1 ----------------
__global__ __launch_bounds__(256)
void smap_kernel(const float* __restrict__ in_map, const float* __restrict__ ds,
                 float* __restrict__ smap)
{
    __shared__ float s_i[10 * 34];
    __shared__ float s_d[10 * 34];
    int tid = threadIdx.x;
    int x0 = blockIdx.x * 32, y0 = blockIdx.y * 8, b = blockIdx.z;
    const float rr = 95.f / 191.f;
    const float* pi = in_map + (size_t)b * h_ * w_;
    const float* pd = ds + (size_t)b * h_ * w_;

    for (int item = tid; item < 340; item += 256) {
        int hy = item / 34, hx = item - hy * 34;
        int gy = y0 - 1 + hy, gx = x0 - 1 + hx;
        float vi = -INFINITY, vd = -INFINITY;
        if ((unsigned)gy < (unsigned)H_ && (unsigned)gx < (unsigned)W_) {
            float sy = gy * rr; int iy0 = (int)sy; float wy = sy - (float)iy0;
            int iy1 = min(iy0 + 1, h_ - 1);
            float sx = gx * rr; int ix0 = (int)sx; float wx = sx - (float)ix0;
            int ix1 = min(ix0 + 1, w_ - 1);
            float w00 = (1.f - wy) * (1.f - wx), w01 = (1.f - wy) * wx;
            float w10 = wy * (1.f - wx),         w11 = wy * wx;
            float ui = pi[iy0 * w_ + ix0] * w00 + pi[iy0 * w_ + ix1] * w01
                     + pi[iy1 * w_ + ix0] * w10 + pi[iy1 * w_ + ix1] * w11;
            float ud = pd[iy0 * w_ + ix0] * w00 + pd[iy0 * w_ + ix1] * w01
                     + pd[iy1 * w_ + ix0] * w10 + pd[iy1 * w_ + ix1] * w11;
            vi = 1.f / (1.f + expf(-ui));
            vd = 1.f / (1.f + expf(-ud));
        }
        s_i[item] = vi; s_d[item] = vd;
    }
    __syncthreads();

    int tx = tid & 31, ty = tid >> 5;
    int ci = (ty + 1) * 34 + tx + 1;
    float mi = -INFINITY, md = -INFINITY;
#pragma unroll
    for (int dy = 0; dy < 3; dy++)
#pragma unroll
        for (int dx = 0; dx < 3; dx++) {
            int o = (ty + dy) * 34 + tx + dx;
            mi = fmaxf(mi, s_i[o]);
            md = fmaxf(md, s_d[o]);
        }
    float s = (mi - s_i[ci]) + (md - s_d[ci]) + 1.0f;
    smap[((size_t)b * H_ + (y0 + ty)) * W_ + x0 + tx] = s;
}

// ---------------- final conv 7x7, 64 -> 1 (fp32), 4 consecutive px/thread ----------------
// Thread (tx4, ty): outputs (ys+ty, x0 + 4*tx4 + 0..3). Sliding 10-wide input
// window -> 5 LDS.64 per (c,ky) instead of 28 scalar LDS. Same accumulation
// order (c, ky, kx) per output -> bit-identical to previous versions.
__global__ __launch_bounds__(256)
void conv_out_kernel(const float* __restrict__ rin, const float* __restrict__ Wo,
                     const float* __restrict__ bo, float* __restrict__ out)
{
    extern __shared__ float s_dyn[];           // 2 x (8*22*70)
    __shared__ float s_w[64 * 49];
    constexpr int BUFE = 8 * 22 * 70;          // 12320 floats
    uint32_t sdb = smem_u32(s_dyn);

    int tid = threadIdx.x;
    int tx4 = tid & 15, ty = tid >> 4;         // 16 x-groups x 16 rows
    int x0 = blockIdx.x * 64, ys = blockIdx.y * 16, b = blockIdx.z;

    for (int idx = tid; idx < 64 * 49; idx += 256)
        s_w[idx] = Wo[idx];

    auto stage = [&](int c0, int buf) {
        float* dst = s_dyn + buf * BUFE;
        uint32_t dbase = sdb + (uint32_t)buf * BUFE * 4;
        for (int idx = tid; idx < BUFE; idx += 256) {
            int c = idx / (22 * 70);
            int r = idx - c * (22 * 70);
            int ly = r / 70, lx = r - ly * 70;
            int gy = ys + ly - 3, gx = x0 + lx - 3;
            if ((unsigned)gy < (unsigned)H_ && (unsigned)gx < (unsigned)W_)
                cpa4(dbase + (uint32_t)idx * 4,
                     rin + ((size_t)(b * 64 + c0 + c) * H_ + gy) * W_ + gx);
            else
                dst[idx] = 0.f;
        }
        CPA_COMMIT();
    };

    stage(0, 0);
    CPA_WAIT0();
    __syncthreads();

    float a0 = 0.f, a1 = 0.f, a2 = 0.f, a3 = 0.f;
    for (int it = 0; it < 8; it++) {
        int buf = it & 1;
        if (it + 1 < 8) stage((it + 1) * 8, buf ^ 1);
        const float* cur = s_dyn + buf * BUFE;
#pragma unroll
        for (int c = 0; c < 8; c++) {
            const float* wrow = &s_w[(it * 8 + c) * 49];
#pragma unroll
            for (int ky = 0; ky < 7; ky++) {
                const float* row = cur + (c * 22 + ty + ky) * 70 + 4 * tx4;
                // 10-value window via 5 aligned float2 loads
                float2 p0 = *(const float2*)(row + 0);
                float2 p1 = *(const float2*)(row + 2);
                float2 p2 = *(const float2*)(row + 4);
                float2 p3 = *(const float2*)(row + 6);
                float2 p4 = *(const float2*)(row + 8);
                float in[10] = { p0.x, p0.y, p1.x, p1.y, p2.x, p2.y,
                                 p3.x, p3.y, p4.x, p4.y };
#pragma unroll
                for (int kx = 0; kx < 7; kx++) {
                    float w = wrow[ky * 7 + kx];
                    a0 += w * in[kx];
                    a1 += w * in[kx + 1];
                    a2 += w * in[kx + 2];
                    a3 += w * in[kx + 3];
                }
            }
        }
        CPA_WAIT0();
        __syncthreads();
    }
    float bv = bo[0];
    float4 res = make_float4(a0 + bv, a1 + bv, a2 + bv, a3 + bv);
    *(float4*)(out + ((size_t)b * H_ + (ys + ty)) * W_ + x0 + 4 * tx4) = res;
}

// ---------------- launch ----------------
#define SMEM_UP (1024 + 14*40*128 + 2*2*8192)   // 105472  (KS=7, G=2)
#define SMEM_3  (1024 + 10*34*128 + 2*3*8192)   // 93696   (KS=3, G=3)
#define SMEM_CO (2*8*22*70*4)                   // 98560

extern "C" void kernel_launch(void* const* d_in, const int* in_sizes, int n_in,
                              void* d_out, int out_size)
{
    const float* x       = (const float*)d_in[0];
    const float* small_x = (const float*)d_in[1];
    const float* in_map  = (const float*)d_in[2];
    const float* W_up  = (const float*)d_in[3];
    const float* b_up  = (const float*)d_in[4];
    const float* gup   = (const float*)d_in[5];
    const float* beup  = (const float*)d_in[6];
    const float* mup   = (const float*)d_in[7];
    const float* vup   = (const float*)d_in[8];
    const float* W_c2  = (const float*)d_in[9];
    const float* b_c2  = (const float*)d_in[10];
    const float* W_d1  = (const float*)d_in[11];
    const float* b_d1  = (const float*)d_in[12];
    const float* gd1   = (const float*)d_in[13];
    const float* bed1  = (const float*)d_in[14];
    const float* md1   = (const float*)d_in[15];
    const float* vd1   = (const float*)d_in[16];
    const float* W_d2  = (const float*)d_in[17];
    const float* b_d2  = (const float*)d_in[18];
    const float* gd2   = (const float*)d_in[19];
    const float* bed2  = (const float*)d_in[20];
    const float* md2   = (const float*)d_in[21];
    const float* vd2   = (const float*)d_in[22];
    const float* W_d3  = (const float*)d_in[23];
    const float* b_d3  = (const float*)d_in[24];
    const float* gd3   = (const float*)d_in[25];
    const float* bed3  = (const float*)d_in[26];
    const float* md3   = (const float*)d_in[27];
    const float* vd3   = (const float*)d_in[28];
    const float* W_out = (const float*)d_in[29];
    const float* b_out = (const float*)d_in[30];
    const float* beta  = (const float*)d_in[31];

    float *u, *ds, *sp;
    __half *fn16, *r116, *r216;
    unsigned char* wbf;
    cudaGetSymbolAddress((void**)&u,    g_u);
    cudaGetSymbolAddress((void**)&ds,   g_diffs);
    cudaGetSymbolAddress((void**)&sp,   g_smap);
    cudaGetSymbolAddress((void**)&fn16, g_fn16);
    cudaGetSymbolAddress((void**)&r116, g_r116);
    cudaGetSymbolAddress((void**)&r216, g_r216);
    cudaGetSymbolAddress((void**)&wbf,  g_wbf);

    cudaFuncSetAttribute(tconv<7,2,2,1,0,0>, cudaFuncAttributeMaxDynamicSharedMemorySize, SMEM_UP);
    cudaFuncSetAttribute(tconv<3,1,3,0,1,1>, cudaFuncAttributeMaxDynamicSharedMemorySize, SMEM_3);
    cudaFuncSetAttribute(tconv<3,2,3,1,2,1>, cudaFuncAttributeMaxDynamicSharedMemorySize, SMEM_3);
    cudaFuncSetAttribute(tconv<3,1,3,1,3,1>, cudaFuncAttributeMaxDynamicSharedMemorySize, SMEM_3);
    cudaFuncSetAttribute(tconv<3,1,3,1,3,0>, cudaFuncAttributeMaxDynamicSharedMemorySize, SMEM_3);
    cudaFuncSetAttribute(conv_out_kernel,    cudaFuncAttributeMaxDynamicSharedMemorySize, SMEM_CO);

    // 1) fused weight prep
    prep_all<<<1024, 256>>>(W_up, W_c2, W_d1, W_d2, W_d3, wbf);

    // 2) up branch: conv7x7 + BN + GELU -> u (96x96 fp32)
    tconv<7,2,2,1,0,0><<<dim3(3, 12, 8), 256, SMEM_UP>>>(
        small_x, nullptr, nullptr, (const uint4*)(wbf + (size_t)CH_UP * 16384),
        b_up, gup, beup, mup, vup, nullptr, u, nullptr, h_, w_);

    // 3) uncertainty maps
    diff_kernel<<<(B_ * h_ * (w_ / 2) + 255) / 256, 256>>>(u, x, ds);
    smap_kernel<<<dim3(6, 24, 8), 256>>>(in_map, ds, sp);

    // 4) conv chain (HMMA fp16; inter-layer buffers fp16 NHWC)
    tconv<3,1,3,0,1,1><<<dim3(6, 24, 8), 256, SMEM_3>>>(
        x, nullptr, sp, (const uint4*)(wbf + (size_t)CH_C2 * 16384),
        b_c2, nullptr, nullptr, nullptr, nullptr, beta, nullptr, fn16, H_, W_);
    tconv<3,2,3,1,2,1><<<dim3(6, 24, 8), 256, SMEM_3>>>(
        nullptr, fn16, u, (const uint4*)(wbf + (size_t)CH_D1 * 16384),
        b_d1, gd1, bed1, md1, vd1, nullptr, nullptr, r116, H_, W_);
    tconv<3,1,3,1,3,1><<<dim3(6, 24, 8), 256, SMEM_3>>>(
        nullptr, r116, nullptr, (const uint4*)(wbf + (size_t)CH_D2 * 16384),
        b_d2, gd2, bed2, md2, vd2, nullptr, nullptr, r216, H_, W_);
    tconv<3,1,3,1,3,0><<<dim3(6, 24, 8), 256, SMEM_3>>>(
        nullptr, r216, nullptr, (const uint4*)(wbf + (size_t)CH_D3 * 16384),
        b_d3, gd3, bed3, md3, vd3, nullptr, (float*)d_out, nullptr, H_, W_);

    // 5) output head (reads r from d_out, writes output_map after it)
    conv_out_kernel<<<dim3(3, 12, 8), 256, SMEM_CO>>>(
        (const float*)d_out, W_out, b_out, (float*)d_out + R_ELEMS);
}